// round 5
// baseline (speedup 1.0000x reference)
#include <cuda_runtime.h>
#include <cuda_bf16.h>
#include <cfloat>
#include <cstdint>

// Problem constants
#define B_  4
#define L_  1024
#define D_  1024
#define H_  16
#define HB_ 64   // H*B

// ===========================================================================
// Scratch (static __device__)
// ===========================================================================
__device__ float g_x  [B_ * L_ * D_];
__device__ float g_pfb[HB_ * L_ * L_];               // fallback p buffer
__device__ __nv_bfloat16 g_ah[B_ * L_ * D_];         // q_in split hi / att hi
__device__ __nv_bfloat16 g_al[B_ * L_ * D_];         // q_in split lo / att lo
__device__ __nv_bfloat16 g_bh[B_ * L_ * D_];         // k_in split hi
__device__ __nv_bfloat16 g_bl[B_ * L_ * D_];         // k_in split lo
__device__ __nv_bfloat16 g_ch[B_ * L_ * D_];         // v_in split hi
__device__ __nv_bfloat16 g_cl[B_ * L_ * D_];         // v_in split lo
__device__ __nv_bfloat16 g_wh[5 * D_ * D_];          // weights^T split hi [N,K]
__device__ __nv_bfloat16 g_wl[5 * D_ * D_];          // weights^T split lo [N,K]
__device__ __nv_bfloat16 g_qh [B_ * L_ * D_];
__device__ __nv_bfloat16 g_ql [B_ * L_ * D_];
__device__ __nv_bfloat16 g_q2h[B_ * L_ * D_];
__device__ __nv_bfloat16 g_q2l[B_ * L_ * D_];
__device__ __nv_bfloat16 g_kh [B_ * L_ * D_];
__device__ __nv_bfloat16 g_kl [B_ * L_ * D_];
__device__ __nv_bfloat16 g_vh [B_ * L_ * D_];
__device__ __nv_bfloat16 g_vl [B_ * L_ * D_];
__device__ __nv_bfloat16 g_eh [H_ * L_ * 64];
__device__ __nv_bfloat16 g_el [H_ * L_ * 64];

// ===========================================================================
// PTX helpers (base sm_103-legal)
// ===========================================================================
__device__ __forceinline__ uint32_t smem_u32(const void* p) {
    uint32_t a;
    asm("{ .reg .u64 t; cvta.to.shared.u64 t, %1; cvt.u32.u64 %0, t; }"
        : "=r"(a) : "l"(p));
    return a;
}
__device__ __forceinline__ void cpa16(uint32_t saddr, const void* g) {
    asm volatile("cp.async.cg.shared.global [%0], [%1], 16;" :: "r"(saddr), "l"(g));
}
__device__ __forceinline__ void cpa16z(uint32_t saddr, const void* g, int sz) {
    asm volatile("cp.async.cg.shared.global [%0], [%1], 16, %2;"
                 :: "r"(saddr), "l"(g), "r"(sz));
}
__device__ __forceinline__ void ldsm_x4(uint32_t* r, uint32_t addr) {
    asm volatile("ldmatrix.sync.aligned.m8n8.x4.shared.b16 {%0,%1,%2,%3}, [%4];"
                 : "=r"(r[0]), "=r"(r[1]), "=r"(r[2]), "=r"(r[3]) : "r"(addr));
}
__device__ __forceinline__ void ldsm_x4_t(uint32_t* r, uint32_t addr) {
    asm volatile("ldmatrix.sync.aligned.m8n8.x4.trans.shared.b16 {%0,%1,%2,%3}, [%4];"
                 : "=r"(r[0]), "=r"(r[1]), "=r"(r[2]), "=r"(r[3]) : "r"(addr));
}
__device__ __forceinline__ void mma16816(float* c, const uint32_t* a, const uint32_t* b) {
    asm volatile(
        "mma.sync.aligned.m16n8k16.row.col.f32.bf16.bf16.f32 "
        "{%0,%1,%2,%3}, {%4,%5,%6,%7}, {%8,%9}, {%0,%1,%2,%3};"
        : "+f"(c[0]), "+f"(c[1]), "+f"(c[2]), "+f"(c[3])
        : "r"(a[0]), "r"(a[1]), "r"(a[2]), "r"(a[3]), "r"(b[0]), "r"(b[1]));
}

// ===========================================================================
// fp32 -> bf16 hi/lo splits: all activations + Er in one launch (grid.z=4)
// ===========================================================================
__global__ __launch_bounds__(256)
void split_act_all(const float* __restrict__ x0, const float* __restrict__ x1,
                   const float* __restrict__ x2, const float* __restrict__ x3,
                   __nv_bfloat16* __restrict__ h0, __nv_bfloat16* __restrict__ l0,
                   __nv_bfloat16* __restrict__ h1, __nv_bfloat16* __restrict__ l1,
                   __nv_bfloat16* __restrict__ h2, __nv_bfloat16* __restrict__ l2,
                   __nv_bfloat16* __restrict__ h3, __nv_bfloat16* __restrict__ l3)
{
    const int zz = blockIdx.z;
    const float* x; __nv_bfloat16 *hi, *lo; int n;
    if      (zz == 0) { x = x0; hi = h0; lo = l0; n = B_ * L_ * D_; }
    else if (zz == 1) { x = x1; hi = h1; lo = l1; n = B_ * L_ * D_; }
    else if (zz == 2) { x = x2; hi = h2; lo = l2; n = B_ * L_ * D_; }
    else              { x = x3; hi = h3; lo = l3; n = H_ * L_ * 64; }
    int i = (blockIdx.x * 256 + threadIdx.x) * 4;
    if (i >= n) return;
    float4 v = *(const float4*)&x[i];
    __nv_bfloat16 a0 = __float2bfloat16(v.x);
    __nv_bfloat16 a1 = __float2bfloat16(v.y);
    __nv_bfloat16 a2 = __float2bfloat16(v.z);
    __nv_bfloat16 a3 = __float2bfloat16(v.w);
    __nv_bfloat162 hp0; hp0.x = a0; hp0.y = a1;
    __nv_bfloat162 hp1; hp1.x = a2; hp1.y = a3;
    *(__nv_bfloat162*)&hi[i]     = hp0;
    *(__nv_bfloat162*)&hi[i + 2] = hp1;
    __nv_bfloat162 lp0, lp1;
    lp0.x = __float2bfloat16(v.x - __bfloat162float(a0));
    lp0.y = __float2bfloat16(v.y - __bfloat162float(a1));
    lp1.x = __float2bfloat16(v.z - __bfloat162float(a2));
    lp1.y = __float2bfloat16(v.w - __bfloat162float(a3));
    *(__nv_bfloat162*)&lo[i]     = lp0;
    *(__nv_bfloat162*)&lo[i + 2] = lp1;
}

// All 5 weights: W[K,N] fp32 -> Wt[N,K] bf16 hi/lo (transpose + split), grid.z=5
__global__ __launch_bounds__(256)
void split_w_all(const float* __restrict__ W0, const float* __restrict__ W1,
                 const float* __restrict__ W2, const float* __restrict__ W3,
                 const float* __restrict__ W4,
                 __nv_bfloat16* __restrict__ th, __nv_bfloat16* __restrict__ tl)
{
    const float* W;
    switch (blockIdx.z) {
        case 0: W = W0; break;
        case 1: W = W1; break;
        case 2: W = W2; break;
        case 3: W = W3; break;
        default: W = W4; break;
    }
    __nv_bfloat16* h = th + (size_t)blockIdx.z * D_ * D_;
    __nv_bfloat16* l = tl + (size_t)blockIdx.z * D_ * D_;
    __shared__ float t[32][33];
    const int bx = blockIdx.x * 32;
    const int by = blockIdx.y * 32;
    const int tx = threadIdx.x & 31;
    const int ty = threadIdx.x >> 5;
    #pragma unroll
    for (int r = ty; r < 32; r += 8)
        t[r][tx] = W[(size_t)(by + r) * D_ + bx + tx];
    __syncthreads();
    #pragma unroll
    for (int r = ty; r < 32; r += 8) {
        float v = t[tx][r];
        __nv_bfloat16 hh = __float2bfloat16(v);
        h[(size_t)(bx + r) * D_ + by + tx] = hh;
        l[(size_t)(bx + r) * D_ + by + tx] = __float2bfloat16(v - __bfloat162float(hh));
    }
}

// ===========================================================================
// HMMA split-bf16 GEMM: C = (Ah+Al)[M,K] @ (Bh+Bl)[N,K]^T
// Output: fp32 C (+R residual) OR bf16 hi/lo pair (Oh/Ol).
// ===========================================================================
#define TSTRIDE 40
#define TILE_BYTES (128 * TSTRIDE * 2)
#define STAGE_BYTES (4 * TILE_BYTES)

__global__ __launch_bounds__(256)
void gemm_tc(const __nv_bfloat16* __restrict__ Ah, const __nv_bfloat16* __restrict__ Al,
             const __nv_bfloat16* __restrict__ Bh, const __nv_bfloat16* __restrict__ Bl,
             float* __restrict__ C, const float* __restrict__ R,
             __nv_bfloat16* __restrict__ Oh, __nv_bfloat16* __restrict__ Ol,
             int K, int N)
{
    extern __shared__ __align__(16) char smem[];
    const uint32_t sb0 = smem_u32(smem);
    const int tid  = threadIdx.x;
    const int wid  = tid >> 5;
    const int lane = tid & 31;
    const int m0 = blockIdx.y * 128;
    const int n0 = blockIdx.x * 128;
    const int wm = (wid & 3) * 32;
    const int wn = (wid >> 2) * 64;

    const __nv_bfloat16* gT[4] = {
        Ah + (size_t)m0 * K, Al + (size_t)m0 * K,
        Bh + (size_t)n0 * K, Bl + (size_t)n0 * K };

    auto load_chunk = [&](int c, int st) {
        const uint32_t sb = sb0 + st * STAGE_BYTES;
        const int k0 = c * 32;
        #pragma unroll
        for (int t = 0; t < 4; t++) {
            const __nv_bfloat16* g = gT[t] + k0;
            const uint32_t tb = sb + t * TILE_BYTES;
            #pragma unroll
            for (int it = 0; it < 2; it++) {
                int o   = tid + it * 256;
                int row = o >> 2, c16 = o & 3;
                cpa16(tb + row * (TSTRIDE * 2) + c16 * 16,
                      g + (size_t)row * K + c16 * 8);
            }
        }
        asm volatile("cp.async.commit_group;" ::: "memory");
    };

    float acc[2][8][4];
    #pragma unroll
    for (int i = 0; i < 2; i++)
        #pragma unroll
        for (int j = 0; j < 8; j++)
            #pragma unroll
            for (int q = 0; q < 4; q++) acc[i][j][q] = 0.f;

    const int arow = lane & 15;
    const int acolq = (lane >> 4) * 8;
    const int nrow = ((lane >> 4) * 8) + (lane & 7);
    const int bcolq = ((lane >> 3) & 1) * 8;

    const int NC = K / 32;
    load_chunk(0, 0);

    for (int c = 0; c < NC; ++c) {
        const int st = c & 1;
        if (c + 1 < NC) {
            load_chunk(c + 1, st ^ 1);
            asm volatile("cp.async.wait_group 1;" ::: "memory");
        } else {
            asm volatile("cp.async.wait_group 0;" ::: "memory");
        }
        __syncthreads();

        const uint32_t sb  = sb0 + st * STAGE_BYTES;
        const uint32_t sAh = sb;
        const uint32_t sAl = sb + TILE_BYTES;
        const uint32_t sBh = sb + 2 * TILE_BYTES;
        const uint32_t sBl = sb + 3 * TILE_BYTES;

        #pragma unroll
        for (int k16 = 0; k16 < 32; k16 += 16) {
            uint32_t ah[2][4], al[2][4], bh[4][4], bl[4][4];
            #pragma unroll
            for (int mt = 0; mt < 2; mt++) {
                uint32_t off = ((wm + mt * 16 + arow) * TSTRIDE + k16 + acolq) * 2;
                ldsm_x4(ah[mt], sAh + off);
                ldsm_x4(al[mt], sAl + off);
            }
            #pragma unroll
            for (int p = 0; p < 4; p++) {
                uint32_t off = ((wn + p * 16 + nrow) * TSTRIDE + k16 + bcolq) * 2;
                ldsm_x4(bh[p], sBh + off);
                ldsm_x4(bl[p], sBl + off);
            }
            #pragma unroll
            for (int mt = 0; mt < 2; mt++)
                #pragma unroll
                for (int nt = 0; nt < 8; nt++) {
                    const uint32_t* bhf = &bh[nt >> 1][(nt & 1) * 2];
                    const uint32_t* blf = &bl[nt >> 1][(nt & 1) * 2];
                    mma16816(acc[mt][nt], ah[mt], bhf);
                    mma16816(acc[mt][nt], ah[mt], blf);
                    mma16816(acc[mt][nt], al[mt], bhf);
                }
        }
        __syncthreads();
    }

    #pragma unroll
    for (int mt = 0; mt < 2; mt++) {
        const int m = m0 + wm + mt * 16 + (lane >> 2);
        #pragma unroll
        for (int nt = 0; nt < 8; nt++) {
            const int n = n0 + wn + nt * 8 + (lane & 3) * 2;
            if (Oh) {
                #pragma unroll
                for (int rr = 0; rr < 2; rr++) {
                    const size_t idx = (size_t)(m + rr * 8) * N + n;
                    float a0 = acc[mt][nt][rr * 2], a1 = acc[mt][nt][rr * 2 + 1];
                    __nv_bfloat162 hh, ll;
                    hh.x = __float2bfloat16(a0);
                    hh.y = __float2bfloat16(a1);
                    ll.x = __float2bfloat16(a0 - __bfloat162float(hh.x));
                    ll.y = __float2bfloat16(a1 - __bfloat162float(hh.y));
                    *(__nv_bfloat162*)&Oh[idx] = hh;
                    *(__nv_bfloat162*)&Ol[idx] = ll;
                }
            } else {
                float2 o0 = make_float2(acc[mt][nt][0], acc[mt][nt][1]);
                float2 o1 = make_float2(acc[mt][nt][2], acc[mt][nt][3]);
                if (R) {
                    const float2 r0 = *(const float2*)&R[(size_t)m * N + n];
                    const float2 r1 = *(const float2*)&R[(size_t)(m + 8) * N + n];
                    o0.x += r0.x; o0.y += r0.y;
                    o1.x += r1.x; o1.y += r1.y;
                }
                *(float2*)&C[(size_t)m * N + n] = o0;
                *(float2*)&C[(size_t)(m + 8) * N + n] = o1;
            }
        }
    }
}

// ===========================================================================
// HMMA score kernel: S[i,j] = (q_i.k_j + q2_i.Er[L-1-(i-j)]) / 8, j <= i tiles.
// Triangular grid: blockIdx.x in [0, 136) -> (ti, tj).
// ===========================================================================
#define SC_SQH 0
#define SC_SQL 8192
#define SC_S2H 16384
#define SC_S2L 24576
#define SC_SKH 32768
#define SC_SKL 40960
#define SC_SEH 49152
#define SC_SEL 65536
#define SC_SR  81920
#define SC_SMEM (81920 + 4 * 5632)   // 104448

__global__ __launch_bounds__(128)
void score_tc(const __nv_bfloat16* __restrict__ qh, const __nv_bfloat16* __restrict__ ql,
              const __nv_bfloat16* __restrict__ q2h, const __nv_bfloat16* __restrict__ q2l,
              const __nv_bfloat16* __restrict__ kh, const __nv_bfloat16* __restrict__ kl,
              const __nv_bfloat16* __restrict__ eh, const __nv_bfloat16* __restrict__ el,
              float* __restrict__ p)
{
    // triangular index -> (ti, tj)
    const int x = blockIdx.x;
    int ti = (int)((__fsqrt_rn(8.0f * x + 1.0f) - 1.0f) * 0.5f);
    if (ti * (ti + 1) / 2 > x) ti--;
    else if ((ti + 1) * (ti + 2) / 2 <= x) ti++;
    const int tj = x - ti * (ti + 1) / 2;
    const int z = blockIdx.y;
    const int i0 = ti * 64, j0 = tj * 64;
    const int h = z >> 2, b = z & 3;
    const int rbase = L_ - 64 - i0 + j0;

    extern __shared__ __align__(16) char smem[];
    const uint32_t sb = smem_u32(smem);
    const int tid = threadIdx.x;
    const int lane = tid & 31, w = tid >> 5;

    auto load64 = [&](uint32_t st, const __nv_bfloat16* g) {
        #pragma unroll
        for (int t = 0; t < 4; t++) {
            int cid = tid + t * 128;
            int row = cid >> 3, c = cid & 7;
            cpa16(sb + st + row * 128 + ((c ^ (row & 7)) * 16),
                  g + (size_t)row * D_ + c * 8);
        }
    };
    const size_t qoff = (size_t)(b * L_ + i0) * D_ + h * 64;
    const size_t koff = (size_t)(b * L_ + j0) * D_ + h * 64;
    load64(SC_SQH, qh  + qoff);
    load64(SC_SQL, ql  + qoff);
    load64(SC_S2H, q2h + qoff);
    load64(SC_S2L, q2l + qoff);
    load64(SC_SKH, kh  + koff);
    load64(SC_SKL, kl  + koff);
    {
        const __nv_bfloat16* ehp = eh + (size_t)h * L_ * 64;
        const __nv_bfloat16* elp = el + (size_t)h * L_ * 64;
        #pragma unroll
        for (int t = 0; t < 8; t++) {
            int cid = tid + t * 128;
            int row = cid >> 3, c = cid & 7;
            int r = rbase + row;
            int sz = (r < L_) ? 16 : 0;
            int rc = (r < L_) ? r : 0;
            uint32_t so = row * 128 + ((c ^ (row & 7)) * 16);
            cpa16z(sb + SC_SEH + so, ehp + (size_t)rc * 64 + c * 8, sz);
            cpa16z(sb + SC_SEL + so, elp + (size_t)rc * 64 + c * 8, sz);
        }
    }
    asm volatile("cp.async.commit_group;" ::: "memory");
    asm volatile("cp.async.wait_group 0;" ::: "memory");
    __syncthreads();

    float aqk[8][4], arl[10][4];
    #pragma unroll
    for (int i = 0; i < 8; i++)
        #pragma unroll
        for (int q = 0; q < 4; q++) aqk[i][q] = 0.f;
    #pragma unroll
    for (int i = 0; i < 10; i++)
        #pragma unroll
        for (int q = 0; q < 4; q++) arl[i][q] = 0.f;

    const int t0w = 48 - 16 * w;

    auto ldA = [&](uint32_t st, int k16, uint32_t* r) {
        int row = 16 * w + (lane & 15);
        int c = (k16 >> 3) + (lane >> 4);
        ldsm_x4(r, sb + st + row * 128 + ((c ^ (row & 7)) * 16));
    };
    auto ldB = [&](uint32_t st, int nrow0, int k16, uint32_t* r) {
        int row = nrow0 + (lane >> 4) * 8 + (lane & 7);
        int c = (k16 >> 3) + ((lane >> 3) & 1);
        ldsm_x4(r, sb + st + row * 128 + ((c ^ (row & 7)) * 16));
    };

    #pragma unroll
    for (int k16 = 0; k16 < 64; k16 += 16) {
        uint32_t Aqh[4], Aql[4], A2h[4], A2l[4];
        ldA(SC_SQH, k16, Aqh);
        ldA(SC_SQL, k16, Aql);
        ldA(SC_S2H, k16, A2h);
        ldA(SC_S2L, k16, A2l);
        #pragma unroll
        for (int pg = 0; pg < 4; pg++) {
            uint32_t Bh[4], Bl[4];
            ldB(SC_SKH, pg * 16, k16, Bh);
            ldB(SC_SKL, pg * 16, k16, Bl);
            mma16816(aqk[2 * pg],     Aqh, Bh);
            mma16816(aqk[2 * pg + 1], Aqh, Bh + 2);
            mma16816(aqk[2 * pg],     Aqh, Bl);
            mma16816(aqk[2 * pg + 1], Aqh, Bl + 2);
            mma16816(aqk[2 * pg],     Aql, Bh);
            mma16816(aqk[2 * pg + 1], Aql, Bh + 2);
        }
        #pragma unroll
        for (int pg = 0; pg < 5; pg++) {
            uint32_t Bh[4], Bl[4];
            ldB(SC_SEH, t0w + pg * 16, k16, Bh);
            ldB(SC_SEL, t0w + pg * 16, k16, Bl);
            mma16816(arl[2 * pg],     A2h, Bh);
            mma16816(arl[2 * pg + 1], A2h, Bh + 2);
            mma16816(arl[2 * pg],     A2h, Bl);
            mma16816(arl[2 * pg + 1], A2h, Bl + 2);
            mma16816(arl[2 * pg],     A2l, Bh);
            mma16816(arl[2 * pg + 1], A2l, Bh + 2);
        }
    }

    float* Rs = (float*)(smem + SC_SR + w * 5632);   // 16 x 88 fp32
    const int r0 = lane >> 2, cb = (lane & 3) * 2;
    #pragma unroll
    for (int nt = 0; nt < 10; nt++) {
        int tb = nt * 8 + cb;
        Rs[r0 * 88 + tb]           = arl[nt][0];
        Rs[r0 * 88 + tb + 1]       = arl[nt][1];
        Rs[(r0 + 8) * 88 + tb]     = arl[nt][2];
        Rs[(r0 + 8) * 88 + tb + 1] = arl[nt][3];
    }
    __syncwarp();

    #pragma unroll
    for (int nt = 0; nt < 8; nt++) {
        int jj = nt * 8 + cb;
        float2 o0, o1;
        o0.x = (aqk[nt][0] + Rs[r0 * 88 + 15 + jj - r0]) * 0.125f;
        o0.y = (aqk[nt][1] + Rs[r0 * 88 + 16 + jj - r0]) * 0.125f;
        o1.x = (aqk[nt][2] + Rs[(r0 + 8) * 88 + 7 + jj - r0]) * 0.125f;
        o1.y = (aqk[nt][3] + Rs[(r0 + 8) * 88 + 8 + jj - r0]) * 0.125f;
        size_t base = ((size_t)z * L_ + i0 + 16 * w + r0) * L_ + j0 + jj;
        *(float2*)&p[base]          = o0;
        *(float2*)&p[base + 8 * L_] = o1;
    }
}

// ===========================================================================
// Fused softmax + pv: reads logits from pbuf, writes probabilities in place,
// accumulates out = p @ v via HMMA, writes att bf16 hi/lo, zero-fills tails.
// 128 threads (4 warps x 16 rows).
// ===========================================================================
__global__ __launch_bounds__(128)
void pv_sm(float* __restrict__ pbuf,
           const __nv_bfloat16* __restrict__ vh, const __nv_bfloat16* __restrict__ vl,
           __nv_bfloat16* __restrict__ oh, __nv_bfloat16* __restrict__ ol)
{
    const int ti = blockIdx.x, z = blockIdx.y;
    const int i0 = ti * 64;
    const int h = z >> 2, b = z & 3;
    const int tid = threadIdx.x;
    const int lane = tid & 31, w = tid >> 5;

    __shared__ __align__(128) char sv[2][2][4096];   // [buf][h/l][32 rows x 128B]
    __shared__ __align__(128) char sp[4][2][1280];   // [warp][h/l][16 rows x 80B]
    __shared__ float sm_m[64], sm_inv[64];
    const uint32_t svb = smem_u32(&sv[0][0][0]);
    const uint32_t spw = smem_u32(&sp[w][0][0]);

    // ---- phase 1: per-row max & sum(exp) over j in [0, i] ----
    {
        const int r = tid >> 1, half = tid & 1;
        const int i = i0 + r;
        const float* row = pbuf + ((size_t)z * L_ + i) * L_;
        const int len = i + 1;
        float m = -FLT_MAX;
        for (int j = half * 4; j < len; j += 8) {
            float4 xv = *(const float4*)&row[j];
            float m4 = xv.x;
            if (j + 1 < len) m4 = fmaxf(m4, xv.y);
            if (j + 2 < len) m4 = fmaxf(m4, xv.z);
            if (j + 3 < len) m4 = fmaxf(m4, xv.w);
            m = fmaxf(m, m4);
        }
        m = fmaxf(m, __shfl_xor_sync(0xffffffffu, m, 1));
        float s = 0.f;
        for (int j = half * 4; j < len; j += 8) {
            float4 xv = *(const float4*)&row[j];
            s += __expf(xv.x - m);
            if (j + 1 < len) s += __expf(xv.y - m);
            if (j + 2 < len) s += __expf(xv.z - m);
            if (j + 3 < len) s += __expf(xv.w - m);
        }
        s += __shfl_xor_sync(0xffffffffu, s, 1);
        if (half == 0) { sm_m[r] = m; sm_inv[r] = 1.0f / s; }
    }
    __syncthreads();

    auto loadV = [&](int kj, int bi) {
        #pragma unroll
        for (int t = 0; t < 4; t++) {
            int cid = tid + t * 128;
            int sel = cid >> 8, rid = (cid >> 3) & 31, c = cid & 7;
            const __nv_bfloat16* g = (sel ? vl : vh)
                + ((size_t)(b * L_ + kj + rid) * D_ + h * 64 + c * 8);
            cpa16(svb + bi * 8192 + sel * 4096 + rid * 128 + ((c ^ (rid & 7)) * 16), g);
        }
        asm volatile("cp.async.commit_group;" ::: "memory");
    };

    float acc[8][4];
    #pragma unroll
    for (int i = 0; i < 8; i++)
        #pragma unroll
        for (int q = 0; q < 4; q++) acc[i][q] = 0.f;

    const int nch = (i0 + 64) >> 5;
    loadV(0, 0);

    for (int c = 0; c < nch; c++) {
        const int bi = c & 1;
        __syncthreads();
        if (c + 1 < nch) loadV((c + 1) * 32, bi ^ 1);

        // per-warp: softmax-ize chunk, write p, stage bf16 hi/lo to smem
        {
            const int row = lane >> 1, chalf = lane & 1;
            const int i = i0 + 16 * w + row;
            const float m = sm_m[16 * w + row];
            const float inv = sm_inv[16 * w + row];
            float* gp = pbuf + ((size_t)z * L_ + i) * L_ + c * 32 + chalf * 16;
            const int jb = c * 32 + chalf * 16;
            uint32_t* ph = (uint32_t*)(&sp[w][0][0] + row * 80 + chalf * 32);
            uint32_t* pl = (uint32_t*)(&sp[w][1][0] + row * 80 + chalf * 32);
            #pragma unroll
            for (int q = 0; q < 4; q++) {
                float4 xv = *(const float4*)(gp + q * 4);
                const int j = jb + q * 4;
                float4 e;
                e.x = (j + 0 <= i) ? __expf(xv.x - m) * inv : 0.f;
                e.y = (j + 1 <= i) ? __expf(xv.y - m) * inv : 0.f;
                e.z = (j + 2 <= i) ? __expf(xv.z - m) * inv : 0.f;
                e.w = (j + 3 <= i) ? __expf(xv.w - m) * inv : 0.f;
                *(float4*)(gp + q * 4) = e;
                __nv_bfloat162 h0, h1, l0, l1;
                h0.x = __float2bfloat16(e.x); h0.y = __float2bfloat16(e.y);
                h1.x = __float2bfloat16(e.z); h1.y = __float2bfloat16(e.w);
                l0.x = __float2bfloat16(e.x - __bfloat162float(h0.x));
                l0.y = __float2bfloat16(e.y - __bfloat162float(h0.y));
                l1.x = __float2bfloat16(e.z - __bfloat162float(h1.x));
                l1.y = __float2bfloat16(e.w - __bfloat162float(h1.y));
                ph[q * 2]     = *(uint32_t*)&h0;
                ph[q * 2 + 1] = *(uint32_t*)&h1;
                pl[q * 2]     = *(uint32_t*)&l0;
                pl[q * 2 + 1] = *(uint32_t*)&l1;
            }
        }
        __syncwarp();
        if (c + 1 < nch) asm volatile("cp.async.wait_group 1;" ::: "memory");
        else             asm volatile("cp.async.wait_group 0;" ::: "memory");
        __syncthreads();

        #pragma unroll
        for (int k16 = 0; k16 < 32; k16 += 16) {
            uint32_t Aph[4], Apl[4];
            {
                int arow = lane & 15;
                int ac = (k16 >> 3) + (lane >> 4);
                ldsm_x4(Aph, spw + arow * 80 + ac * 16);
                ldsm_x4(Apl, spw + 1280 + arow * 80 + ac * 16);
            }
            #pragma unroll
            for (int p4 = 0; p4 < 4; p4++) {
                uint32_t Bh[4], Bl[4];
                int krow = k16 + ((lane >> 3) & 1) * 8 + (lane & 7);
                int cc = p4 * 2 + (lane >> 4);
                uint32_t off = krow * 128 + ((cc ^ (krow & 7)) * 16);
                ldsm_x4_t(Bh, svb + bi * 8192 + off);
                ldsm_x4_t(Bl, svb + bi * 8192 + 4096 + off);
                mma16816(acc[2 * p4],     Aph, Bh);
                mma16816(acc[2 * p4 + 1], Aph, Bh + 2);
                mma16816(acc[2 * p4],     Aph, Bl);
                mma16816(acc[2 * p4 + 1], Aph, Bl + 2);
                mma16816(acc[2 * p4],     Apl, Bh);
                mma16816(acc[2 * p4 + 1], Apl, Bh + 2);
            }
        }
    }

    // epilogue: att -> bf16 hi/lo
    const int r0 = lane >> 2, cb = (lane & 3) * 2;
    #pragma unroll
    for (int nt = 0; nt < 8; nt++) {
        const int d = nt * 8 + cb;
        #pragma unroll
        for (int rr = 0; rr < 2; rr++) {
            const int i = i0 + 16 * w + r0 + rr * 8;
            const size_t idx = (size_t)(b * L_ + i) * D_ + h * 64 + d;
            float a0 = acc[nt][rr * 2], a1 = acc[nt][rr * 2 + 1];
            __nv_bfloat162 hh, ll;
            hh.x = __float2bfloat16(a0);
            hh.y = __float2bfloat16(a1);
            ll.x = __float2bfloat16(a0 - __bfloat162float(hh.x));
            ll.y = __float2bfloat16(a1 - __bfloat162float(hh.y));
            *(__nv_bfloat162*)&oh[idx] = hh;
            *(__nv_bfloat162*)&ol[idx] = ll;
        }
    }

    // zero-fill p[i0..i0+64, i0+64..L)
    const int tail0 = i0 + 64;
    const int nt4 = (L_ - tail0) >> 2;
    if (nt4 > 0) {
        const float4 z4 = make_float4(0.f, 0.f, 0.f, 0.f);
        const int tot = 64 * nt4;
        for (int t = tid; t < tot; t += 128) {
            int r = t / nt4, c4 = t - r * nt4;
            *(float4*)&pbuf[((size_t)z * L_ + i0 + r) * L_ + tail0 + c4 * 4] = z4;
        }
    }
}

// ===========================================================================
// LayerNorm
// ===========================================================================
__global__ __launch_bounds__(256)
void ln_kernel(const float* __restrict__ x, const float* __restrict__ gam,
               const float* __restrict__ bet, float* __restrict__ y)
{
    const int r = blockIdx.x, tid = threadIdx.x;
    __shared__ float sh[16];
    const float* xr = x + (size_t)r * D_;
    float4 xv = *(const float4*)&xr[tid * 4];
    float s  = xv.x + xv.y + xv.z + xv.w;
    float ss = xv.x*xv.x + xv.y*xv.y + xv.z*xv.z + xv.w*xv.w;
    #pragma unroll
    for (int o = 16; o > 0; o >>= 1) {
        s  += __shfl_xor_sync(0xffffffffu, s,  o);
        ss += __shfl_xor_sync(0xffffffffu, ss, o);
    }
    if ((tid & 31) == 0) { sh[tid >> 5] = s; sh[8 + (tid >> 5)] = ss; }
    __syncthreads();
    float st = 0.f, sst = 0.f;
    #pragma unroll
    for (int wv = 0; wv < 8; wv++) { st += sh[wv]; sst += sh[8 + wv]; }
    const float mu  = st * (1.0f / D_);
    const float var = sst * (1.0f / D_) - mu * mu;
    const float rs  = rsqrtf(var + 1e-5f);
    float4 gv = *(const float4*)&gam[tid * 4];
    float4 bv = *(const float4*)&bet[tid * 4];
    float4 o4;
    o4.x = (xv.x - mu) * rs * gv.x + bv.x;
    o4.y = (xv.y - mu) * rs * gv.y + bv.y;
    o4.z = (xv.z - mu) * rs * gv.z + bv.z;
    o4.w = (xv.w - mu) * rs * gv.w + bv.w;
    *(float4*)&y[(size_t)r * D_ + tid * 4] = o4;
}

// ===========================================================================
// Launch
// ===========================================================================
extern "C" void kernel_launch(void* const* d_in, const int* in_sizes, int n_in,
                              void* d_out, int out_size)
{
    const float* q_in = (const float*)d_in[0];
    const float* k_in = (const float*)d_in[1];
    const float* v_in = (const float*)d_in[2];
    const float* Wq   = (const float*)d_in[3];
    const float* Wq2  = (const float*)d_in[4];
    const float* Wk   = (const float*)d_in[5];
    const float* Wv   = (const float*)d_in[6];
    const float* Wo   = (const float*)d_in[7];
    const float* ln_g = (const float*)d_in[8];
    const float* ln_b = (const float*)d_in[9];
    const float* Er   = (const float*)d_in[10];
    (void)in_sizes; (void)n_in;

    float *px, *pfb;
    __nv_bfloat16 *ah, *al, *bh, *bl, *ch, *cl, *wh, *wl;
    __nv_bfloat16 *qh, *ql, *q2h, *q2l, *kh, *kl, *vh, *vl, *eh, *el;
    cudaGetSymbolAddress((void**)&px,  g_x);
    cudaGetSymbolAddress((void**)&pfb, g_pfb);
    cudaGetSymbolAddress((void**)&ah,  g_ah);
    cudaGetSymbolAddress((void**)&al,  g_al);
    cudaGetSymbolAddress((void**)&bh,  g_bh);
    cudaGetSymbolAddress((void**)&bl,  g_bl);
    cudaGetSymbolAddress((void**)&ch,  g_ch);
    cudaGetSymbolAddress((void**)&cl,  g_cl);
    cudaGetSymbolAddress((void**)&wh,  g_wh);
    cudaGetSymbolAddress((void**)&wl,  g_wl);
    cudaGetSymbolAddress((void**)&qh,  g_qh);
    cudaGetSymbolAddress((void**)&ql,  g_ql);
    cudaGetSymbolAddress((void**)&q2h, g_q2h);
    cudaGetSymbolAddress((void**)&q2l, g_q2l);
    cudaGetSymbolAddress((void**)&kh,  g_kh);
    cudaGetSymbolAddress((void**)&kl,  g_kl);
    cudaGetSymbolAddress((void**)&vh,  g_vh);
    cudaGetSymbolAddress((void**)&vl,  g_vl);
    cudaGetSymbolAddress((void**)&eh,  g_eh);
    cudaGetSymbolAddress((void**)&el,  g_el);

    float* y_out = (float*)d_out;
    const long long ysz = (long long)B_ * L_ * D_;
    const long long psz = (long long)HB_ * L_ * L_;
    float* p_buf = ((long long)out_size >= ysz + psz) ? (y_out + ysz) : pfb;

    const int gsmem = 2 * STAGE_BYTES;
    cudaFuncSetAttribute(gemm_tc, cudaFuncAttributeMaxDynamicSharedMemorySize, gsmem);
    cudaFuncSetAttribute(score_tc, cudaFuncAttributeMaxDynamicSharedMemorySize, SC_SMEM);

    const int M = B_ * L_;
    const dim3 ggemm(D_ / 128, M / 128);
    const size_t WSZ = (size_t)D_ * D_;

    // all splits upfront
    split_act_all<<<dim3(4096, 1, 4), 256>>>(q_in, k_in, v_in, Er,
                                             ah, al, bh, bl, ch, cl, eh, el);
    split_w_all<<<dim3(32, 32, 5), 256>>>(Wq, Wq2, Wk, Wv, Wo, wh, wl);

    // projections -> bf16 hi/lo outputs
    gemm_tc<<<ggemm, 256, gsmem>>>(ah, al, wh + 0 * WSZ, wl + 0 * WSZ,
                                   nullptr, nullptr, qh, ql, D_, D_);
    gemm_tc<<<ggemm, 256, gsmem>>>(ah, al, wh + 1 * WSZ, wl + 1 * WSZ,
                                   nullptr, nullptr, q2h, q2l, D_, D_);
    gemm_tc<<<ggemm, 256, gsmem>>>(bh, bl, wh + 2 * WSZ, wl + 2 * WSZ,
                                   nullptr, nullptr, kh, kl, D_, D_);
    gemm_tc<<<ggemm, 256, gsmem>>>(ch, cl, wh + 3 * WSZ, wl + 3 * WSZ,
                                   nullptr, nullptr, vh, vl, D_, D_);

    // attention middle: scores (tri-grid) then fused softmax + pv
    score_tc<<<dim3(136, HB_), 128, SC_SMEM>>>(qh, ql, q2h, q2l, kh, kl, eh, el, p_buf);
    pv_sm<<<dim3(16, HB_), 128>>>(p_buf, vh, vl, ah, al);   // att -> ah/al

    // Wo GEMM (fp32 out + residual), then LN
    gemm_tc<<<ggemm, 256, gsmem>>>(ah, al, wh + 4 * WSZ, wl + 4 * WSZ,
                                   px, q_in, nullptr, nullptr, D_, D_);
    ln_kernel<<<B_ * L_, 256>>>(px, ln_g, ln_b, y_out);
}

// round 6
// speedup vs baseline: 1.4549x; 1.4549x over previous
#include <cuda_runtime.h>
#include <cuda_bf16.h>
#include <cfloat>
#include <cstdint>

// Problem constants
#define B_  4
#define L_  1024
#define D_  1024
#define H_  16
#define HB_ 64   // H*B

// ===========================================================================
// Scratch (static __device__)
// ===========================================================================
__device__ float g_x  [B_ * L_ * D_];
__device__ float g_pfb[HB_ * L_ * L_];               // fallback p buffer
__device__ __nv_bfloat16 g_ah[B_ * L_ * D_];         // q_in split hi / att hi
__device__ __nv_bfloat16 g_al[B_ * L_ * D_];         // q_in split lo / att lo
__device__ __nv_bfloat16 g_bh[B_ * L_ * D_];         // k_in split hi
__device__ __nv_bfloat16 g_bl[B_ * L_ * D_];         // k_in split lo
__device__ __nv_bfloat16 g_ch[B_ * L_ * D_];         // v_in split hi
__device__ __nv_bfloat16 g_cl[B_ * L_ * D_];         // v_in split lo
__device__ __nv_bfloat16 g_wh[5 * D_ * D_];          // weights^T split hi [N,K]
__device__ __nv_bfloat16 g_wl[5 * D_ * D_];          // weights^T split lo [N,K]
__device__ __nv_bfloat16 g_qh [B_ * L_ * D_];
__device__ __nv_bfloat16 g_ql [B_ * L_ * D_];
__device__ __nv_bfloat16 g_q2h[B_ * L_ * D_];
__device__ __nv_bfloat16 g_q2l[B_ * L_ * D_];
__device__ __nv_bfloat16 g_kh [B_ * L_ * D_];
__device__ __nv_bfloat16 g_kl [B_ * L_ * D_];
__device__ __nv_bfloat16 g_vh [B_ * L_ * D_];
__device__ __nv_bfloat16 g_vl [B_ * L_ * D_];
__device__ __nv_bfloat16 g_eh [H_ * L_ * 64];
__device__ __nv_bfloat16 g_el [H_ * L_ * 64];

// ===========================================================================
// PTX helpers (base sm_103-legal)
// ===========================================================================
__device__ __forceinline__ uint32_t smem_u32(const void* p) {
    uint32_t a;
    asm("{ .reg .u64 t; cvta.to.shared.u64 t, %1; cvt.u32.u64 %0, t; }"
        : "=r"(a) : "l"(p));
    return a;
}
__device__ __forceinline__ void cpa16(uint32_t saddr, const void* g) {
    asm volatile("cp.async.cg.shared.global [%0], [%1], 16;" :: "r"(saddr), "l"(g));
}
__device__ __forceinline__ void cpa16z(uint32_t saddr, const void* g, int sz) {
    asm volatile("cp.async.cg.shared.global [%0], [%1], 16, %2;"
                 :: "r"(saddr), "l"(g), "r"(sz));
}
__device__ __forceinline__ void ldsm_x4(uint32_t* r, uint32_t addr) {
    asm volatile("ldmatrix.sync.aligned.m8n8.x4.shared.b16 {%0,%1,%2,%3}, [%4];"
                 : "=r"(r[0]), "=r"(r[1]), "=r"(r[2]), "=r"(r[3]) : "r"(addr));
}
__device__ __forceinline__ void ldsm_x4_t(uint32_t* r, uint32_t addr) {
    asm volatile("ldmatrix.sync.aligned.m8n8.x4.trans.shared.b16 {%0,%1,%2,%3}, [%4];"
                 : "=r"(r[0]), "=r"(r[1]), "=r"(r[2]), "=r"(r[3]) : "r"(addr));
}
__device__ __forceinline__ void mma16816(float* c, const uint32_t* a, const uint32_t* b) {
    asm volatile(
        "mma.sync.aligned.m16n8k16.row.col.f32.bf16.bf16.f32 "
        "{%0,%1,%2,%3}, {%4,%5,%6,%7}, {%8,%9}, {%0,%1,%2,%3};"
        : "+f"(c[0]), "+f"(c[1]), "+f"(c[2]), "+f"(c[3])
        : "r"(a[0]), "r"(a[1]), "r"(a[2]), "r"(a[3]), "r"(b[0]), "r"(b[1]));
}

// ===========================================================================
// fp32 -> bf16 hi/lo splits: all activations + Er in one launch (grid.z=4)
// ===========================================================================
__global__ __launch_bounds__(256)
void split_act_all(const float* __restrict__ x0, const float* __restrict__ x1,
                   const float* __restrict__ x2, const float* __restrict__ x3,
                   __nv_bfloat16* __restrict__ h0, __nv_bfloat16* __restrict__ l0,
                   __nv_bfloat16* __restrict__ h1, __nv_bfloat16* __restrict__ l1,
                   __nv_bfloat16* __restrict__ h2, __nv_bfloat16* __restrict__ l2,
                   __nv_bfloat16* __restrict__ h3, __nv_bfloat16* __restrict__ l3)
{
    const int zz = blockIdx.z;
    const float* x; __nv_bfloat16 *hi, *lo; int n;
    if      (zz == 0) { x = x0; hi = h0; lo = l0; n = B_ * L_ * D_; }
    else if (zz == 1) { x = x1; hi = h1; lo = l1; n = B_ * L_ * D_; }
    else if (zz == 2) { x = x2; hi = h2; lo = l2; n = B_ * L_ * D_; }
    else              { x = x3; hi = h3; lo = l3; n = H_ * L_ * 64; }
    int i = (blockIdx.x * 256 + threadIdx.x) * 4;
    if (i >= n) return;
    float4 v = *(const float4*)&x[i];
    __nv_bfloat16 a0 = __float2bfloat16(v.x);
    __nv_bfloat16 a1 = __float2bfloat16(v.y);
    __nv_bfloat16 a2 = __float2bfloat16(v.z);
    __nv_bfloat16 a3 = __float2bfloat16(v.w);
    __nv_bfloat162 hp0; hp0.x = a0; hp0.y = a1;
    __nv_bfloat162 hp1; hp1.x = a2; hp1.y = a3;
    *(__nv_bfloat162*)&hi[i]     = hp0;
    *(__nv_bfloat162*)&hi[i + 2] = hp1;
    __nv_bfloat162 lp0, lp1;
    lp0.x = __float2bfloat16(v.x - __bfloat162float(a0));
    lp0.y = __float2bfloat16(v.y - __bfloat162float(a1));
    lp1.x = __float2bfloat16(v.z - __bfloat162float(a2));
    lp1.y = __float2bfloat16(v.w - __bfloat162float(a3));
    *(__nv_bfloat162*)&lo[i]     = lp0;
    *(__nv_bfloat162*)&lo[i + 2] = lp1;
}

// All 5 weights: W[K,N] fp32 -> Wt[N,K] bf16 hi/lo (transpose + split), grid.z=5
__global__ __launch_bounds__(256)
void split_w_all(const float* __restrict__ W0, const float* __restrict__ W1,
                 const float* __restrict__ W2, const float* __restrict__ W3,
                 const float* __restrict__ W4,
                 __nv_bfloat16* __restrict__ th, __nv_bfloat16* __restrict__ tl)
{
    const float* W;
    switch (blockIdx.z) {
        case 0: W = W0; break;
        case 1: W = W1; break;
        case 2: W = W2; break;
        case 3: W = W3; break;
        default: W = W4; break;
    }
    __nv_bfloat16* h = th + (size_t)blockIdx.z * D_ * D_;
    __nv_bfloat16* l = tl + (size_t)blockIdx.z * D_ * D_;
    __shared__ float t[32][33];
    const int bx = blockIdx.x * 32;
    const int by = blockIdx.y * 32;
    const int tx = threadIdx.x & 31;
    const int ty = threadIdx.x >> 5;
    #pragma unroll
    for (int r = ty; r < 32; r += 8)
        t[r][tx] = W[(size_t)(by + r) * D_ + bx + tx];
    __syncthreads();
    #pragma unroll
    for (int r = ty; r < 32; r += 8) {
        float v = t[tx][r];
        __nv_bfloat16 hh = __float2bfloat16(v);
        h[(size_t)(bx + r) * D_ + by + tx] = hh;
        l[(size_t)(bx + r) * D_ + by + tx] = __float2bfloat16(v - __bfloat162float(hh));
    }
}

// ===========================================================================
// HMMA split-bf16 GEMM: C = (Ah+Al)[M,K] @ (Bh+Bl)[N,K]^T
// Output: fp32 C (+R residual) OR bf16 hi/lo pair (Oh/Ol).
// ===========================================================================
#define TSTRIDE 40
#define TILE_BYTES (128 * TSTRIDE * 2)
#define STAGE_BYTES (4 * TILE_BYTES)

__global__ __launch_bounds__(256)
void gemm_tc(const __nv_bfloat16* __restrict__ Ah, const __nv_bfloat16* __restrict__ Al,
             const __nv_bfloat16* __restrict__ Bh, const __nv_bfloat16* __restrict__ Bl,
             float* __restrict__ C, const float* __restrict__ R,
             __nv_bfloat16* __restrict__ Oh, __nv_bfloat16* __restrict__ Ol,
             int K, int N)
{
    extern __shared__ __align__(16) char smem[];
    const uint32_t sb0 = smem_u32(smem);
    const int tid  = threadIdx.x;
    const int wid  = tid >> 5;
    const int lane = tid & 31;
    const int m0 = blockIdx.y * 128;
    const int n0 = blockIdx.x * 128;
    const int wm = (wid & 3) * 32;
    const int wn = (wid >> 2) * 64;

    const __nv_bfloat16* gT[4] = {
        Ah + (size_t)m0 * K, Al + (size_t)m0 * K,
        Bh + (size_t)n0 * K, Bl + (size_t)n0 * K };

    auto load_chunk = [&](int c, int st) {
        const uint32_t sb = sb0 + st * STAGE_BYTES;
        const int k0 = c * 32;
        #pragma unroll
        for (int t = 0; t < 4; t++) {
            const __nv_bfloat16* g = gT[t] + k0;
            const uint32_t tb = sb + t * TILE_BYTES;
            #pragma unroll
            for (int it = 0; it < 2; it++) {
                int o   = tid + it * 256;
                int row = o >> 2, c16 = o & 3;
                cpa16(tb + row * (TSTRIDE * 2) + c16 * 16,
                      g + (size_t)row * K + c16 * 8);
            }
        }
        asm volatile("cp.async.commit_group;" ::: "memory");
    };

    float acc[2][8][4];
    #pragma unroll
    for (int i = 0; i < 2; i++)
        #pragma unroll
        for (int j = 0; j < 8; j++)
            #pragma unroll
            for (int q = 0; q < 4; q++) acc[i][j][q] = 0.f;

    const int arow = lane & 15;
    const int acolq = (lane >> 4) * 8;
    const int nrow = ((lane >> 4) * 8) + (lane & 7);
    const int bcolq = ((lane >> 3) & 1) * 8;

    const int NC = K / 32;
    load_chunk(0, 0);

    for (int c = 0; c < NC; ++c) {
        const int st = c & 1;
        if (c + 1 < NC) {
            load_chunk(c + 1, st ^ 1);
            asm volatile("cp.async.wait_group 1;" ::: "memory");
        } else {
            asm volatile("cp.async.wait_group 0;" ::: "memory");
        }
        __syncthreads();

        const uint32_t sb  = sb0 + st * STAGE_BYTES;
        const uint32_t sAh = sb;
        const uint32_t sAl = sb + TILE_BYTES;
        const uint32_t sBh = sb + 2 * TILE_BYTES;
        const uint32_t sBl = sb + 3 * TILE_BYTES;

        #pragma unroll
        for (int k16 = 0; k16 < 32; k16 += 16) {
            uint32_t ah[2][4], al[2][4], bh[4][4], bl[4][4];
            #pragma unroll
            for (int mt = 0; mt < 2; mt++) {
                uint32_t off = ((wm + mt * 16 + arow) * TSTRIDE + k16 + acolq) * 2;
                ldsm_x4(ah[mt], sAh + off);
                ldsm_x4(al[mt], sAl + off);
            }
            #pragma unroll
            for (int p = 0; p < 4; p++) {
                uint32_t off = ((wn + p * 16 + nrow) * TSTRIDE + k16 + bcolq) * 2;
                ldsm_x4(bh[p], sBh + off);
                ldsm_x4(bl[p], sBl + off);
            }
            #pragma unroll
            for (int mt = 0; mt < 2; mt++)
                #pragma unroll
                for (int nt = 0; nt < 8; nt++) {
                    const uint32_t* bhf = &bh[nt >> 1][(nt & 1) * 2];
                    const uint32_t* blf = &bl[nt >> 1][(nt & 1) * 2];
                    mma16816(acc[mt][nt], ah[mt], bhf);
                    mma16816(acc[mt][nt], ah[mt], blf);
                    mma16816(acc[mt][nt], al[mt], bhf);
                }
        }
        __syncthreads();
    }

    #pragma unroll
    for (int mt = 0; mt < 2; mt++) {
        const int m = m0 + wm + mt * 16 + (lane >> 2);
        #pragma unroll
        for (int nt = 0; nt < 8; nt++) {
            const int n = n0 + wn + nt * 8 + (lane & 3) * 2;
            if (Oh) {
                #pragma unroll
                for (int rr = 0; rr < 2; rr++) {
                    const size_t idx = (size_t)(m + rr * 8) * N + n;
                    float a0 = acc[mt][nt][rr * 2], a1 = acc[mt][nt][rr * 2 + 1];
                    __nv_bfloat162 hh, ll;
                    hh.x = __float2bfloat16(a0);
                    hh.y = __float2bfloat16(a1);
                    ll.x = __float2bfloat16(a0 - __bfloat162float(hh.x));
                    ll.y = __float2bfloat16(a1 - __bfloat162float(hh.y));
                    *(__nv_bfloat162*)&Oh[idx] = hh;
                    *(__nv_bfloat162*)&Ol[idx] = ll;
                }
            } else {
                float2 o0 = make_float2(acc[mt][nt][0], acc[mt][nt][1]);
                float2 o1 = make_float2(acc[mt][nt][2], acc[mt][nt][3]);
                if (R) {
                    const float2 r0 = *(const float2*)&R[(size_t)m * N + n];
                    const float2 r1 = *(const float2*)&R[(size_t)(m + 8) * N + n];
                    o0.x += r0.x; o0.y += r0.y;
                    o1.x += r1.x; o1.y += r1.y;
                }
                *(float2*)&C[(size_t)m * N + n] = o0;
                *(float2*)&C[(size_t)(m + 8) * N + n] = o1;
            }
        }
    }
}

// ===========================================================================
// HMMA score kernel: S[i,j] = (q_i.k_j + q2_i.Er[L-1-(i-j)]) / 8, j <= i tiles.
// Triangular grid: blockIdx.x in [0, 136) -> (ti, tj).
// ===========================================================================
#define SC_SQH 0
#define SC_SQL 8192
#define SC_S2H 16384
#define SC_S2L 24576
#define SC_SKH 32768
#define SC_SKL 40960
#define SC_SEH 49152
#define SC_SEL 65536
#define SC_SR  81920
#define SC_SMEM (81920 + 4 * 5632)   // 104448

__global__ __launch_bounds__(128)
void score_tc(const __nv_bfloat16* __restrict__ qh, const __nv_bfloat16* __restrict__ ql,
              const __nv_bfloat16* __restrict__ q2h, const __nv_bfloat16* __restrict__ q2l,
              const __nv_bfloat16* __restrict__ kh, const __nv_bfloat16* __restrict__ kl,
              const __nv_bfloat16* __restrict__ eh, const __nv_bfloat16* __restrict__ el,
              float* __restrict__ p)
{
    const int x = blockIdx.x;
    int ti = (int)((__fsqrt_rn(8.0f * x + 1.0f) - 1.0f) * 0.5f);
    if (ti * (ti + 1) / 2 > x) ti--;
    else if ((ti + 1) * (ti + 2) / 2 <= x) ti++;
    const int tj = x - ti * (ti + 1) / 2;
    const int z = blockIdx.y;
    const int i0 = ti * 64, j0 = tj * 64;
    const int h = z >> 2, b = z & 3;
    const int rbase = L_ - 64 - i0 + j0;

    extern __shared__ __align__(16) char smem[];
    const uint32_t sb = smem_u32(smem);
    const int tid = threadIdx.x;
    const int lane = tid & 31, w = tid >> 5;

    auto load64 = [&](uint32_t st, const __nv_bfloat16* g) {
        #pragma unroll
        for (int t = 0; t < 4; t++) {
            int cid = tid + t * 128;
            int row = cid >> 3, c = cid & 7;
            cpa16(sb + st + row * 128 + ((c ^ (row & 7)) * 16),
                  g + (size_t)row * D_ + c * 8);
        }
    };
    const size_t qoff = (size_t)(b * L_ + i0) * D_ + h * 64;
    const size_t koff = (size_t)(b * L_ + j0) * D_ + h * 64;
    load64(SC_SQH, qh  + qoff);
    load64(SC_SQL, ql  + qoff);
    load64(SC_S2H, q2h + qoff);
    load64(SC_S2L, q2l + qoff);
    load64(SC_SKH, kh  + koff);
    load64(SC_SKL, kl  + koff);
    {
        const __nv_bfloat16* ehp = eh + (size_t)h * L_ * 64;
        const __nv_bfloat16* elp = el + (size_t)h * L_ * 64;
        #pragma unroll
        for (int t = 0; t < 8; t++) {
            int cid = tid + t * 128;
            int row = cid >> 3, c = cid & 7;
            int r = rbase + row;
            int sz = (r < L_) ? 16 : 0;
            int rc = (r < L_) ? r : 0;
            uint32_t so = row * 128 + ((c ^ (row & 7)) * 16);
            cpa16z(sb + SC_SEH + so, ehp + (size_t)rc * 64 + c * 8, sz);
            cpa16z(sb + SC_SEL + so, elp + (size_t)rc * 64 + c * 8, sz);
        }
    }
    asm volatile("cp.async.commit_group;" ::: "memory");
    asm volatile("cp.async.wait_group 0;" ::: "memory");
    __syncthreads();

    float aqk[8][4], arl[10][4];
    #pragma unroll
    for (int i = 0; i < 8; i++)
        #pragma unroll
        for (int q = 0; q < 4; q++) aqk[i][q] = 0.f;
    #pragma unroll
    for (int i = 0; i < 10; i++)
        #pragma unroll
        for (int q = 0; q < 4; q++) arl[i][q] = 0.f;

    const int t0w = 48 - 16 * w;

    auto ldA = [&](uint32_t st, int k16, uint32_t* r) {
        int row = 16 * w + (lane & 15);
        int c = (k16 >> 3) + (lane >> 4);
        ldsm_x4(r, sb + st + row * 128 + ((c ^ (row & 7)) * 16));
    };
    auto ldB = [&](uint32_t st, int nrow0, int k16, uint32_t* r) {
        int row = nrow0 + (lane >> 4) * 8 + (lane & 7);
        int c = (k16 >> 3) + ((lane >> 3) & 1);
        ldsm_x4(r, sb + st + row * 128 + ((c ^ (row & 7)) * 16));
    };

    #pragma unroll
    for (int k16 = 0; k16 < 64; k16 += 16) {
        uint32_t Aqh[4], Aql[4], A2h[4], A2l[4];
        ldA(SC_SQH, k16, Aqh);
        ldA(SC_SQL, k16, Aql);
        ldA(SC_S2H, k16, A2h);
        ldA(SC_S2L, k16, A2l);
        #pragma unroll
        for (int pg = 0; pg < 4; pg++) {
            uint32_t Bh[4], Bl[4];
            ldB(SC_SKH, pg * 16, k16, Bh);
            ldB(SC_SKL, pg * 16, k16, Bl);
            mma16816(aqk[2 * pg],     Aqh, Bh);
            mma16816(aqk[2 * pg + 1], Aqh, Bh + 2);
            mma16816(aqk[2 * pg],     Aqh, Bl);
            mma16816(aqk[2 * pg + 1], Aqh, Bl + 2);
            mma16816(aqk[2 * pg],     Aql, Bh);
            mma16816(aqk[2 * pg + 1], Aql, Bh + 2);
        }
        #pragma unroll
        for (int pg = 0; pg < 5; pg++) {
            uint32_t Bh[4], Bl[4];
            ldB(SC_SEH, t0w + pg * 16, k16, Bh);
            ldB(SC_SEL, t0w + pg * 16, k16, Bl);
            mma16816(arl[2 * pg],     A2h, Bh);
            mma16816(arl[2 * pg + 1], A2h, Bh + 2);
            mma16816(arl[2 * pg],     A2h, Bl);
            mma16816(arl[2 * pg + 1], A2h, Bl + 2);
            mma16816(arl[2 * pg],     A2l, Bh);
            mma16816(arl[2 * pg + 1], A2l, Bh + 2);
        }
    }

    float* Rs = (float*)(smem + SC_SR + w * 5632);   // 16 x 88 fp32
    const int r0 = lane >> 2, cb = (lane & 3) * 2;
    #pragma unroll
    for (int nt = 0; nt < 10; nt++) {
        int tb = nt * 8 + cb;
        Rs[r0 * 88 + tb]           = arl[nt][0];
        Rs[r0 * 88 + tb + 1]       = arl[nt][1];
        Rs[(r0 + 8) * 88 + tb]     = arl[nt][2];
        Rs[(r0 + 8) * 88 + tb + 1] = arl[nt][3];
    }
    __syncwarp();

    #pragma unroll
    for (int nt = 0; nt < 8; nt++) {
        int jj = nt * 8 + cb;
        float2 o0, o1;
        o0.x = (aqk[nt][0] + Rs[r0 * 88 + 15 + jj - r0]) * 0.125f;
        o0.y = (aqk[nt][1] + Rs[r0 * 88 + 16 + jj - r0]) * 0.125f;
        o1.x = (aqk[nt][2] + Rs[(r0 + 8) * 88 + 7 + jj - r0]) * 0.125f;
        o1.y = (aqk[nt][3] + Rs[(r0 + 8) * 88 + 8 + jj - r0]) * 0.125f;
        size_t base = ((size_t)z * L_ + i0 + 16 * w + r0) * L_ + j0 + jj;
        *(float2*)&p[base]          = o0;
        *(float2*)&p[base + 8 * L_] = o1;
    }
}

// ===========================================================================
// Single-pass row softmax; loads ONLY j <= i (predicated), writes full row
// (zeros for j > i via exp(-FLT_MAX) = 0).
// ===========================================================================
__global__ __launch_bounds__(256)
void softmax1p(float* __restrict__ p)
{
    const int i = blockIdx.x, z = blockIdx.y, tid = threadIdx.x;
    float* row = p + ((size_t)z * L_ + i) * L_;
    __shared__ float sh[8];

    const int j0 = tid * 4;
    float4 x;
    if (j0 <= i) {
        x = *(const float4*)&row[j0];
        if (j0 + 1 > i) x.y = -FLT_MAX;
        if (j0 + 2 > i) x.z = -FLT_MAX;
        if (j0 + 3 > i) x.w = -FLT_MAX;
    } else {
        x = make_float4(-FLT_MAX, -FLT_MAX, -FLT_MAX, -FLT_MAX);
    }

    float m = fmaxf(fmaxf(x.x, x.y), fmaxf(x.z, x.w));
    #pragma unroll
    for (int o = 16; o > 0; o >>= 1) m = fmaxf(m, __shfl_xor_sync(0xffffffffu, m, o));
    if ((tid & 31) == 0) sh[tid >> 5] = m;
    __syncthreads();
    float mt = -FLT_MAX;
    #pragma unroll
    for (int wv = 0; wv < 8; wv++) mt = fmaxf(mt, sh[wv]);
    __syncthreads();

    float4 e;
    e.x = __expf(x.x - mt);
    e.y = __expf(x.y - mt);
    e.z = __expf(x.z - mt);
    e.w = __expf(x.w - mt);
    float s = e.x + e.y + e.z + e.w;
    #pragma unroll
    for (int o = 16; o > 0; o >>= 1) s += __shfl_xor_sync(0xffffffffu, s, o);
    if ((tid & 31) == 0) sh[tid >> 5] = s;
    __syncthreads();
    float st = 0.f;
    #pragma unroll
    for (int wv = 0; wv < 8; wv++) st += sh[wv];
    const float inv = 1.0f / st;

    e.x *= inv; e.y *= inv; e.z *= inv; e.w *= inv;
    *(float4*)&row[j0] = e;
}

// ===========================================================================
// HMMA pv: out[i,d] = sum_{j<=i} p[i,j] v[j,d]; writes att bf16 hi/lo directly.
// 128 threads (4 warps x 16 rows), j-chunks of 32, double-buffered v.
// ===========================================================================
__global__ __launch_bounds__(128)
void pv_tc(const float* __restrict__ p,
           const __nv_bfloat16* __restrict__ vh, const __nv_bfloat16* __restrict__ vl,
           __nv_bfloat16* __restrict__ oh, __nv_bfloat16* __restrict__ ol)
{
    const int ti = blockIdx.x, z = blockIdx.y;
    const int i0 = ti * 64;
    const int h = z >> 2, b = z & 3;
    const int tid = threadIdx.x;
    const int lane = tid & 31, w = tid >> 5;

    __shared__ __align__(128) char sv[2][2][4096];   // [buf][h/l][32 rows x 128B]
    __shared__ __align__(128) char sp[4][2][1280];   // [warp][h/l][16 rows x 80B]
    const uint32_t svb = smem_u32(&sv[0][0][0]);
    const uint32_t spw = smem_u32(&sp[w][0][0]);

    auto loadV = [&](int kj, int bi) {
        #pragma unroll
        for (int t = 0; t < 4; t++) {
            int cid = tid + t * 128;
            int sel = cid >> 8, rid = (cid >> 3) & 31, c = cid & 7;
            const __nv_bfloat16* g = (sel ? vl : vh)
                + ((size_t)(b * L_ + kj + rid) * D_ + h * 64 + c * 8);
            cpa16(svb + bi * 8192 + sel * 4096 + rid * 128 + ((c ^ (rid & 7)) * 16), g);
        }
        asm volatile("cp.async.commit_group;" ::: "memory");
    };

    float acc[8][4];
    #pragma unroll
    for (int i = 0; i < 8; i++)
        #pragma unroll
        for (int q = 0; q < 4; q++) acc[i][q] = 0.f;

    const int nch = (i0 + 64) >> 5;
    loadV(0, 0);

    for (int c = 0; c < nch; c++) {
        const int bi = c & 1;
        __syncthreads();
        if (c + 1 < nch) loadV((c + 1) * 32, bi ^ 1);

        {
            const int row = lane >> 1, chalf = lane & 1;
            const float* gp = p + ((size_t)z * L_ + i0 + 16 * w + row) * L_
                                + c * 32 + chalf * 16;
            uint32_t* ph = (uint32_t*)(&sp[w][0][0] + row * 80 + chalf * 32);
            uint32_t* pl = (uint32_t*)(&sp[w][1][0] + row * 80 + chalf * 32);
            #pragma unroll
            for (int q = 0; q < 4; q++) {
                float4 v = *(const float4*)(gp + q * 4);
                __nv_bfloat162 h0, h1, l0, l1;
                h0.x = __float2bfloat16(v.x); h0.y = __float2bfloat16(v.y);
                h1.x = __float2bfloat16(v.z); h1.y = __float2bfloat16(v.w);
                l0.x = __float2bfloat16(v.x - __bfloat162float(h0.x));
                l0.y = __float2bfloat16(v.y - __bfloat162float(h0.y));
                l1.x = __float2bfloat16(v.z - __bfloat162float(h1.x));
                l1.y = __float2bfloat16(v.w - __bfloat162float(h1.y));
                ph[q * 2]     = *(uint32_t*)&h0;
                ph[q * 2 + 1] = *(uint32_t*)&h1;
                pl[q * 2]     = *(uint32_t*)&l0;
                pl[q * 2 + 1] = *(uint32_t*)&l1;
            }
        }
        __syncwarp();
        if (c + 1 < nch) asm volatile("cp.async.wait_group 1;" ::: "memory");
        else             asm volatile("cp.async.wait_group 0;" ::: "memory");
        __syncthreads();

        #pragma unroll
        for (int k16 = 0; k16 < 32; k16 += 16) {
            uint32_t Aph[4], Apl[4];
            {
                int arow = lane & 15;
                int ac = (k16 >> 3) + (lane >> 4);
                ldsm_x4(Aph, spw + arow * 80 + ac * 16);
                ldsm_x4(Apl, spw + 1280 + arow * 80 + ac * 16);
            }
            #pragma unroll
            for (int p4 = 0; p4 < 4; p4++) {
                uint32_t Bh[4], Bl[4];
                int krow = k16 + ((lane >> 3) & 1) * 8 + (lane & 7);
                int cc = p4 * 2 + (lane >> 4);
                uint32_t off = krow * 128 + ((cc ^ (krow & 7)) * 16);
                ldsm_x4_t(Bh, svb + bi * 8192 + off);
                ldsm_x4_t(Bl, svb + bi * 8192 + 4096 + off);
                mma16816(acc[2 * p4],     Aph, Bh);
                mma16816(acc[2 * p4 + 1], Aph, Bh + 2);
                mma16816(acc[2 * p4],     Aph, Bl);
                mma16816(acc[2 * p4 + 1], Aph, Bl + 2);
                mma16816(acc[2 * p4],     Apl, Bh);
                mma16816(acc[2 * p4 + 1], Apl, Bh + 2);
            }
        }
    }

    const int r0 = lane >> 2, cb = (lane & 3) * 2;
    #pragma unroll
    for (int nt = 0; nt < 8; nt++) {
        const int d = nt * 8 + cb;
        #pragma unroll
        for (int rr = 0; rr < 2; rr++) {
            const int i = i0 + 16 * w + r0 + rr * 8;
            const size_t idx = (size_t)(b * L_ + i) * D_ + h * 64 + d;
            float a0 = acc[nt][rr * 2], a1 = acc[nt][rr * 2 + 1];
            __nv_bfloat162 hh, ll;
            hh.x = __float2bfloat16(a0);
            hh.y = __float2bfloat16(a1);
            ll.x = __float2bfloat16(a0 - __bfloat162float(hh.x));
            ll.y = __float2bfloat16(a1 - __bfloat162float(hh.y));
            *(__nv_bfloat162*)&oh[idx] = hh;
            *(__nv_bfloat162*)&ol[idx] = ll;
        }
    }
}

// ===========================================================================
// LayerNorm
// ===========================================================================
__global__ __launch_bounds__(256)
void ln_kernel(const float* __restrict__ x, const float* __restrict__ gam,
               const float* __restrict__ bet, float* __restrict__ y)
{
    const int r = blockIdx.x, tid = threadIdx.x;
    __shared__ float sh[16];
    const float* xr = x + (size_t)r * D_;
    float4 xv = *(const float4*)&xr[tid * 4];
    float s  = xv.x + xv.y + xv.z + xv.w;
    float ss = xv.x*xv.x + xv.y*xv.y + xv.z*xv.z + xv.w*xv.w;
    #pragma unroll
    for (int o = 16; o > 0; o >>= 1) {
        s  += __shfl_xor_sync(0xffffffffu, s,  o);
        ss += __shfl_xor_sync(0xffffffffu, ss, o);
    }
    if ((tid & 31) == 0) { sh[tid >> 5] = s; sh[8 + (tid >> 5)] = ss; }
    __syncthreads();
    float st = 0.f, sst = 0.f;
    #pragma unroll
    for (int wv = 0; wv < 8; wv++) { st += sh[wv]; sst += sh[8 + wv]; }
    const float mu  = st * (1.0f / D_);
    const float var = sst * (1.0f / D_) - mu * mu;
    const float rs  = rsqrtf(var + 1e-5f);
    float4 gv = *(const float4*)&gam[tid * 4];
    float4 bv = *(const float4*)&bet[tid * 4];
    float4 o4;
    o4.x = (xv.x - mu) * rs * gv.x + bv.x;
    o4.y = (xv.y - mu) * rs * gv.y + bv.y;
    o4.z = (xv.z - mu) * rs * gv.z + bv.z;
    o4.w = (xv.w - mu) * rs * gv.w + bv.w;
    *(float4*)&y[(size_t)r * D_ + tid * 4] = o4;
}

// ===========================================================================
// Launch
// ===========================================================================
extern "C" void kernel_launch(void* const* d_in, const int* in_sizes, int n_in,
                              void* d_out, int out_size)
{
    const float* q_in = (const float*)d_in[0];
    const float* k_in = (const float*)d_in[1];
    const float* v_in = (const float*)d_in[2];
    const float* Wq   = (const float*)d_in[3];
    const float* Wq2  = (const float*)d_in[4];
    const float* Wk   = (const float*)d_in[5];
    const float* Wv   = (const float*)d_in[6];
    const float* Wo   = (const float*)d_in[7];
    const float* ln_g = (const float*)d_in[8];
    const float* ln_b = (const float*)d_in[9];
    const float* Er   = (const float*)d_in[10];
    (void)in_sizes; (void)n_in;

    float *px, *pfb;
    __nv_bfloat16 *ah, *al, *bh, *bl, *ch, *cl, *wh, *wl;
    __nv_bfloat16 *qh, *ql, *q2h, *q2l, *kh, *kl, *vh, *vl, *eh, *el;
    cudaGetSymbolAddress((void**)&px,  g_x);
    cudaGetSymbolAddress((void**)&pfb, g_pfb);
    cudaGetSymbolAddress((void**)&ah,  g_ah);
    cudaGetSymbolAddress((void**)&al,  g_al);
    cudaGetSymbolAddress((void**)&bh,  g_bh);
    cudaGetSymbolAddress((void**)&bl,  g_bl);
    cudaGetSymbolAddress((void**)&ch,  g_ch);
    cudaGetSymbolAddress((void**)&cl,  g_cl);
    cudaGetSymbolAddress((void**)&wh,  g_wh);
    cudaGetSymbolAddress((void**)&wl,  g_wl);
    cudaGetSymbolAddress((void**)&qh,  g_qh);
    cudaGetSymbolAddress((void**)&ql,  g_ql);
    cudaGetSymbolAddress((void**)&q2h, g_q2h);
    cudaGetSymbolAddress((void**)&q2l, g_q2l);
    cudaGetSymbolAddress((void**)&kh,  g_kh);
    cudaGetSymbolAddress((void**)&kl,  g_kl);
    cudaGetSymbolAddress((void**)&vh,  g_vh);
    cudaGetSymbolAddress((void**)&vl,  g_vl);
    cudaGetSymbolAddress((void**)&eh,  g_eh);
    cudaGetSymbolAddress((void**)&el,  g_el);

    float* y_out = (float*)d_out;
    const long long ysz = (long long)B_ * L_ * D_;
    const long long psz = (long long)HB_ * L_ * L_;
    float* p_buf = ((long long)out_size >= ysz + psz) ? (y_out + ysz) : pfb;

    const int gsmem = 2 * STAGE_BYTES;
    cudaFuncSetAttribute(gemm_tc, cudaFuncAttributeMaxDynamicSharedMemorySize, gsmem);
    cudaFuncSetAttribute(score_tc, cudaFuncAttributeMaxDynamicSharedMemorySize, SC_SMEM);

    const int M = B_ * L_;
    const dim3 ggemm(D_ / 128, M / 128);
    const size_t WSZ = (size_t)D_ * D_;

    // all splits upfront
    split_act_all<<<dim3(4096, 1, 4), 256>>>(q_in, k_in, v_in, Er,
                                             ah, al, bh, bl, ch, cl, eh, el);
    split_w_all<<<dim3(32, 32, 5), 256>>>(Wq, Wq2, Wk, Wv, Wo, wh, wl);

    // projections -> bf16 hi/lo outputs
    gemm_tc<<<ggemm, 256, gsmem>>>(ah, al, wh + 0 * WSZ, wl + 0 * WSZ,
                                   nullptr, nullptr, qh, ql, D_, D_);
    gemm_tc<<<ggemm, 256, gsmem>>>(ah, al, wh + 1 * WSZ, wl + 1 * WSZ,
                                   nullptr, nullptr, q2h, q2l, D_, D_);
    gemm_tc<<<ggemm, 256, gsmem>>>(bh, bl, wh + 2 * WSZ, wl + 2 * WSZ,
                                   nullptr, nullptr, kh, kl, D_, D_);
    gemm_tc<<<ggemm, 256, gsmem>>>(ch, cl, wh + 3 * WSZ, wl + 3 * WSZ,
                                   nullptr, nullptr, vh, vl, D_, D_);

    // attention middle: scores (tri-grid), softmax, pv
    score_tc<<<dim3(136, HB_), 128, SC_SMEM>>>(qh, ql, q2h, q2l, kh, kl, eh, el, p_buf);
    softmax1p<<<dim3(L_, HB_), 256>>>(p_buf);
    pv_tc<<<dim3(16, HB_), 128>>>(p_buf, vh, vl, ah, al);   // att -> ah/al

    // Wo GEMM (fp32 out + residual), then LN
    gemm_tc<<<ggemm, 256, gsmem>>>(ah, al, wh + 4 * WSZ, wl + 4 * WSZ,
                                   px, q_in, nullptr, nullptr, D_, D_);
    ln_kernel<<<B_ * L_, 256>>>(px, ln_g, ln_b, y_out);
}

// round 7
// speedup vs baseline: 1.5928x; 1.0948x over previous
#include <cuda_runtime.h>
#include <cuda_bf16.h>
#include <cfloat>
#include <cstdint>

// Problem constants
#define B_  4
#define L_  1024
#define D_  1024
#define H_  16
#define HB_ 64   // H*B

// ===========================================================================
// Scratch (static __device__)
// ===========================================================================
__device__ float g_x  [B_ * L_ * D_];
__device__ float g_pfb[HB_ * L_ * L_];               // fallback p buffer
__device__ __nv_bfloat16 g_ah[B_ * L_ * D_];         // q_in split hi / att hi
__device__ __nv_bfloat16 g_al[B_ * L_ * D_];         // q_in split lo / att lo
__device__ __nv_bfloat16 g_bh[B_ * L_ * D_];         // k_in split hi
__device__ __nv_bfloat16 g_bl[B_ * L_ * D_];         // k_in split lo
__device__ __nv_bfloat16 g_ch[B_ * L_ * D_];         // v_in split hi
__device__ __nv_bfloat16 g_cl[B_ * L_ * D_];         // v_in split lo
__device__ __nv_bfloat16 g_wh[5 * D_ * D_];          // weights^T split hi [N,K]
__device__ __nv_bfloat16 g_wl[5 * D_ * D_];          // weights^T split lo [N,K]
__device__ __nv_bfloat16 g_qh [B_ * L_ * D_];
__device__ __nv_bfloat16 g_ql [B_ * L_ * D_];
__device__ __nv_bfloat16 g_q2h[B_ * L_ * D_];
__device__ __nv_bfloat16 g_q2l[B_ * L_ * D_];
__device__ __nv_bfloat16 g_kh [B_ * L_ * D_];
__device__ __nv_bfloat16 g_kl [B_ * L_ * D_];
__device__ __nv_bfloat16 g_vh [B_ * L_ * D_];
__device__ __nv_bfloat16 g_vl [B_ * L_ * D_];
__device__ __nv_bfloat16 g_eh [H_ * L_ * 64];
__device__ __nv_bfloat16 g_el [H_ * L_ * 64];

// ===========================================================================
// PTX helpers (base sm_103-legal)
// ===========================================================================
__device__ __forceinline__ uint32_t smem_u32(const void* p) {
    uint32_t a;
    asm("{ .reg .u64 t; cvta.to.shared.u64 t, %1; cvt.u32.u64 %0, t; }"
        : "=r"(a) : "l"(p));
    return a;
}
__device__ __forceinline__ void cpa16(uint32_t saddr, const void* g) {
    asm volatile("cp.async.cg.shared.global [%0], [%1], 16;" :: "r"(saddr), "l"(g));
}
__device__ __forceinline__ void cpa16z(uint32_t saddr, const void* g, int sz) {
    asm volatile("cp.async.cg.shared.global [%0], [%1], 16, %2;"
                 :: "r"(saddr), "l"(g), "r"(sz));
}
__device__ __forceinline__ void ldsm_x4(uint32_t* r, uint32_t addr) {
    asm volatile("ldmatrix.sync.aligned.m8n8.x4.shared.b16 {%0,%1,%2,%3}, [%4];"
                 : "=r"(r[0]), "=r"(r[1]), "=r"(r[2]), "=r"(r[3]) : "r"(addr));
}
__device__ __forceinline__ void ldsm_x4_t(uint32_t* r, uint32_t addr) {
    asm volatile("ldmatrix.sync.aligned.m8n8.x4.trans.shared.b16 {%0,%1,%2,%3}, [%4];"
                 : "=r"(r[0]), "=r"(r[1]), "=r"(r[2]), "=r"(r[3]) : "r"(addr));
}
__device__ __forceinline__ void mma16816(float* c, const uint32_t* a, const uint32_t* b) {
    asm volatile(
        "mma.sync.aligned.m16n8k16.row.col.f32.bf16.bf16.f32 "
        "{%0,%1,%2,%3}, {%4,%5,%6,%7}, {%8,%9}, {%0,%1,%2,%3};"
        : "+f"(c[0]), "+f"(c[1]), "+f"(c[2]), "+f"(c[3])
        : "r"(a[0]), "r"(a[1]), "r"(a[2]), "r"(a[3]), "r"(b[0]), "r"(b[1]));
}

// ===========================================================================
// fp32 -> bf16 hi/lo splits: all activations + Er in one launch (grid.z=4)
// ===========================================================================
__global__ __launch_bounds__(256)
void split_act_all(const float* __restrict__ x0, const float* __restrict__ x1,
                   const float* __restrict__ x2, const float* __restrict__ x3,
                   __nv_bfloat16* __restrict__ h0, __nv_bfloat16* __restrict__ l0,
                   __nv_bfloat16* __restrict__ h1, __nv_bfloat16* __restrict__ l1,
                   __nv_bfloat16* __restrict__ h2, __nv_bfloat16* __restrict__ l2,
                   __nv_bfloat16* __restrict__ h3, __nv_bfloat16* __restrict__ l3)
{
    const int zz = blockIdx.z;
    const float* x; __nv_bfloat16 *hi, *lo; int n;
    if      (zz == 0) { x = x0; hi = h0; lo = l0; n = B_ * L_ * D_; }
    else if (zz == 1) { x = x1; hi = h1; lo = l1; n = B_ * L_ * D_; }
    else if (zz == 2) { x = x2; hi = h2; lo = l2; n = B_ * L_ * D_; }
    else              { x = x3; hi = h3; lo = l3; n = H_ * L_ * 64; }
    int i = (blockIdx.x * 256 + threadIdx.x) * 4;
    if (i >= n) return;
    float4 v = *(const float4*)&x[i];
    __nv_bfloat16 a0 = __float2bfloat16(v.x);
    __nv_bfloat16 a1 = __float2bfloat16(v.y);
    __nv_bfloat16 a2 = __float2bfloat16(v.z);
    __nv_bfloat16 a3 = __float2bfloat16(v.w);
    __nv_bfloat162 hp0; hp0.x = a0; hp0.y = a1;
    __nv_bfloat162 hp1; hp1.x = a2; hp1.y = a3;
    *(__nv_bfloat162*)&hi[i]     = hp0;
    *(__nv_bfloat162*)&hi[i + 2] = hp1;
    __nv_bfloat162 lp0, lp1;
    lp0.x = __float2bfloat16(v.x - __bfloat162float(a0));
    lp0.y = __float2bfloat16(v.y - __bfloat162float(a1));
    lp1.x = __float2bfloat16(v.z - __bfloat162float(a2));
    lp1.y = __float2bfloat16(v.w - __bfloat162float(a3));
    *(__nv_bfloat162*)&lo[i]     = lp0;
    *(__nv_bfloat162*)&lo[i + 2] = lp1;
}

// All 5 weights: W[K,N] fp32 -> Wt[N,K] bf16 hi/lo (transpose + split), grid.z=5
__global__ __launch_bounds__(256)
void split_w_all(const float* __restrict__ W0, const float* __restrict__ W1,
                 const float* __restrict__ W2, const float* __restrict__ W3,
                 const float* __restrict__ W4,
                 __nv_bfloat16* __restrict__ th, __nv_bfloat16* __restrict__ tl)
{
    const float* W;
    switch (blockIdx.z) {
        case 0: W = W0; break;
        case 1: W = W1; break;
        case 2: W = W2; break;
        case 3: W = W3; break;
        default: W = W4; break;
    }
    __nv_bfloat16* h = th + (size_t)blockIdx.z * D_ * D_;
    __nv_bfloat16* l = tl + (size_t)blockIdx.z * D_ * D_;
    __shared__ float t[32][33];
    const int bx = blockIdx.x * 32;
    const int by = blockIdx.y * 32;
    const int tx = threadIdx.x & 31;
    const int ty = threadIdx.x >> 5;
    #pragma unroll
    for (int r = ty; r < 32; r += 8)
        t[r][tx] = W[(size_t)(by + r) * D_ + bx + tx];
    __syncthreads();
    #pragma unroll
    for (int r = ty; r < 32; r += 8) {
        float v = t[tx][r];
        __nv_bfloat16 hh = __float2bfloat16(v);
        h[(size_t)(bx + r) * D_ + by + tx] = hh;
        l[(size_t)(bx + r) * D_ + by + tx] = __float2bfloat16(v - __bfloat162float(hh));
    }
}

// ===========================================================================
// HMMA split-bf16 GEMM body: C = (Ah+Al)[M,K] @ (Bh+Bl)[N,K]^T
// Output: fp32 C (+R residual) OR bf16 hi/lo pair (Oh/Ol).
// ===========================================================================
#define TSTRIDE 40
#define TILE_BYTES (128 * TSTRIDE * 2)
#define STAGE_BYTES (4 * TILE_BYTES)

__device__ __forceinline__ void gemm_body(
    const __nv_bfloat16* __restrict__ Ah, const __nv_bfloat16* __restrict__ Al,
    const __nv_bfloat16* __restrict__ Bh, const __nv_bfloat16* __restrict__ Bl,
    float* __restrict__ C, const float* __restrict__ R,
    __nv_bfloat16* __restrict__ Oh, __nv_bfloat16* __restrict__ Ol,
    int K, int N, char* smem)
{
    const uint32_t sb0 = smem_u32(smem);
    const int tid  = threadIdx.x;
    const int wid  = tid >> 5;
    const int lane = tid & 31;
    const int m0 = blockIdx.y * 128;
    const int n0 = blockIdx.x * 128;
    const int wm = (wid & 3) * 32;
    const int wn = (wid >> 2) * 64;

    const __nv_bfloat16* gT[4] = {
        Ah + (size_t)m0 * K, Al + (size_t)m0 * K,
        Bh + (size_t)n0 * K, Bl + (size_t)n0 * K };

    auto load_chunk = [&](int c, int st) {
        const uint32_t sb = sb0 + st * STAGE_BYTES;
        const int k0 = c * 32;
        #pragma unroll
        for (int t = 0; t < 4; t++) {
            const __nv_bfloat16* g = gT[t] + k0;
            const uint32_t tb = sb + t * TILE_BYTES;
            #pragma unroll
            for (int it = 0; it < 2; it++) {
                int o   = tid + it * 256;
                int row = o >> 2, c16 = o & 3;
                cpa16(tb + row * (TSTRIDE * 2) + c16 * 16,
                      g + (size_t)row * K + c16 * 8);
            }
        }
        asm volatile("cp.async.commit_group;" ::: "memory");
    };

    float acc[2][8][4];
    #pragma unroll
    for (int i = 0; i < 2; i++)
        #pragma unroll
        for (int j = 0; j < 8; j++)
            #pragma unroll
            for (int q = 0; q < 4; q++) acc[i][j][q] = 0.f;

    const int arow = lane & 15;
    const int acolq = (lane >> 4) * 8;
    const int nrow = ((lane >> 4) * 8) + (lane & 7);
    const int bcolq = ((lane >> 3) & 1) * 8;

    const int NC = K / 32;
    load_chunk(0, 0);

    for (int c = 0; c < NC; ++c) {
        const int st = c & 1;
        if (c + 1 < NC) {
            load_chunk(c + 1, st ^ 1);
            asm volatile("cp.async.wait_group 1;" ::: "memory");
        } else {
            asm volatile("cp.async.wait_group 0;" ::: "memory");
        }
        __syncthreads();

        const uint32_t sb  = sb0 + st * STAGE_BYTES;
        const uint32_t sAh = sb;
        const uint32_t sAl = sb + TILE_BYTES;
        const uint32_t sBh = sb + 2 * TILE_BYTES;
        const uint32_t sBl = sb + 3 * TILE_BYTES;

        #pragma unroll
        for (int k16 = 0; k16 < 32; k16 += 16) {
            uint32_t ah[2][4], al[2][4], bh[4][4], bl[4][4];
            #pragma unroll
            for (int mt = 0; mt < 2; mt++) {
                uint32_t off = ((wm + mt * 16 + arow) * TSTRIDE + k16 + acolq) * 2;
                ldsm_x4(ah[mt], sAh + off);
                ldsm_x4(al[mt], sAl + off);
            }
            #pragma unroll
            for (int p = 0; p < 4; p++) {
                uint32_t off = ((wn + p * 16 + nrow) * TSTRIDE + k16 + bcolq) * 2;
                ldsm_x4(bh[p], sBh + off);
                ldsm_x4(bl[p], sBl + off);
            }
            #pragma unroll
            for (int mt = 0; mt < 2; mt++)
                #pragma unroll
                for (int nt = 0; nt < 8; nt++) {
                    const uint32_t* bhf = &bh[nt >> 1][(nt & 1) * 2];
                    const uint32_t* blf = &bl[nt >> 1][(nt & 1) * 2];
                    mma16816(acc[mt][nt], ah[mt], bhf);
                    mma16816(acc[mt][nt], ah[mt], blf);
                    mma16816(acc[mt][nt], al[mt], bhf);
                }
        }
        __syncthreads();
    }

    #pragma unroll
    for (int mt = 0; mt < 2; mt++) {
        const int m = m0 + wm + mt * 16 + (lane >> 2);
        #pragma unroll
        for (int nt = 0; nt < 8; nt++) {
            const int n = n0 + wn + nt * 8 + (lane & 3) * 2;
            if (Oh) {
                #pragma unroll
                for (int rr = 0; rr < 2; rr++) {
                    const size_t idx = (size_t)(m + rr * 8) * N + n;
                    float a0 = acc[mt][nt][rr * 2], a1 = acc[mt][nt][rr * 2 + 1];
                    __nv_bfloat162 hh, ll;
                    hh.x = __float2bfloat16(a0);
                    hh.y = __float2bfloat16(a1);
                    ll.x = __float2bfloat16(a0 - __bfloat162float(hh.x));
                    ll.y = __float2bfloat16(a1 - __bfloat162float(hh.y));
                    *(__nv_bfloat162*)&Oh[idx] = hh;
                    *(__nv_bfloat162*)&Ol[idx] = ll;
                }
            } else {
                float2 o0 = make_float2(acc[mt][nt][0], acc[mt][nt][1]);
                float2 o1 = make_float2(acc[mt][nt][2], acc[mt][nt][3]);
                if (R) {
                    const float2 r0 = *(const float2*)&R[(size_t)m * N + n];
                    const float2 r1 = *(const float2*)&R[(size_t)(m + 8) * N + n];
                    o0.x += r0.x; o0.y += r0.y;
                    o1.x += r1.x; o1.y += r1.y;
                }
                *(float2*)&C[(size_t)m * N + n] = o0;
                *(float2*)&C[(size_t)(m + 8) * N + n] = o1;
            }
        }
    }
}

// Generic GEMM entry (used for Wo)
__global__ __launch_bounds__(256, 2)
void gemm_tc(const __nv_bfloat16* __restrict__ Ah, const __nv_bfloat16* __restrict__ Al,
             const __nv_bfloat16* __restrict__ Bh, const __nv_bfloat16* __restrict__ Bl,
             float* __restrict__ C, const float* __restrict__ R,
             __nv_bfloat16* __restrict__ Oh, __nv_bfloat16* __restrict__ Ol,
             int K, int N)
{
    extern __shared__ __align__(16) char smem[];
    gemm_body(Ah, Al, Bh, Bl, C, R, Oh, Ol, K, N, smem);
}

// Batched projection GEMMs: z selects (A, W, O) from static buffers.
__global__ __launch_bounds__(256, 2)
void gemm_proj4()
{
    extern __shared__ __align__(16) char smem[];
    const size_t WSZ = (size_t)D_ * D_;
    const __nv_bfloat16 *Ah, *Al;
    __nv_bfloat16 *Oh, *Ol;
    const int z = blockIdx.z;
    switch (z) {
        case 0:  Ah = g_ah; Al = g_al; Oh = g_qh;  Ol = g_ql;  break;
        case 1:  Ah = g_ah; Al = g_al; Oh = g_q2h; Ol = g_q2l; break;
        case 2:  Ah = g_bh; Al = g_bl; Oh = g_kh;  Ol = g_kl;  break;
        default: Ah = g_ch; Al = g_cl; Oh = g_vh;  Ol = g_vl;  break;
    }
    gemm_body(Ah, Al, g_wh + z * WSZ, g_wl + z * WSZ,
              nullptr, nullptr, Oh, Ol, D_, D_, smem);
}

// ===========================================================================
// HMMA score kernel: S[i,j] = (q_i.k_j + q2_i.Er[L-1-(i-j)]) / 8, j <= i tiles.
// Triangular grid: blockIdx.x in [0, 136) -> (ti, tj).
// ===========================================================================
#define SC_SQH 0
#define SC_SQL 8192
#define SC_S2H 16384
#define SC_S2L 24576
#define SC_SKH 32768
#define SC_SKL 40960
#define SC_SEH 49152
#define SC_SEL 65536
#define SC_SR  81920
#define SC_SMEM (81920 + 4 * 5632)   // 104448

__global__ __launch_bounds__(128)
void score_tc(const __nv_bfloat16* __restrict__ qh, const __nv_bfloat16* __restrict__ ql,
              const __nv_bfloat16* __restrict__ q2h, const __nv_bfloat16* __restrict__ q2l,
              const __nv_bfloat16* __restrict__ kh, const __nv_bfloat16* __restrict__ kl,
              const __nv_bfloat16* __restrict__ eh, const __nv_bfloat16* __restrict__ el,
              float* __restrict__ p)
{
    const int x = blockIdx.x;
    int ti = (int)((__fsqrt_rn(8.0f * x + 1.0f) - 1.0f) * 0.5f);
    if (ti * (ti + 1) / 2 > x) ti--;
    else if ((ti + 1) * (ti + 2) / 2 <= x) ti++;
    const int tj = x - ti * (ti + 1) / 2;
    const int z = blockIdx.y;
    const int i0 = ti * 64, j0 = tj * 64;
    const int h = z >> 2, b = z & 3;
    const int rbase = L_ - 64 - i0 + j0;

    extern __shared__ __align__(16) char smem[];
    const uint32_t sb = smem_u32(smem);
    const int tid = threadIdx.x;
    const int lane = tid & 31, w = tid >> 5;

    auto load64 = [&](uint32_t st, const __nv_bfloat16* g) {
        #pragma unroll
        for (int t = 0; t < 4; t++) {
            int cid = tid + t * 128;
            int row = cid >> 3, c = cid & 7;
            cpa16(sb + st + row * 128 + ((c ^ (row & 7)) * 16),
                  g + (size_t)row * D_ + c * 8);
        }
    };
    const size_t qoff = (size_t)(b * L_ + i0) * D_ + h * 64;
    const size_t koff = (size_t)(b * L_ + j0) * D_ + h * 64;
    load64(SC_SQH, qh  + qoff);
    load64(SC_SQL, ql  + qoff);
    load64(SC_S2H, q2h + qoff);
    load64(SC_S2L, q2l + qoff);
    load64(SC_SKH, kh  + koff);
    load64(SC_SKL, kl  + koff);
    {
        const __nv_bfloat16* ehp = eh + (size_t)h * L_ * 64;
        const __nv_bfloat16* elp = el + (size_t)h * L_ * 64;
        #pragma unroll
        for (int t = 0; t < 8; t++) {
            int cid = tid + t * 128;
            int row = cid >> 3, c = cid & 7;
            int r = rbase + row;
            int sz = (r < L_) ? 16 : 0;
            int rc = (r < L_) ? r : 0;
            uint32_t so = row * 128 + ((c ^ (row & 7)) * 16);
            cpa16z(sb + SC_SEH + so, ehp + (size_t)rc * 64 + c * 8, sz);
            cpa16z(sb + SC_SEL + so, elp + (size_t)rc * 64 + c * 8, sz);
        }
    }
    asm volatile("cp.async.commit_group;" ::: "memory");
    asm volatile("cp.async.wait_group 0;" ::: "memory");
    __syncthreads();

    float aqk[8][4], arl[10][4];
    #pragma unroll
    for (int i = 0; i < 8; i++)
        #pragma unroll
        for (int q = 0; q < 4; q++) aqk[i][q] = 0.f;
    #pragma unroll
    for (int i = 0; i < 10; i++)
        #pragma unroll
        for (int q = 0; q < 4; q++) arl[i][q] = 0.f;

    const int t0w = 48 - 16 * w;

    auto ldA = [&](uint32_t st, int k16, uint32_t* r) {
        int row = 16 * w + (lane & 15);
        int c = (k16 >> 3) + (lane >> 4);
        ldsm_x4(r, sb + st + row * 128 + ((c ^ (row & 7)) * 16));
    };
    auto ldB = [&](uint32_t st, int nrow0, int k16, uint32_t* r) {
        int row = nrow0 + (lane >> 4) * 8 + (lane & 7);
        int c = (k16 >> 3) + ((lane >> 3) & 1);
        ldsm_x4(r, sb + st + row * 128 + ((c ^ (row & 7)) * 16));
    };

    #pragma unroll
    for (int k16 = 0; k16 < 64; k16 += 16) {
        uint32_t Aqh[4], Aql[4], A2h[4], A2l[4];
        ldA(SC_SQH, k16, Aqh);
        ldA(SC_SQL, k16, Aql);
        ldA(SC_S2H, k16, A2h);
        ldA(SC_S2L, k16, A2l);
        #pragma unroll
        for (int pg = 0; pg < 4; pg++) {
            uint32_t Bh[4], Bl[4];
            ldB(SC_SKH, pg * 16, k16, Bh);
            ldB(SC_SKL, pg * 16, k16, Bl);
            mma16816(aqk[2 * pg],     Aqh, Bh);
            mma16816(aqk[2 * pg + 1], Aqh, Bh + 2);
            mma16816(aqk[2 * pg],     Aqh, Bl);
            mma16816(aqk[2 * pg + 1], Aqh, Bl + 2);
            mma16816(aqk[2 * pg],     Aql, Bh);
            mma16816(aqk[2 * pg + 1], Aql, Bh + 2);
        }
        #pragma unroll
        for (int pg = 0; pg < 5; pg++) {
            uint32_t Bh[4], Bl[4];
            ldB(SC_SEH, t0w + pg * 16, k16, Bh);
            ldB(SC_SEL, t0w + pg * 16, k16, Bl);
            mma16816(arl[2 * pg],     A2h, Bh);
            mma16816(arl[2 * pg + 1], A2h, Bh + 2);
            mma16816(arl[2 * pg],     A2h, Bl);
            mma16816(arl[2 * pg + 1], A2h, Bl + 2);
            mma16816(arl[2 * pg],     A2l, Bh);
            mma16816(arl[2 * pg + 1], A2l, Bh + 2);
        }
    }

    float* Rs = (float*)(smem + SC_SR + w * 5632);   // 16 x 88 fp32
    const int r0 = lane >> 2, cb = (lane & 3) * 2;
    #pragma unroll
    for (int nt = 0; nt < 10; nt++) {
        int tb = nt * 8 + cb;
        Rs[r0 * 88 + tb]           = arl[nt][0];
        Rs[r0 * 88 + tb + 1]       = arl[nt][1];
        Rs[(r0 + 8) * 88 + tb]     = arl[nt][2];
        Rs[(r0 + 8) * 88 + tb + 1] = arl[nt][3];
    }
    __syncwarp();

    #pragma unroll
    for (int nt = 0; nt < 8; nt++) {
        int jj = nt * 8 + cb;
        float2 o0, o1;
        o0.x = (aqk[nt][0] + Rs[r0 * 88 + 15 + jj - r0]) * 0.125f;
        o0.y = (aqk[nt][1] + Rs[r0 * 88 + 16 + jj - r0]) * 0.125f;
        o1.x = (aqk[nt][2] + Rs[(r0 + 8) * 88 + 7 + jj - r0]) * 0.125f;
        o1.y = (aqk[nt][3] + Rs[(r0 + 8) * 88 + 8 + jj - r0]) * 0.125f;
        size_t base = ((size_t)z * L_ + i0 + 16 * w + r0) * L_ + j0 + jj;
        *(float2*)&p[base]          = o0;
        *(float2*)&p[base + 8 * L_] = o1;
    }
}

// ===========================================================================
// Single-pass row softmax; loads ONLY j <= i (predicated), writes full row.
// ===========================================================================
__global__ __launch_bounds__(256)
void softmax1p(float* __restrict__ p)
{
    const int i = blockIdx.x, z = blockIdx.y, tid = threadIdx.x;
    float* row = p + ((size_t)z * L_ + i) * L_;
    __shared__ float sh[8];

    const int j0 = tid * 4;
    float4 x;
    if (j0 <= i) {
        x = *(const float4*)&row[j0];
        if (j0 + 1 > i) x.y = -FLT_MAX;
        if (j0 + 2 > i) x.z = -FLT_MAX;
        if (j0 + 3 > i) x.w = -FLT_MAX;
    } else {
        x = make_float4(-FLT_MAX, -FLT_MAX, -FLT_MAX, -FLT_MAX);
    }

    float m = fmaxf(fmaxf(x.x, x.y), fmaxf(x.z, x.w));
    #pragma unroll
    for (int o = 16; o > 0; o >>= 1) m = fmaxf(m, __shfl_xor_sync(0xffffffffu, m, o));
    if ((tid & 31) == 0) sh[tid >> 5] = m;
    __syncthreads();
    float mt = -FLT_MAX;
    #pragma unroll
    for (int wv = 0; wv < 8; wv++) mt = fmaxf(mt, sh[wv]);
    __syncthreads();

    float4 e;
    e.x = __expf(x.x - mt);
    e.y = __expf(x.y - mt);
    e.z = __expf(x.z - mt);
    e.w = __expf(x.w - mt);
    float s = e.x + e.y + e.z + e.w;
    #pragma unroll
    for (int o = 16; o > 0; o >>= 1) s += __shfl_xor_sync(0xffffffffu, s, o);
    if ((tid & 31) == 0) sh[tid >> 5] = s;
    __syncthreads();
    float st = 0.f;
    #pragma unroll
    for (int wv = 0; wv < 8; wv++) st += sh[wv];
    const float inv = 1.0f / st;

    e.x *= inv; e.y *= inv; e.z *= inv; e.w *= inv;
    *(float4*)&row[j0] = e;
}

// ===========================================================================
// HMMA pv: out[i,d] = sum_{j<=i} p[i,j] v[j,d]; writes att bf16 hi/lo directly.
// ===========================================================================
__global__ __launch_bounds__(128)
void pv_tc(const float* __restrict__ p,
           const __nv_bfloat16* __restrict__ vh, const __nv_bfloat16* __restrict__ vl,
           __nv_bfloat16* __restrict__ oh, __nv_bfloat16* __restrict__ ol)
{
    const int ti = blockIdx.x, z = blockIdx.y;
    const int i0 = ti * 64;
    const int h = z >> 2, b = z & 3;
    const int tid = threadIdx.x;
    const int lane = tid & 31, w = tid >> 5;

    __shared__ __align__(128) char sv[2][2][4096];
    __shared__ __align__(128) char sp[4][2][1280];
    const uint32_t svb = smem_u32(&sv[0][0][0]);
    const uint32_t spw = smem_u32(&sp[w][0][0]);

    auto loadV = [&](int kj, int bi) {
        #pragma unroll
        for (int t = 0; t < 4; t++) {
            int cid = tid + t * 128;
            int sel = cid >> 8, rid = (cid >> 3) & 31, c = cid & 7;
            const __nv_bfloat16* g = (sel ? vl : vh)
                + ((size_t)(b * L_ + kj + rid) * D_ + h * 64 + c * 8);
            cpa16(svb + bi * 8192 + sel * 4096 + rid * 128 + ((c ^ (rid & 7)) * 16), g);
        }
        asm volatile("cp.async.commit_group;" ::: "memory");
    };

    float acc[8][4];
    #pragma unroll
    for (int i = 0; i < 8; i++)
        #pragma unroll
        for (int q = 0; q < 4; q++) acc[i][q] = 0.f;

    const int nch = (i0 + 64) >> 5;
    loadV(0, 0);

    for (int c = 0; c < nch; c++) {
        const int bi = c & 1;
        __syncthreads();
        if (c + 1 < nch) loadV((c + 1) * 32, bi ^ 1);

        {
            const int row = lane >> 1, chalf = lane & 1;
            const float* gp = p + ((size_t)z * L_ + i0 + 16 * w + row) * L_
                                + c * 32 + chalf * 16;
            uint32_t* ph = (uint32_t*)(&sp[w][0][0] + row * 80 + chalf * 32);
            uint32_t* pl = (uint32_t*)(&sp[w][1][0] + row * 80 + chalf * 32);
            #pragma unroll
            for (int q = 0; q < 4; q++) {
                float4 v = *(const float4*)(gp + q * 4);
                __nv_bfloat162 h0, h1, l0, l1;
                h0.x = __float2bfloat16(v.x); h0.y = __float2bfloat16(v.y);
                h1.x = __float2bfloat16(v.z); h1.y = __float2bfloat16(v.w);
                l0.x = __float2bfloat16(v.x - __bfloat162float(h0.x));
                l0.y = __float2bfloat16(v.y - __bfloat162float(h0.y));
                l1.x = __float2bfloat16(v.z - __bfloat162float(h1.x));
                l1.y = __float2bfloat16(v.w - __bfloat162float(h1.y));
                ph[q * 2]     = *(uint32_t*)&h0;
                ph[q * 2 + 1] = *(uint32_t*)&h1;
                pl[q * 2]     = *(uint32_t*)&l0;
                pl[q * 2 + 1] = *(uint32_t*)&l1;
            }
        }
        __syncwarp();
        if (c + 1 < nch) asm volatile("cp.async.wait_group 1;" ::: "memory");
        else             asm volatile("cp.async.wait_group 0;" ::: "memory");
        __syncthreads();

        #pragma unroll
        for (int k16 = 0; k16 < 32; k16 += 16) {
            uint32_t Aph[4], Apl[4];
            {
                int arow = lane & 15;
                int ac = (k16 >> 3) + (lane >> 4);
                ldsm_x4(Aph, spw + arow * 80 + ac * 16);
                ldsm_x4(Apl, spw + 1280 + arow * 80 + ac * 16);
            }
            #pragma unroll
            for (int p4 = 0; p4 < 4; p4++) {
                uint32_t Bh[4], Bl[4];
                int krow = k16 + ((lane >> 3) & 1) * 8 + (lane & 7);
                int cc = p4 * 2 + (lane >> 4);
                uint32_t off = krow * 128 + ((cc ^ (krow & 7)) * 16);
                ldsm_x4_t(Bh, svb + bi * 8192 + off);
                ldsm_x4_t(Bl, svb + bi * 8192 + 4096 + off);
                mma16816(acc[2 * p4],     Aph, Bh);
                mma16816(acc[2 * p4 + 1], Aph, Bh + 2);
                mma16816(acc[2 * p4],     Aph, Bl);
                mma16816(acc[2 * p4 + 1], Aph, Bl + 2);
                mma16816(acc[2 * p4],     Apl, Bh);
                mma16816(acc[2 * p4 + 1], Apl, Bh + 2);
            }
        }
    }

    const int r0 = lane >> 2, cb = (lane & 3) * 2;
    #pragma unroll
    for (int nt = 0; nt < 8; nt++) {
        const int d = nt * 8 + cb;
        #pragma unroll
        for (int rr = 0; rr < 2; rr++) {
            const int i = i0 + 16 * w + r0 + rr * 8;
            const size_t idx = (size_t)(b * L_ + i) * D_ + h * 64 + d;
            float a0 = acc[nt][rr * 2], a1 = acc[nt][rr * 2 + 1];
            __nv_bfloat162 hh, ll;
            hh.x = __float2bfloat16(a0);
            hh.y = __float2bfloat16(a1);
            ll.x = __float2bfloat16(a0 - __bfloat162float(hh.x));
            ll.y = __float2bfloat16(a1 - __bfloat162float(hh.y));
            *(__nv_bfloat162*)&oh[idx] = hh;
            *(__nv_bfloat162*)&ol[idx] = ll;
        }
    }
}

// ===========================================================================
// LayerNorm
// ===========================================================================
__global__ __launch_bounds__(256)
void ln_kernel(const float* __restrict__ x, const float* __restrict__ gam,
               const float* __restrict__ bet, float* __restrict__ y)
{
    const int r = blockIdx.x, tid = threadIdx.x;
    __shared__ float sh[16];
    const float* xr = x + (size_t)r * D_;
    float4 xv = *(const float4*)&xr[tid * 4];
    float s  = xv.x + xv.y + xv.z + xv.w;
    float ss = xv.x*xv.x + xv.y*xv.y + xv.z*xv.z + xv.w*xv.w;
    #pragma unroll
    for (int o = 16; o > 0; o >>= 1) {
        s  += __shfl_xor_sync(0xffffffffu, s,  o);
        ss += __shfl_xor_sync(0xffffffffu, ss, o);
    }
    if ((tid & 31) == 0) { sh[tid >> 5] = s; sh[8 + (tid >> 5)] = ss; }
    __syncthreads();
    float st = 0.f, sst = 0.f;
    #pragma unroll
    for (int wv = 0; wv < 8; wv++) { st += sh[wv]; sst += sh[8 + wv]; }
    const float mu  = st * (1.0f / D_);
    const float var = sst * (1.0f / D_) - mu * mu;
    const float rs  = rsqrtf(var + 1e-5f);
    float4 gv = *(const float4*)&gam[tid * 4];
    float4 bv = *(const float4*)&bet[tid * 4];
    float4 o4;
    o4.x = (xv.x - mu) * rs * gv.x + bv.x;
    o4.y = (xv.y - mu) * rs * gv.y + bv.y;
    o4.z = (xv.z - mu) * rs * gv.z + bv.z;
    o4.w = (xv.w - mu) * rs * gv.w + bv.w;
    *(float4*)&y[(size_t)r * D_ + tid * 4] = o4;
}

// ===========================================================================
// Launch
// ===========================================================================
extern "C" void kernel_launch(void* const* d_in, const int* in_sizes, int n_in,
                              void* d_out, int out_size)
{
    const float* q_in = (const float*)d_in[0];
    const float* k_in = (const float*)d_in[1];
    const float* v_in = (const float*)d_in[2];
    const float* Wq   = (const float*)d_in[3];
    const float* Wq2  = (const float*)d_in[4];
    const float* Wk   = (const float*)d_in[5];
    const float* Wv   = (const float*)d_in[6];
    const float* Wo   = (const float*)d_in[7];
    const float* ln_g = (const float*)d_in[8];
    const float* ln_b = (const float*)d_in[9];
    const float* Er   = (const float*)d_in[10];
    (void)in_sizes; (void)n_in;

    float *px, *pfb;
    __nv_bfloat16 *ah, *al, *bh, *bl, *ch, *cl, *wh, *wl;
    __nv_bfloat16 *qh, *ql, *q2h, *q2l, *kh, *kl, *vh, *vl, *eh, *el;
    cudaGetSymbolAddress((void**)&px,  g_x);
    cudaGetSymbolAddress((void**)&pfb, g_pfb);
    cudaGetSymbolAddress((void**)&ah,  g_ah);
    cudaGetSymbolAddress((void**)&al,  g_al);
    cudaGetSymbolAddress((void**)&bh,  g_bh);
    cudaGetSymbolAddress((void**)&bl,  g_bl);
    cudaGetSymbolAddress((void**)&ch,  g_ch);
    cudaGetSymbolAddress((void**)&cl,  g_cl);
    cudaGetSymbolAddress((void**)&wh,  g_wh);
    cudaGetSymbolAddress((void**)&wl,  g_wl);
    cudaGetSymbolAddress((void**)&qh,  g_qh);
    cudaGetSymbolAddress((void**)&ql,  g_ql);
    cudaGetSymbolAddress((void**)&q2h, g_q2h);
    cudaGetSymbolAddress((void**)&q2l, g_q2l);
    cudaGetSymbolAddress((void**)&kh,  g_kh);
    cudaGetSymbolAddress((void**)&kl,  g_kl);
    cudaGetSymbolAddress((void**)&vh,  g_vh);
    cudaGetSymbolAddress((void**)&vl,  g_vl);
    cudaGetSymbolAddress((void**)&eh,  g_eh);
    cudaGetSymbolAddress((void**)&el,  g_el);

    float* y_out = (float*)d_out;
    const long long ysz = (long long)B_ * L_ * D_;
    const long long psz = (long long)HB_ * L_ * L_;
    float* p_buf = ((long long)out_size >= ysz + psz) ? (y_out + ysz) : pfb;

    const int gsmem = 2 * STAGE_BYTES;
    cudaFuncSetAttribute(gemm_tc, cudaFuncAttributeMaxDynamicSharedMemorySize, gsmem);
    cudaFuncSetAttribute(gemm_proj4, cudaFuncAttributeMaxDynamicSharedMemorySize, gsmem);
    cudaFuncSetAttribute(score_tc, cudaFuncAttributeMaxDynamicSharedMemorySize, SC_SMEM);

    const int M = B_ * L_;
    const dim3 ggemm(D_ / 128, M / 128);
    const size_t WSZ = (size_t)D_ * D_;

    // all splits upfront
    split_act_all<<<dim3(4096, 1, 4), 256>>>(q_in, k_in, v_in, Er,
                                             ah, al, bh, bl, ch, cl, eh, el);
    split_w_all<<<dim3(32, 32, 5), 256>>>(Wq, Wq2, Wk, Wv, Wo, wh, wl);

    // 4 projections in ONE batched launch (z selects buffers)
    gemm_proj4<<<dim3(D_ / 128, M / 128, 4), 256, gsmem>>>();

    // attention middle: scores (tri-grid), softmax, pv
    score_tc<<<dim3(136, HB_), 128, SC_SMEM>>>(qh, ql, q2h, q2l, kh, kl, eh, el, p_buf);
    softmax1p<<<dim3(L_, HB_), 256>>>(p_buf);
    pv_tc<<<dim3(16, HB_), 128>>>(p_buf, vh, vl, ah, al);   // att -> ah/al

    // Wo GEMM (fp32 out + residual), then LN
    gemm_tc<<<ggemm, 256, gsmem>>>(ah, al, wh + 4 * WSZ, wl + 4 * WSZ,
                                   px, q_in, nullptr, nullptr, D_, D_);
    ln_kernel<<<B_ * L_, 256>>>(px, ln_g, ln_b, y_out);
}

// round 8
// speedup vs baseline: 1.6055x; 1.0079x over previous
#include <cuda_runtime.h>
#include <cuda_bf16.h>
#include <cfloat>
#include <cstdint>

// Problem constants
#define B_  4
#define L_  1024
#define D_  1024
#define H_  16
#define HB_ 64   // H*B

// ===========================================================================
// Scratch (static __device__)
// ===========================================================================
__device__ float g_x  [B_ * L_ * D_];
__device__ float g_pfb[HB_ * L_ * L_];               // fallback p buffer
__device__ __nv_bfloat16 g_ah[B_ * L_ * D_];         // q_in split hi / att hi
__device__ __nv_bfloat16 g_al[B_ * L_ * D_];         // q_in split lo / att lo
__device__ __nv_bfloat16 g_bh[B_ * L_ * D_];         // k_in split hi
__device__ __nv_bfloat16 g_bl[B_ * L_ * D_];         // k_in split lo
__device__ __nv_bfloat16 g_ch[B_ * L_ * D_];         // v_in split hi
__device__ __nv_bfloat16 g_cl[B_ * L_ * D_];         // v_in split lo
__device__ __nv_bfloat16 g_wh[5 * D_ * D_];          // weights^T split hi [N,K]
__device__ __nv_bfloat16 g_wl[5 * D_ * D_];          // weights^T split lo [N,K]
__device__ __nv_bfloat16 g_qh [B_ * L_ * D_];
__device__ __nv_bfloat16 g_ql [B_ * L_ * D_];
__device__ __nv_bfloat16 g_q2h[B_ * L_ * D_];
__device__ __nv_bfloat16 g_q2l[B_ * L_ * D_];
__device__ __nv_bfloat16 g_kh [B_ * L_ * D_];
__device__ __nv_bfloat16 g_kl [B_ * L_ * D_];
__device__ __nv_bfloat16 g_vh [B_ * L_ * D_];
__device__ __nv_bfloat16 g_vl [B_ * L_ * D_];
__device__ __nv_bfloat16 g_eh [H_ * L_ * 64];
__device__ __nv_bfloat16 g_el [H_ * L_ * 64];

// ===========================================================================
// PTX helpers (base sm_103-legal)
// ===========================================================================
__device__ __forceinline__ uint32_t smem_u32(const void* p) {
    uint32_t a;
    asm("{ .reg .u64 t; cvta.to.shared.u64 t, %1; cvt.u32.u64 %0, t; }"
        : "=r"(a) : "l"(p));
    return a;
}
__device__ __forceinline__ void cpa16(uint32_t saddr, const void* g) {
    asm volatile("cp.async.cg.shared.global [%0], [%1], 16;" :: "r"(saddr), "l"(g));
}
__device__ __forceinline__ void cpa16z(uint32_t saddr, const void* g, int sz) {
    asm volatile("cp.async.cg.shared.global [%0], [%1], 16, %2;"
                 :: "r"(saddr), "l"(g), "r"(sz));
}
__device__ __forceinline__ void ldsm_x4(uint32_t* r, uint32_t addr) {
    asm volatile("ldmatrix.sync.aligned.m8n8.x4.shared.b16 {%0,%1,%2,%3}, [%4];"
                 : "=r"(r[0]), "=r"(r[1]), "=r"(r[2]), "=r"(r[3]) : "r"(addr));
}
__device__ __forceinline__ void ldsm_x4_t(uint32_t* r, uint32_t addr) {
    asm volatile("ldmatrix.sync.aligned.m8n8.x4.trans.shared.b16 {%0,%1,%2,%3}, [%4];"
                 : "=r"(r[0]), "=r"(r[1]), "=r"(r[2]), "=r"(r[3]) : "r"(addr));
}
__device__ __forceinline__ void mma16816(float* c, const uint32_t* a, const uint32_t* b) {
    asm volatile(
        "mma.sync.aligned.m16n8k16.row.col.f32.bf16.bf16.f32 "
        "{%0,%1,%2,%3}, {%4,%5,%6,%7}, {%8,%9}, {%0,%1,%2,%3};"
        : "+f"(c[0]), "+f"(c[1]), "+f"(c[2]), "+f"(c[3])
        : "r"(a[0]), "r"(a[1]), "r"(a[2]), "r"(a[3]), "r"(b[0]), "r"(b[1]));
}

// ===========================================================================
// fp32 -> bf16 hi/lo splits: all activations + Er in one launch (grid.z=4)
// ===========================================================================
__global__ __launch_bounds__(256)
void split_act_all(const float* __restrict__ x0, const float* __restrict__ x1,
                   const float* __restrict__ x2, const float* __restrict__ x3,
                   __nv_bfloat16* __restrict__ h0, __nv_bfloat16* __restrict__ l0,
                   __nv_bfloat16* __restrict__ h1, __nv_bfloat16* __restrict__ l1,
                   __nv_bfloat16* __restrict__ h2, __nv_bfloat16* __restrict__ l2,
                   __nv_bfloat16* __restrict__ h3, __nv_bfloat16* __restrict__ l3)
{
    const int zz = blockIdx.z;
    const float* x; __nv_bfloat16 *hi, *lo; int n;
    if      (zz == 0) { x = x0; hi = h0; lo = l0; n = B_ * L_ * D_; }
    else if (zz == 1) { x = x1; hi = h1; lo = l1; n = B_ * L_ * D_; }
    else if (zz == 2) { x = x2; hi = h2; lo = l2; n = B_ * L_ * D_; }
    else              { x = x3; hi = h3; lo = l3; n = H_ * L_ * 64; }
    int i = (blockIdx.x * 256 + threadIdx.x) * 4;
    if (i >= n) return;
    float4 v = *(const float4*)&x[i];
    __nv_bfloat16 a0 = __float2bfloat16(v.x);
    __nv_bfloat16 a1 = __float2bfloat16(v.y);
    __nv_bfloat16 a2 = __float2bfloat16(v.z);
    __nv_bfloat16 a3 = __float2bfloat16(v.w);
    __nv_bfloat162 hp0; hp0.x = a0; hp0.y = a1;
    __nv_bfloat162 hp1; hp1.x = a2; hp1.y = a3;
    *(__nv_bfloat162*)&hi[i]     = hp0;
    *(__nv_bfloat162*)&hi[i + 2] = hp1;
    __nv_bfloat162 lp0, lp1;
    lp0.x = __float2bfloat16(v.x - __bfloat162float(a0));
    lp0.y = __float2bfloat16(v.y - __bfloat162float(a1));
    lp1.x = __float2bfloat16(v.z - __bfloat162float(a2));
    lp1.y = __float2bfloat16(v.w - __bfloat162float(a3));
    *(__nv_bfloat162*)&lo[i]     = lp0;
    *(__nv_bfloat162*)&lo[i + 2] = lp1;
}

// All 5 weights: W[K,N] fp32 -> Wt[N,K] bf16 hi/lo (transpose + split), grid.z=5
__global__ __launch_bounds__(256)
void split_w_all(const float* __restrict__ W0, const float* __restrict__ W1,
                 const float* __restrict__ W2, const float* __restrict__ W3,
                 const float* __restrict__ W4,
                 __nv_bfloat16* __restrict__ th, __nv_bfloat16* __restrict__ tl)
{
    const float* W;
    switch (blockIdx.z) {
        case 0: W = W0; break;
        case 1: W = W1; break;
        case 2: W = W2; break;
        case 3: W = W3; break;
        default: W = W4; break;
    }
    __nv_bfloat16* h = th + (size_t)blockIdx.z * D_ * D_;
    __nv_bfloat16* l = tl + (size_t)blockIdx.z * D_ * D_;
    __shared__ float t[32][33];
    const int bx = blockIdx.x * 32;
    const int by = blockIdx.y * 32;
    const int tx = threadIdx.x & 31;
    const int ty = threadIdx.x >> 5;
    #pragma unroll
    for (int r = ty; r < 32; r += 8)
        t[r][tx] = W[(size_t)(by + r) * D_ + bx + tx];
    __syncthreads();
    #pragma unroll
    for (int r = ty; r < 32; r += 8) {
        float v = t[tx][r];
        __nv_bfloat16 hh = __float2bfloat16(v);
        h[(size_t)(bx + r) * D_ + by + tx] = hh;
        l[(size_t)(bx + r) * D_ + by + tx] = __float2bfloat16(v - __bfloat162float(hh));
    }
}

// ===========================================================================
// HMMA split-bf16 GEMM body
// ===========================================================================
#define TSTRIDE 40
#define TILE_BYTES (128 * TSTRIDE * 2)
#define STAGE_BYTES (4 * TILE_BYTES)

__device__ __forceinline__ void gemm_body(
    const __nv_bfloat16* __restrict__ Ah, const __nv_bfloat16* __restrict__ Al,
    const __nv_bfloat16* __restrict__ Bh, const __nv_bfloat16* __restrict__ Bl,
    float* __restrict__ C, const float* __restrict__ R,
    __nv_bfloat16* __restrict__ Oh, __nv_bfloat16* __restrict__ Ol,
    int K, int N, char* smem)
{
    const uint32_t sb0 = smem_u32(smem);
    const int tid  = threadIdx.x;
    const int wid  = tid >> 5;
    const int lane = tid & 31;
    const int m0 = blockIdx.y * 128;
    const int n0 = blockIdx.x * 128;
    const int wm = (wid & 3) * 32;
    const int wn = (wid >> 2) * 64;

    const __nv_bfloat16* gT[4] = {
        Ah + (size_t)m0 * K, Al + (size_t)m0 * K,
        Bh + (size_t)n0 * K, Bl + (size_t)n0 * K };

    auto load_chunk = [&](int c, int st) {
        const uint32_t sb = sb0 + st * STAGE_BYTES;
        const int k0 = c * 32;
        #pragma unroll
        for (int t = 0; t < 4; t++) {
            const __nv_bfloat16* g = gT[t] + k0;
            const uint32_t tb = sb + t * TILE_BYTES;
            #pragma unroll
            for (int it = 0; it < 2; it++) {
                int o   = tid + it * 256;
                int row = o >> 2, c16 = o & 3;
                cpa16(tb + row * (TSTRIDE * 2) + c16 * 16,
                      g + (size_t)row * K + c16 * 8);
            }
        }
        asm volatile("cp.async.commit_group;" ::: "memory");
    };

    float acc[2][8][4];
    #pragma unroll
    for (int i = 0; i < 2; i++)
        #pragma unroll
        for (int j = 0; j < 8; j++)
            #pragma unroll
            for (int q = 0; q < 4; q++) acc[i][j][q] = 0.f;

    const int arow = lane & 15;
    const int acolq = (lane >> 4) * 8;
    const int nrow = ((lane >> 4) * 8) + (lane & 7);
    const int bcolq = ((lane >> 3) & 1) * 8;

    const int NC = K / 32;
    load_chunk(0, 0);

    for (int c = 0; c < NC; ++c) {
        const int st = c & 1;
        if (c + 1 < NC) {
            load_chunk(c + 1, st ^ 1);
            asm volatile("cp.async.wait_group 1;" ::: "memory");
        } else {
            asm volatile("cp.async.wait_group 0;" ::: "memory");
        }
        __syncthreads();

        const uint32_t sb  = sb0 + st * STAGE_BYTES;
        const uint32_t sAh = sb;
        const uint32_t sAl = sb + TILE_BYTES;
        const uint32_t sBh = sb + 2 * TILE_BYTES;
        const uint32_t sBl = sb + 3 * TILE_BYTES;

        #pragma unroll
        for (int k16 = 0; k16 < 32; k16 += 16) {
            uint32_t ah[2][4], al[2][4], bh[4][4], bl[4][4];
            #pragma unroll
            for (int mt = 0; mt < 2; mt++) {
                uint32_t off = ((wm + mt * 16 + arow) * TSTRIDE + k16 + acolq) * 2;
                ldsm_x4(ah[mt], sAh + off);
                ldsm_x4(al[mt], sAl + off);
            }
            #pragma unroll
            for (int p = 0; p < 4; p++) {
                uint32_t off = ((wn + p * 16 + nrow) * TSTRIDE + k16 + bcolq) * 2;
                ldsm_x4(bh[p], sBh + off);
                ldsm_x4(bl[p], sBl + off);
            }
            #pragma unroll
            for (int mt = 0; mt < 2; mt++)
                #pragma unroll
                for (int nt = 0; nt < 8; nt++) {
                    const uint32_t* bhf = &bh[nt >> 1][(nt & 1) * 2];
                    const uint32_t* blf = &bl[nt >> 1][(nt & 1) * 2];
                    mma16816(acc[mt][nt], ah[mt], bhf);
                    mma16816(acc[mt][nt], ah[mt], blf);
                    mma16816(acc[mt][nt], al[mt], bhf);
                }
        }
        __syncthreads();
    }

    #pragma unroll
    for (int mt = 0; mt < 2; mt++) {
        const int m = m0 + wm + mt * 16 + (lane >> 2);
        #pragma unroll
        for (int nt = 0; nt < 8; nt++) {
            const int n = n0 + wn + nt * 8 + (lane & 3) * 2;
            if (Oh) {
                #pragma unroll
                for (int rr = 0; rr < 2; rr++) {
                    const size_t idx = (size_t)(m + rr * 8) * N + n;
                    float a0 = acc[mt][nt][rr * 2], a1 = acc[mt][nt][rr * 2 + 1];
                    __nv_bfloat162 hh, ll;
                    hh.x = __float2bfloat16(a0);
                    hh.y = __float2bfloat16(a1);
                    ll.x = __float2bfloat16(a0 - __bfloat162float(hh.x));
                    ll.y = __float2bfloat16(a1 - __bfloat162float(hh.y));
                    *(__nv_bfloat162*)&Oh[idx] = hh;
                    *(__nv_bfloat162*)&Ol[idx] = ll;
                }
            } else {
                float2 o0 = make_float2(acc[mt][nt][0], acc[mt][nt][1]);
                float2 o1 = make_float2(acc[mt][nt][2], acc[mt][nt][3]);
                if (R) {
                    const float2 r0 = *(const float2*)&R[(size_t)m * N + n];
                    const float2 r1 = *(const float2*)&R[(size_t)(m + 8) * N + n];
                    o0.x += r0.x; o0.y += r0.y;
                    o1.x += r1.x; o1.y += r1.y;
                }
                *(float2*)&C[(size_t)m * N + n] = o0;
                *(float2*)&C[(size_t)(m + 8) * N + n] = o1;
            }
        }
    }
}

// Generic GEMM entry (used for Wo)
__global__ __launch_bounds__(256, 2)
void gemm_tc(const __nv_bfloat16* __restrict__ Ah, const __nv_bfloat16* __restrict__ Al,
             const __nv_bfloat16* __restrict__ Bh, const __nv_bfloat16* __restrict__ Bl,
             float* __restrict__ C, const float* __restrict__ R,
             __nv_bfloat16* __restrict__ Oh, __nv_bfloat16* __restrict__ Ol,
             int K, int N)
{
    extern __shared__ __align__(16) char smem[];
    gemm_body(Ah, Al, Bh, Bl, C, R, Oh, Ol, K, N, smem);
}

// Batched projection GEMMs: z selects (A, W, O) from static buffers.
__global__ __launch_bounds__(256, 2)
void gemm_proj4()
{
    extern __shared__ __align__(16) char smem[];
    const size_t WSZ = (size_t)D_ * D_;
    const __nv_bfloat16 *Ah, *Al;
    __nv_bfloat16 *Oh, *Ol;
    const int z = blockIdx.z;
    switch (z) {
        case 0:  Ah = g_ah; Al = g_al; Oh = g_qh;  Ol = g_ql;  break;
        case 1:  Ah = g_ah; Al = g_al; Oh = g_q2h; Ol = g_q2l; break;
        case 2:  Ah = g_bh; Al = g_bl; Oh = g_kh;  Ol = g_kl;  break;
        default: Ah = g_ch; Al = g_cl; Oh = g_vh;  Ol = g_vl;  break;
    }
    gemm_body(Ah, Al, g_wh + z * WSZ, g_wl + z * WSZ,
              nullptr, nullptr, Oh, Ol, D_, D_, smem);
}

// ===========================================================================
// HMMA score kernel v2: 256 threads, 8 warps in 4(i) x 2(j) quadrants.
// Each warp: 16 i-rows x 32 j-cols, 48-wide rel band.
// S[i,j] = (q_i.k_j + q2_i.Er[L-1-(i-j)]) / 8, lower-triangle tiles only.
// ===========================================================================
#define SC_SQH 0
#define SC_SQL 8192
#define SC_S2H 16384
#define SC_S2L 24576
#define SC_SKH 32768
#define SC_SKL 40960
#define SC_SEH 49152
#define SC_SEL 65536
#define SC_SR  81920
#define SC_RSW 3584                    // per-warp gather bytes (16 x 56 fp32)
#define SC_SMEM (81920 + 8 * SC_RSW)   // 110592

__global__ __launch_bounds__(256)
void score_tc(const __nv_bfloat16* __restrict__ qh, const __nv_bfloat16* __restrict__ ql,
              const __nv_bfloat16* __restrict__ q2h, const __nv_bfloat16* __restrict__ q2l,
              const __nv_bfloat16* __restrict__ kh, const __nv_bfloat16* __restrict__ kl,
              const __nv_bfloat16* __restrict__ eh, const __nv_bfloat16* __restrict__ el,
              float* __restrict__ p)
{
    const int x = blockIdx.x;
    int ti = (int)((__fsqrt_rn(8.0f * x + 1.0f) - 1.0f) * 0.5f);
    if (ti * (ti + 1) / 2 > x) ti--;
    else if ((ti + 1) * (ti + 2) / 2 <= x) ti++;
    const int tj = x - ti * (ti + 1) / 2;
    const int z = blockIdx.y;
    const int i0 = ti * 64, j0 = tj * 64;
    const int h = z >> 2, b = z & 3;
    const int rbase = L_ - 64 - i0 + j0;

    extern __shared__ __align__(16) char smem[];
    const uint32_t sb = smem_u32(smem);
    const int tid = threadIdx.x;
    const int lane = tid & 31, w = tid >> 5;
    const int iw = w & 3, jw = w >> 2;   // 4 i-groups x 2 j-groups

    // ---- loads: 256 threads ----
    auto load64 = [&](uint32_t st, const __nv_bfloat16* g) {
        #pragma unroll
        for (int t = 0; t < 2; t++) {
            int cid = tid + t * 256;          // 0..511
            int row = cid >> 3, c = cid & 7;
            cpa16(sb + st + row * 128 + ((c ^ (row & 7)) * 16),
                  g + (size_t)row * D_ + c * 8);
        }
    };
    const size_t qoff = (size_t)(b * L_ + i0) * D_ + h * 64;
    const size_t koff = (size_t)(b * L_ + j0) * D_ + h * 64;
    load64(SC_SQH, qh  + qoff);
    load64(SC_SQL, ql  + qoff);
    load64(SC_S2H, q2h + qoff);
    load64(SC_S2L, q2l + qoff);
    load64(SC_SKH, kh  + koff);
    load64(SC_SKL, kl  + koff);
    {
        const __nv_bfloat16* ehp = eh + (size_t)h * L_ * 64;
        const __nv_bfloat16* elp = el + (size_t)h * L_ * 64;
        #pragma unroll
        for (int t = 0; t < 4; t++) {
            int cid = tid + t * 256;          // 0..1023
            int row = cid >> 3, c = cid & 7;
            int r = rbase + row;
            int sz = (r < L_) ? 16 : 0;
            int rc = (r < L_) ? r : 0;
            uint32_t so = row * 128 + ((c ^ (row & 7)) * 16);
            cpa16z(sb + SC_SEH + so, ehp + (size_t)rc * 64 + c * 8, sz);
            cpa16z(sb + SC_SEL + so, elp + (size_t)rc * 64 + c * 8, sz);
        }
    }
    asm volatile("cp.async.commit_group;" ::: "memory");
    asm volatile("cp.async.wait_group 0;" ::: "memory");
    __syncthreads();

    float aqk[4][4], arl[6][4];
    #pragma unroll
    for (int i = 0; i < 4; i++)
        #pragma unroll
        for (int q = 0; q < 4; q++) aqk[i][q] = 0.f;
    #pragma unroll
    for (int i = 0; i < 6; i++)
        #pragma unroll
        for (int q = 0; q < 4; q++) arl[i][q] = 0.f;

    const int t0w = 48 + 32 * jw - 16 * iw;   // rel band base for this warp

    auto ldA = [&](uint32_t st, int k16, uint32_t* r) {
        int row = 16 * iw + (lane & 15);
        int c = (k16 >> 3) + (lane >> 4);
        ldsm_x4(r, sb + st + row * 128 + ((c ^ (row & 7)) * 16));
    };
    auto ldB = [&](uint32_t st, int nrow0, int k16, uint32_t* r) {
        int row = nrow0 + (lane >> 4) * 8 + (lane & 7);
        int c = (k16 >> 3) + ((lane >> 3) & 1);
        ldsm_x4(r, sb + st + row * 128 + ((c ^ (row & 7)) * 16));
    };

    #pragma unroll
    for (int k16 = 0; k16 < 64; k16 += 16) {
        uint32_t Aqh[4], Aql[4], A2h[4], A2l[4];
        ldA(SC_SQH, k16, Aqh);
        ldA(SC_SQL, k16, Aql);
        ldA(SC_S2H, k16, A2h);
        ldA(SC_S2L, k16, A2l);
        #pragma unroll
        for (int pg = 0; pg < 2; pg++) {
            uint32_t Bh[4], Bl[4];
            ldB(SC_SKH, 32 * jw + pg * 16, k16, Bh);
            ldB(SC_SKL, 32 * jw + pg * 16, k16, Bl);
            mma16816(aqk[2 * pg],     Aqh, Bh);
            mma16816(aqk[2 * pg + 1], Aqh, Bh + 2);
            mma16816(aqk[2 * pg],     Aqh, Bl);
            mma16816(aqk[2 * pg + 1], Aqh, Bl + 2);
            mma16816(aqk[2 * pg],     Aql, Bh);
            mma16816(aqk[2 * pg + 1], Aql, Bh + 2);
        }
        #pragma unroll
        for (int pg = 0; pg < 3; pg++) {
            uint32_t Bh[4], Bl[4];
            ldB(SC_SEH, t0w + pg * 16, k16, Bh);
            ldB(SC_SEL, t0w + pg * 16, k16, Bl);
            mma16816(arl[2 * pg],     A2h, Bh);
            mma16816(arl[2 * pg + 1], A2h, Bh + 2);
            mma16816(arl[2 * pg],     A2h, Bl);
            mma16816(arl[2 * pg + 1], A2h, Bl + 2);
            mma16816(arl[2 * pg],     A2l, Bh);
            mma16816(arl[2 * pg + 1], A2l, Bh + 2);
        }
    }

    // ---- per-warp skew gather (band is 48 wide; stride 56 fp32) ----
    float* Rs = (float*)(smem + SC_SR + w * SC_RSW);   // 16 x 56 fp32
    const int r0 = lane >> 2, cb = (lane & 3) * 2;
    #pragma unroll
    for (int nt = 0; nt < 6; nt++) {
        int tb = nt * 8 + cb;
        Rs[r0 * 56 + tb]           = arl[nt][0];
        Rs[r0 * 56 + tb + 1]       = arl[nt][1];
        Rs[(r0 + 8) * 56 + tb]     = arl[nt][2];
        Rs[(r0 + 8) * 56 + tb + 1] = arl[nt][3];
    }
    __syncwarp();

    #pragma unroll
    for (int nt = 0; nt < 4; nt++) {
        int jc = nt * 8 + cb;
        float2 o0, o1;
        o0.x = (aqk[nt][0] + Rs[r0 * 56 + 15 + jc - r0]) * 0.125f;
        o0.y = (aqk[nt][1] + Rs[r0 * 56 + 16 + jc - r0]) * 0.125f;
        o1.x = (aqk[nt][2] + Rs[(r0 + 8) * 56 + 7 + jc - r0]) * 0.125f;
        o1.y = (aqk[nt][3] + Rs[(r0 + 8) * 56 + 8 + jc - r0]) * 0.125f;
        size_t base = ((size_t)z * L_ + i0 + 16 * iw + r0) * L_ + j0 + 32 * jw + jc;
        *(float2*)&p[base]          = o0;
        *(float2*)&p[base + 8 * L_] = o1;
    }
}

// ===========================================================================
// Single-pass row softmax; loads ONLY j <= i (predicated), writes full row.
// ===========================================================================
__global__ __launch_bounds__(256)
void softmax1p(float* __restrict__ p)
{
    const int i = blockIdx.x, z = blockIdx.y, tid = threadIdx.x;
    float* row = p + ((size_t)z * L_ + i) * L_;
    __shared__ float sh[8];

    const int j0 = tid * 4;
    float4 x;
    if (j0 <= i) {
        x = *(const float4*)&row[j0];
        if (j0 + 1 > i) x.y = -FLT_MAX;
        if (j0 + 2 > i) x.z = -FLT_MAX;
        if (j0 + 3 > i) x.w = -FLT_MAX;
    } else {
        x = make_float4(-FLT_MAX, -FLT_MAX, -FLT_MAX, -FLT_MAX);
    }

    float m = fmaxf(fmaxf(x.x, x.y), fmaxf(x.z, x.w));
    #pragma unroll
    for (int o = 16; o > 0; o >>= 1) m = fmaxf(m, __shfl_xor_sync(0xffffffffu, m, o));
    if ((tid & 31) == 0) sh[tid >> 5] = m;
    __syncthreads();
    float mt = -FLT_MAX;
    #pragma unroll
    for (int wv = 0; wv < 8; wv++) mt = fmaxf(mt, sh[wv]);
    __syncthreads();

    float4 e;
    e.x = __expf(x.x - mt);
    e.y = __expf(x.y - mt);
    e.z = __expf(x.z - mt);
    e.w = __expf(x.w - mt);
    float s = e.x + e.y + e.z + e.w;
    #pragma unroll
    for (int o = 16; o > 0; o >>= 1) s += __shfl_xor_sync(0xffffffffu, s, o);
    if ((tid & 31) == 0) sh[tid >> 5] = s;
    __syncthreads();
    float st = 0.f;
    #pragma unroll
    for (int wv = 0; wv < 8; wv++) st += sh[wv];
    const float inv = 1.0f / st;

    e.x *= inv; e.y *= inv; e.z *= inv; e.w *= inv;
    *(float4*)&row[j0] = e;
}

// ===========================================================================
// HMMA pv: out[i,d] = sum_{j<=i} p[i,j] v[j,d]; writes att bf16 hi/lo directly.
// ===========================================================================
__global__ __launch_bounds__(128)
void pv_tc(const float* __restrict__ p,
           const __nv_bfloat16* __restrict__ vh, const __nv_bfloat16* __restrict__ vl,
           __nv_bfloat16* __restrict__ oh, __nv_bfloat16* __restrict__ ol)
{
    const int ti = blockIdx.x, z = blockIdx.y;
    const int i0 = ti * 64;
    const int h = z >> 2, b = z & 3;
    const int tid = threadIdx.x;
    const int lane = tid & 31, w = tid >> 5;

    __shared__ __align__(128) char sv[2][2][4096];
    __shared__ __align__(128) char sp[4][2][1280];
    const uint32_t svb = smem_u32(&sv[0][0][0]);
    const uint32_t spw = smem_u32(&sp[w][0][0]);

    auto loadV = [&](int kj, int bi) {
        #pragma unroll
        for (int t = 0; t < 4; t++) {
            int cid = tid + t * 128;
            int sel = cid >> 8, rid = (cid >> 3) & 31, c = cid & 7;
            const __nv_bfloat16* g = (sel ? vl : vh)
                + ((size_t)(b * L_ + kj + rid) * D_ + h * 64 + c * 8);
            cpa16(svb + bi * 8192 + sel * 4096 + rid * 128 + ((c ^ (rid & 7)) * 16), g);
        }
        asm volatile("cp.async.commit_group;" ::: "memory");
    };

    float acc[8][4];
    #pragma unroll
    for (int i = 0; i < 8; i++)
        #pragma unroll
        for (int q = 0; q < 4; q++) acc[i][q] = 0.f;

    const int nch = (i0 + 64) >> 5;
    loadV(0, 0);

    for (int c = 0; c < nch; c++) {
        const int bi = c & 1;
        __syncthreads();
        if (c + 1 < nch) loadV((c + 1) * 32, bi ^ 1);

        {
            const int row = lane >> 1, chalf = lane & 1;
            const float* gp = p + ((size_t)z * L_ + i0 + 16 * w + row) * L_
                                + c * 32 + chalf * 16;
            uint32_t* ph = (uint32_t*)(&sp[w][0][0] + row * 80 + chalf * 32);
            uint32_t* pl = (uint32_t*)(&sp[w][1][0] + row * 80 + chalf * 32);
            #pragma unroll
            for (int q = 0; q < 4; q++) {
                float4 v = *(const float4*)(gp + q * 4);
                __nv_bfloat162 h0, h1, l0, l1;
                h0.x = __float2bfloat16(v.x); h0.y = __float2bfloat16(v.y);
                h1.x = __float2bfloat16(v.z); h1.y = __float2bfloat16(v.w);
                l0.x = __float2bfloat16(v.x - __bfloat162float(h0.x));
                l0.y = __float2bfloat16(v.y - __bfloat162float(h0.y));
                l1.x = __float2bfloat16(v.z - __bfloat162float(h1.x));
                l1.y = __float2bfloat16(v.w - __bfloat162float(h1.y));
                ph[q * 2]     = *(uint32_t*)&h0;
                ph[q * 2 + 1] = *(uint32_t*)&h1;
                pl[q * 2]     = *(uint32_t*)&l0;
                pl[q * 2 + 1] = *(uint32_t*)&l1;
            }
        }
        __syncwarp();
        if (c + 1 < nch) asm volatile("cp.async.wait_group 1;" ::: "memory");
        else             asm volatile("cp.async.wait_group 0;" ::: "memory");
        __syncthreads();

        #pragma unroll
        for (int k16 = 0; k16 < 32; k16 += 16) {
            uint32_t Aph[4], Apl[4];
            {
                int arow = lane & 15;
                int ac = (k16 >> 3) + (lane >> 4);
                ldsm_x4(Aph, spw + arow * 80 + ac * 16);
                ldsm_x4(Apl, spw + 1280 + arow * 80 + ac * 16);
            }
            #pragma unroll
            for (int p4 = 0; p4 < 4; p4++) {
                uint32_t Bh[4], Bl[4];
                int krow = k16 + ((lane >> 3) & 1) * 8 + (lane & 7);
                int cc = p4 * 2 + (lane >> 4);
                uint32_t off = krow * 128 + ((cc ^ (krow & 7)) * 16);
                ldsm_x4_t(Bh, svb + bi * 8192 + off);
                ldsm_x4_t(Bl, svb + bi * 8192 + 4096 + off);
                mma16816(acc[2 * p4],     Aph, Bh);
                mma16816(acc[2 * p4 + 1], Aph, Bh + 2);
                mma16816(acc[2 * p4],     Aph, Bl);
                mma16816(acc[2 * p4 + 1], Aph, Bl + 2);
                mma16816(acc[2 * p4],     Apl, Bh);
                mma16816(acc[2 * p4 + 1], Apl, Bh + 2);
            }
        }
    }

    const int r0 = lane >> 2, cb = (lane & 3) * 2;
    #pragma unroll
    for (int nt = 0; nt < 8; nt++) {
        const int d = nt * 8 + cb;
        #pragma unroll
        for (int rr = 0; rr < 2; rr++) {
            const int i = i0 + 16 * w + r0 + rr * 8;
            const size_t idx = (size_t)(b * L_ + i) * D_ + h * 64 + d;
            float a0 = acc[nt][rr * 2], a1 = acc[nt][rr * 2 + 1];
            __nv_bfloat162 hh, ll;
            hh.x = __float2bfloat16(a0);
            hh.y = __float2bfloat16(a1);
            ll.x = __float2bfloat16(a0 - __bfloat162float(hh.x));
            ll.y = __float2bfloat16(a1 - __bfloat162float(hh.y));
            *(__nv_bfloat162*)&oh[idx] = hh;
            *(__nv_bfloat162*)&ol[idx] = ll;
        }
    }
}

// ===========================================================================
// LayerNorm
// ===========================================================================
__global__ __launch_bounds__(256)
void ln_kernel(const float* __restrict__ x, const float* __restrict__ gam,
               const float* __restrict__ bet, float* __restrict__ y)
{
    const int r = blockIdx.x, tid = threadIdx.x;
    __shared__ float sh[16];
    const float* xr = x + (size_t)r * D_;
    float4 xv = *(const float4*)&xr[tid * 4];
    float s  = xv.x + xv.y + xv.z + xv.w;
    float ss = xv.x*xv.x + xv.y*xv.y + xv.z*xv.z + xv.w*xv.w;
    #pragma unroll
    for (int o = 16; o > 0; o >>= 1) {
        s  += __shfl_xor_sync(0xffffffffu, s,  o);
        ss += __shfl_xor_sync(0xffffffffu, ss, o);
    }
    if ((tid & 31) == 0) { sh[tid >> 5] = s; sh[8 + (tid >> 5)] = ss; }
    __syncthreads();
    float st = 0.f, sst = 0.f;
    #pragma unroll
    for (int wv = 0; wv < 8; wv++) { st += sh[wv]; sst += sh[8 + wv]; }
    const float mu  = st * (1.0f / D_);
    const float var = sst * (1.0f / D_) - mu * mu;
    const float rs  = rsqrtf(var + 1e-5f);
    float4 gv = *(const float4*)&gam[tid * 4];
    float4 bv = *(const float4*)&bet[tid * 4];
    float4 o4;
    o4.x = (xv.x - mu) * rs * gv.x + bv.x;
    o4.y = (xv.y - mu) * rs * gv.y + bv.y;
    o4.z = (xv.z - mu) * rs * gv.z + bv.z;
    o4.w = (xv.w - mu) * rs * gv.w + bv.w;
    *(float4*)&y[(size_t)r * D_ + tid * 4] = o4;
}

// ===========================================================================
// Launch
// ===========================================================================
extern "C" void kernel_launch(void* const* d_in, const int* in_sizes, int n_in,
                              void* d_out, int out_size)
{
    const float* q_in = (const float*)d_in[0];
    const float* k_in = (const float*)d_in[1];
    const float* v_in = (const float*)d_in[2];
    const float* Wq   = (const float*)d_in[3];
    const float* Wq2  = (const float*)d_in[4];
    const float* Wk   = (const float*)d_in[5];
    const float* Wv   = (const float*)d_in[6];
    const float* Wo   = (const float*)d_in[7];
    const float* ln_g = (const float*)d_in[8];
    const float* ln_b = (const float*)d_in[9];
    const float* Er   = (const float*)d_in[10];
    (void)in_sizes; (void)n_in;

    float *px, *pfb;
    __nv_bfloat16 *ah, *al, *bh, *bl, *ch, *cl, *wh, *wl;
    __nv_bfloat16 *qh, *ql, *q2h, *q2l, *kh, *kl, *vh, *vl, *eh, *el;
    cudaGetSymbolAddress((void**)&px,  g_x);
    cudaGetSymbolAddress((void**)&pfb, g_pfb);
    cudaGetSymbolAddress((void**)&ah,  g_ah);
    cudaGetSymbolAddress((void**)&al,  g_al);
    cudaGetSymbolAddress((void**)&bh,  g_bh);
    cudaGetSymbolAddress((void**)&bl,  g_bl);
    cudaGetSymbolAddress((void**)&ch,  g_ch);
    cudaGetSymbolAddress((void**)&cl,  g_cl);
    cudaGetSymbolAddress((void**)&wh,  g_wh);
    cudaGetSymbolAddress((void**)&wl,  g_wl);
    cudaGetSymbolAddress((void**)&qh,  g_qh);
    cudaGetSymbolAddress((void**)&ql,  g_ql);
    cudaGetSymbolAddress((void**)&q2h, g_q2h);
    cudaGetSymbolAddress((void**)&q2l, g_q2l);
    cudaGetSymbolAddress((void**)&kh,  g_kh);
    cudaGetSymbolAddress((void**)&kl,  g_kl);
    cudaGetSymbolAddress((void**)&vh,  g_vh);
    cudaGetSymbolAddress((void**)&vl,  g_vl);
    cudaGetSymbolAddress((void**)&eh,  g_eh);
    cudaGetSymbolAddress((void**)&el,  g_el);

    float* y_out = (float*)d_out;
    const long long ysz = (long long)B_ * L_ * D_;
    const long long psz = (long long)HB_ * L_ * L_;
    float* p_buf = ((long long)out_size >= ysz + psz) ? (y_out + ysz) : pfb;

    const int gsmem = 2 * STAGE_BYTES;
    cudaFuncSetAttribute(gemm_tc, cudaFuncAttributeMaxDynamicSharedMemorySize, gsmem);
    cudaFuncSetAttribute(gemm_proj4, cudaFuncAttributeMaxDynamicSharedMemorySize, gsmem);
    cudaFuncSetAttribute(score_tc, cudaFuncAttributeMaxDynamicSharedMemorySize, SC_SMEM);

    const int M = B_ * L_;
    const dim3 ggemm(D_ / 128, M / 128);
    const size_t WSZ = (size_t)D_ * D_;

    // all splits upfront
    split_act_all<<<dim3(4096, 1, 4), 256>>>(q_in, k_in, v_in, Er,
                                             ah, al, bh, bl, ch, cl, eh, el);
    split_w_all<<<dim3(32, 32, 5), 256>>>(Wq, Wq2, Wk, Wv, Wo, wh, wl);

    // 4 projections in ONE batched launch (z selects buffers)
    gemm_proj4<<<dim3(D_ / 128, M / 128, 4), 256, gsmem>>>();

    // attention middle: scores (tri-grid, 256-thread quadrant layout), softmax, pv
    score_tc<<<dim3(136, HB_), 256, SC_SMEM>>>(qh, ql, q2h, q2l, kh, kl, eh, el, p_buf);
    softmax1p<<<dim3(L_, HB_), 256>>>(p_buf);
    pv_tc<<<dim3(16, HB_), 128>>>(p_buf, vh, vl, ah, al);   // att -> ah/al

    // Wo GEMM (fp32 out + residual), then LN
    gemm_tc<<<ggemm, 256, gsmem>>>(ah, al, wh + 4 * WSZ, wl + 4 * WSZ,
                                   px, q_in, nullptr, nullptr, D_, D_);
    ln_kernel<<<B_ * L_, 256>>>(px, ln_g, ln_b, y_out);
}

// round 9
// speedup vs baseline: 1.6250x; 1.0122x over previous
#include <cuda_runtime.h>
#include <cuda_bf16.h>
#include <cfloat>
#include <cstdint>

// Problem constants
#define B_  4
#define L_  1024
#define D_  1024
#define H_  16
#define HB_ 64   // H*B

// ===========================================================================
// Scratch (static __device__)
// ===========================================================================
__device__ float g_x  [B_ * L_ * D_];
__device__ float g_pfb[HB_ * L_ * L_];               // fallback p buffer
__device__ __nv_bfloat16 g_ah[B_ * L_ * D_];         // q_in split hi / att hi
__device__ __nv_bfloat16 g_al[B_ * L_ * D_];         // q_in split lo / att lo
__device__ __nv_bfloat16 g_bh[B_ * L_ * D_];         // k_in split hi
__device__ __nv_bfloat16 g_bl[B_ * L_ * D_];         // k_in split lo
__device__ __nv_bfloat16 g_ch[B_ * L_ * D_];         // v_in split hi
__device__ __nv_bfloat16 g_cl[B_ * L_ * D_];         // v_in split lo
__device__ __nv_bfloat16 g_wh[5 * D_ * D_];          // weights^T split hi [N,K]
__device__ __nv_bfloat16 g_wl[5 * D_ * D_];          // weights^T split lo [N,K]
__device__ __nv_bfloat16 g_qh [B_ * L_ * D_];
__device__ __nv_bfloat16 g_ql [B_ * L_ * D_];
__device__ __nv_bfloat16 g_q2h[B_ * L_ * D_];
__device__ __nv_bfloat16 g_q2l[B_ * L_ * D_];
__device__ __nv_bfloat16 g_kh [B_ * L_ * D_];
__device__ __nv_bfloat16 g_kl [B_ * L_ * D_];
__device__ __nv_bfloat16 g_vh [B_ * L_ * D_];
__device__ __nv_bfloat16 g_vl [B_ * L_ * D_];
__device__ __nv_bfloat16 g_eh [H_ * L_ * 64];
__device__ __nv_bfloat16 g_el [H_ * L_ * 64];

// ===========================================================================
// PTX helpers (base sm_103-legal)
// ===========================================================================
__device__ __forceinline__ uint32_t smem_u32(const void* p) {
    uint32_t a;
    asm("{ .reg .u64 t; cvta.to.shared.u64 t, %1; cvt.u32.u64 %0, t; }"
        : "=r"(a) : "l"(p));
    return a;
}
__device__ __forceinline__ void cpa16(uint32_t saddr, const void* g) {
    asm volatile("cp.async.cg.shared.global [%0], [%1], 16;" :: "r"(saddr), "l"(g));
}
__device__ __forceinline__ void cpa16z(uint32_t saddr, const void* g, int sz) {
    asm volatile("cp.async.cg.shared.global [%0], [%1], 16, %2;"
                 :: "r"(saddr), "l"(g), "r"(sz));
}
__device__ __forceinline__ void ldsm_x4(uint32_t* r, uint32_t addr) {
    asm volatile("ldmatrix.sync.aligned.m8n8.x4.shared.b16 {%0,%1,%2,%3}, [%4];"
                 : "=r"(r[0]), "=r"(r[1]), "=r"(r[2]), "=r"(r[3]) : "r"(addr));
}
__device__ __forceinline__ void ldsm_x4_t(uint32_t* r, uint32_t addr) {
    asm volatile("ldmatrix.sync.aligned.m8n8.x4.trans.shared.b16 {%0,%1,%2,%3}, [%4];"
                 : "=r"(r[0]), "=r"(r[1]), "=r"(r[2]), "=r"(r[3]) : "r"(addr));
}
__device__ __forceinline__ void mma16816(float* c, const uint32_t* a, const uint32_t* b) {
    asm volatile(
        "mma.sync.aligned.m16n8k16.row.col.f32.bf16.bf16.f32 "
        "{%0,%1,%2,%3}, {%4,%5,%6,%7}, {%8,%9}, {%0,%1,%2,%3};"
        : "+f"(c[0]), "+f"(c[1]), "+f"(c[2]), "+f"(c[3])
        : "r"(a[0]), "r"(a[1]), "r"(a[2]), "r"(a[3]), "r"(b[0]), "r"(b[1]));
}

// ===========================================================================
// fp32 -> bf16 hi/lo splits: all activations + Er in one launch (grid.z=4)
// ===========================================================================
__global__ __launch_bounds__(256)
void split_act_all(const float* __restrict__ x0, const float* __restrict__ x1,
                   const float* __restrict__ x2, const float* __restrict__ x3,
                   __nv_bfloat16* __restrict__ h0, __nv_bfloat16* __restrict__ l0,
                   __nv_bfloat16* __restrict__ h1, __nv_bfloat16* __restrict__ l1,
                   __nv_bfloat16* __restrict__ h2, __nv_bfloat16* __restrict__ l2,
                   __nv_bfloat16* __restrict__ h3, __nv_bfloat16* __restrict__ l3)
{
    const int zz = blockIdx.z;
    const float* x; __nv_bfloat16 *hi, *lo; int n;
    if      (zz == 0) { x = x0; hi = h0; lo = l0; n = B_ * L_ * D_; }
    else if (zz == 1) { x = x1; hi = h1; lo = l1; n = B_ * L_ * D_; }
    else if (zz == 2) { x = x2; hi = h2; lo = l2; n = B_ * L_ * D_; }
    else              { x = x3; hi = h3; lo = l3; n = H_ * L_ * 64; }
    int i = (blockIdx.x * 256 + threadIdx.x) * 4;
    if (i >= n) return;
    float4 v = *(const float4*)&x[i];
    __nv_bfloat16 a0 = __float2bfloat16(v.x);
    __nv_bfloat16 a1 = __float2bfloat16(v.y);
    __nv_bfloat16 a2 = __float2bfloat16(v.z);
    __nv_bfloat16 a3 = __float2bfloat16(v.w);
    __nv_bfloat162 hp0; hp0.x = a0; hp0.y = a1;
    __nv_bfloat162 hp1; hp1.x = a2; hp1.y = a3;
    *(__nv_bfloat162*)&hi[i]     = hp0;
    *(__nv_bfloat162*)&hi[i + 2] = hp1;
    __nv_bfloat162 lp0, lp1;
    lp0.x = __float2bfloat16(v.x - __bfloat162float(a0));
    lp0.y = __float2bfloat16(v.y - __bfloat162float(a1));
    lp1.x = __float2bfloat16(v.z - __bfloat162float(a2));
    lp1.y = __float2bfloat16(v.w - __bfloat162float(a3));
    *(__nv_bfloat162*)&lo[i]     = lp0;
    *(__nv_bfloat162*)&lo[i + 2] = lp1;
}

// All 5 weights: W[K,N] fp32 -> Wt[N,K] bf16 hi/lo (transpose + split), grid.z=5
__global__ __launch_bounds__(256)
void split_w_all(const float* __restrict__ W0, const float* __restrict__ W1,
                 const float* __restrict__ W2, const float* __restrict__ W3,
                 const float* __restrict__ W4,
                 __nv_bfloat16* __restrict__ th, __nv_bfloat16* __restrict__ tl)
{
    const float* W;
    switch (blockIdx.z) {
        case 0: W = W0; break;
        case 1: W = W1; break;
        case 2: W = W2; break;
        case 3: W = W3; break;
        default: W = W4; break;
    }
    __nv_bfloat16* h = th + (size_t)blockIdx.z * D_ * D_;
    __nv_bfloat16* l = tl + (size_t)blockIdx.z * D_ * D_;
    __shared__ float t[32][33];
    const int bx = blockIdx.x * 32;
    const int by = blockIdx.y * 32;
    const int tx = threadIdx.x & 31;
    const int ty = threadIdx.x >> 5;
    #pragma unroll
    for (int r = ty; r < 32; r += 8)
        t[r][tx] = W[(size_t)(by + r) * D_ + bx + tx];
    __syncthreads();
    #pragma unroll
    for (int r = ty; r < 32; r += 8) {
        float v = t[tx][r];
        __nv_bfloat16 hh = __float2bfloat16(v);
        h[(size_t)(bx + r) * D_ + by + tx] = hh;
        l[(size_t)(bx + r) * D_ + by + tx] = __float2bfloat16(v - __bfloat162float(hh));
    }
}

// ===========================================================================
// HMMA split-bf16 GEMM body
// ===========================================================================
#define TSTRIDE 40
#define TILE_BYTES (128 * TSTRIDE * 2)
#define STAGE_BYTES (4 * TILE_BYTES)

__device__ __forceinline__ void gemm_body(
    const __nv_bfloat16* __restrict__ Ah, const __nv_bfloat16* __restrict__ Al,
    const __nv_bfloat16* __restrict__ Bh, const __nv_bfloat16* __restrict__ Bl,
    float* __restrict__ C, const float* __restrict__ R,
    __nv_bfloat16* __restrict__ Oh, __nv_bfloat16* __restrict__ Ol,
    int K, int N, char* smem)
{
    const uint32_t sb0 = smem_u32(smem);
    const int tid  = threadIdx.x;
    const int wid  = tid >> 5;
    const int lane = tid & 31;
    const int m0 = blockIdx.y * 128;
    const int n0 = blockIdx.x * 128;
    const int wm = (wid & 3) * 32;
    const int wn = (wid >> 2) * 64;

    const __nv_bfloat16* gT[4] = {
        Ah + (size_t)m0 * K, Al + (size_t)m0 * K,
        Bh + (size_t)n0 * K, Bl + (size_t)n0 * K };

    auto load_chunk = [&](int c, int st) {
        const uint32_t sb = sb0 + st * STAGE_BYTES;
        const int k0 = c * 32;
        #pragma unroll
        for (int t = 0; t < 4; t++) {
            const __nv_bfloat16* g = gT[t] + k0;
            const uint32_t tb = sb + t * TILE_BYTES;
            #pragma unroll
            for (int it = 0; it < 2; it++) {
                int o   = tid + it * 256;
                int row = o >> 2, c16 = o & 3;
                cpa16(tb + row * (TSTRIDE * 2) + c16 * 16,
                      g + (size_t)row * K + c16 * 8);
            }
        }
        asm volatile("cp.async.commit_group;" ::: "memory");
    };

    float acc[2][8][4];
    #pragma unroll
    for (int i = 0; i < 2; i++)
        #pragma unroll
        for (int j = 0; j < 8; j++)
            #pragma unroll
            for (int q = 0; q < 4; q++) acc[i][j][q] = 0.f;

    const int arow = lane & 15;
    const int acolq = (lane >> 4) * 8;
    const int nrow = ((lane >> 4) * 8) + (lane & 7);
    const int bcolq = ((lane >> 3) & 1) * 8;

    const int NC = K / 32;
    load_chunk(0, 0);

    for (int c = 0; c < NC; ++c) {
        const int st = c & 1;
        if (c + 1 < NC) {
            load_chunk(c + 1, st ^ 1);
            asm volatile("cp.async.wait_group 1;" ::: "memory");
        } else {
            asm volatile("cp.async.wait_group 0;" ::: "memory");
        }
        __syncthreads();

        const uint32_t sb  = sb0 + st * STAGE_BYTES;
        const uint32_t sAh = sb;
        const uint32_t sAl = sb + TILE_BYTES;
        const uint32_t sBh = sb + 2 * TILE_BYTES;
        const uint32_t sBl = sb + 3 * TILE_BYTES;

        #pragma unroll
        for (int k16 = 0; k16 < 32; k16 += 16) {
            uint32_t ah[2][4], al[2][4], bh[4][4], bl[4][4];
            #pragma unroll
            for (int mt = 0; mt < 2; mt++) {
                uint32_t off = ((wm + mt * 16 + arow) * TSTRIDE + k16 + acolq) * 2;
                ldsm_x4(ah[mt], sAh + off);
                ldsm_x4(al[mt], sAl + off);
            }
            #pragma unroll
            for (int p = 0; p < 4; p++) {
                uint32_t off = ((wn + p * 16 + nrow) * TSTRIDE + k16 + bcolq) * 2;
                ldsm_x4(bh[p], sBh + off);
                ldsm_x4(bl[p], sBl + off);
            }
            #pragma unroll
            for (int mt = 0; mt < 2; mt++)
                #pragma unroll
                for (int nt = 0; nt < 8; nt++) {
                    const uint32_t* bhf = &bh[nt >> 1][(nt & 1) * 2];
                    const uint32_t* blf = &bl[nt >> 1][(nt & 1) * 2];
                    mma16816(acc[mt][nt], ah[mt], bhf);
                    mma16816(acc[mt][nt], ah[mt], blf);
                    mma16816(acc[mt][nt], al[mt], bhf);
                }
        }
        __syncthreads();
    }

    #pragma unroll
    for (int mt = 0; mt < 2; mt++) {
        const int m = m0 + wm + mt * 16 + (lane >> 2);
        #pragma unroll
        for (int nt = 0; nt < 8; nt++) {
            const int n = n0 + wn + nt * 8 + (lane & 3) * 2;
            if (Oh) {
                #pragma unroll
                for (int rr = 0; rr < 2; rr++) {
                    const size_t idx = (size_t)(m + rr * 8) * N + n;
                    float a0 = acc[mt][nt][rr * 2], a1 = acc[mt][nt][rr * 2 + 1];
                    __nv_bfloat162 hh, ll;
                    hh.x = __float2bfloat16(a0);
                    hh.y = __float2bfloat16(a1);
                    ll.x = __float2bfloat16(a0 - __bfloat162float(hh.x));
                    ll.y = __float2bfloat16(a1 - __bfloat162float(hh.y));
                    *(__nv_bfloat162*)&Oh[idx] = hh;
                    *(__nv_bfloat162*)&Ol[idx] = ll;
                }
            } else {
                float2 o0 = make_float2(acc[mt][nt][0], acc[mt][nt][1]);
                float2 o1 = make_float2(acc[mt][nt][2], acc[mt][nt][3]);
                if (R) {
                    const float2 r0 = *(const float2*)&R[(size_t)m * N + n];
                    const float2 r1 = *(const float2*)&R[(size_t)(m + 8) * N + n];
                    o0.x += r0.x; o0.y += r0.y;
                    o1.x += r1.x; o1.y += r1.y;
                }
                *(float2*)&C[(size_t)m * N + n] = o0;
                *(float2*)&C[(size_t)(m + 8) * N + n] = o1;
            }
        }
    }
}

// Generic GEMM entry (used for Wo)
__global__ __launch_bounds__(256, 2)
void gemm_tc(const __nv_bfloat16* __restrict__ Ah, const __nv_bfloat16* __restrict__ Al,
             const __nv_bfloat16* __restrict__ Bh, const __nv_bfloat16* __restrict__ Bl,
             float* __restrict__ C, const float* __restrict__ R,
             __nv_bfloat16* __restrict__ Oh, __nv_bfloat16* __restrict__ Ol,
             int K, int N)
{
    extern __shared__ __align__(16) char smem[];
    gemm_body(Ah, Al, Bh, Bl, C, R, Oh, Ol, K, N, smem);
}

// Batched projection GEMMs: z selects (A, W, O) from static buffers.
__global__ __launch_bounds__(256, 2)
void gemm_proj4()
{
    extern __shared__ __align__(16) char smem[];
    const size_t WSZ = (size_t)D_ * D_;
    const __nv_bfloat16 *Ah, *Al;
    __nv_bfloat16 *Oh, *Ol;
    const int z = blockIdx.z;
    switch (z) {
        case 0:  Ah = g_ah; Al = g_al; Oh = g_qh;  Ol = g_ql;  break;
        case 1:  Ah = g_ah; Al = g_al; Oh = g_q2h; Ol = g_q2l; break;
        case 2:  Ah = g_bh; Al = g_bl; Oh = g_kh;  Ol = g_kl;  break;
        default: Ah = g_ch; Al = g_cl; Oh = g_vh;  Ol = g_vl;  break;
    }
    gemm_body(Ah, Al, g_wh + z * WSZ, g_wl + z * WSZ,
              nullptr, nullptr, Oh, Ol, D_, D_, smem);
}

// ===========================================================================
// HMMA score kernel v3: 128 threads, 4 warps in 2(i) x 2(j) quadrants,
// each warp computes 32x32 (two 16-row m-tiles sharing a 64-wide Er band).
// S[i,j] = (q_i.k_j + q2_i.Er[L-1-(i-j)]) / 8, lower-triangle tiles only.
// ===========================================================================
#define SC_SQH 0
#define SC_SQL 8192
#define SC_S2H 16384
#define SC_S2L 24576
#define SC_SKH 32768
#define SC_SKL 40960
#define SC_SEH 49152
#define SC_SEL 65536
#define SC_SR  81920
#define SC_RSW 3584                    // per-(warp,mt) gather bytes (16 x 56 fp32)
#define SC_SMEM (81920 + 8 * SC_RSW)   // 110592

__global__ __launch_bounds__(128, 2)
void score_tc(const __nv_bfloat16* __restrict__ qh, const __nv_bfloat16* __restrict__ ql,
              const __nv_bfloat16* __restrict__ q2h, const __nv_bfloat16* __restrict__ q2l,
              const __nv_bfloat16* __restrict__ kh, const __nv_bfloat16* __restrict__ kl,
              const __nv_bfloat16* __restrict__ eh, const __nv_bfloat16* __restrict__ el,
              float* __restrict__ p)
{
    const int x = blockIdx.x;
    int ti = (int)((__fsqrt_rn(8.0f * x + 1.0f) - 1.0f) * 0.5f);
    if (ti * (ti + 1) / 2 > x) ti--;
    else if ((ti + 1) * (ti + 2) / 2 <= x) ti++;
    const int tj = x - ti * (ti + 1) / 2;
    const int z = blockIdx.y;
    const int i0 = ti * 64, j0 = tj * 64;
    const int h = z >> 2, b = z & 3;
    const int rbase = L_ - 64 - i0 + j0;

    extern __shared__ __align__(16) char smem[];
    const uint32_t sb = smem_u32(smem);
    const int tid = threadIdx.x;
    const int lane = tid & 31, w = tid >> 5;
    const int iw = w & 1, jw = w >> 1;   // 2 i-groups x 2 j-groups of 32

    // ---- loads (128 threads) ----
    auto load64 = [&](uint32_t st, const __nv_bfloat16* g) {
        #pragma unroll
        for (int t = 0; t < 4; t++) {
            int cid = tid + t * 128;          // 0..511
            int row = cid >> 3, c = cid & 7;
            cpa16(sb + st + row * 128 + ((c ^ (row & 7)) * 16),
                  g + (size_t)row * D_ + c * 8);
        }
    };
    const size_t qoff = (size_t)(b * L_ + i0) * D_ + h * 64;
    const size_t koff = (size_t)(b * L_ + j0) * D_ + h * 64;
    load64(SC_SQH, qh  + qoff);
    load64(SC_SQL, ql  + qoff);
    load64(SC_S2H, q2h + qoff);
    load64(SC_S2L, q2l + qoff);
    load64(SC_SKH, kh  + koff);
    load64(SC_SKL, kl  + koff);
    {
        const __nv_bfloat16* ehp = eh + (size_t)h * L_ * 64;
        const __nv_bfloat16* elp = el + (size_t)h * L_ * 64;
        #pragma unroll
        for (int t = 0; t < 8; t++) {
            int cid = tid + t * 128;          // 0..1023
            int row = cid >> 3, c = cid & 7;
            int r = rbase + row;
            int sz = (r < L_) ? 16 : 0;
            int rc = (r < L_) ? r : 0;
            uint32_t so = row * 128 + ((c ^ (row & 7)) * 16);
            cpa16z(sb + SC_SEH + so, ehp + (size_t)rc * 64 + c * 8, sz);
            cpa16z(sb + SC_SEL + so, elp + (size_t)rc * 64 + c * 8, sz);
        }
    }
    asm volatile("cp.async.commit_group;" ::: "memory");
    asm volatile("cp.async.wait_group 0;" ::: "memory");
    __syncthreads();

    float aqk[2][4][4], arl[2][6][4];
    #pragma unroll
    for (int m2 = 0; m2 < 2; m2++) {
        #pragma unroll
        for (int i = 0; i < 4; i++)
            #pragma unroll
            for (int q = 0; q < 4; q++) aqk[m2][i][q] = 0.f;
        #pragma unroll
        for (int i = 0; i < 6; i++)
            #pragma unroll
            for (int q = 0; q < 4; q++) arl[m2][i][q] = 0.f;
    }

    const int tb = 32 + 32 * jw - 32 * iw;   // Er band base (union of both m-tiles)

    auto ldB = [&](uint32_t st, int nrow0, int k16, uint32_t* r) {
        int row = nrow0 + (lane >> 4) * 8 + (lane & 7);
        int c = (k16 >> 3) + ((lane >> 3) & 1);
        ldsm_x4(r, sb + st + row * 128 + ((c ^ (row & 7)) * 16));
    };

    #pragma unroll
    for (int k16 = 0; k16 < 64; k16 += 16) {
        uint32_t Aq[2][2][4], A2[2][2][4];   // [mt][h/l][4]
        #pragma unroll
        for (int mt = 0; mt < 2; mt++) {
            int row = 32 * iw + 16 * mt + (lane & 15);
            int c = (k16 >> 3) + (lane >> 4);
            uint32_t off = row * 128 + ((c ^ (row & 7)) * 16);
            ldsm_x4(Aq[mt][0], sb + SC_SQH + off);
            ldsm_x4(Aq[mt][1], sb + SC_SQL + off);
            ldsm_x4(A2[mt][0], sb + SC_S2H + off);
            ldsm_x4(A2[mt][1], sb + SC_S2L + off);
        }
        // qk: K tile cols 32*jw..+32 (2 groups of 16)
        #pragma unroll
        for (int pg = 0; pg < 2; pg++) {
            uint32_t Bh[4], Bl[4];
            ldB(SC_SKH, 32 * jw + pg * 16, k16, Bh);
            ldB(SC_SKL, 32 * jw + pg * 16, k16, Bl);
            #pragma unroll
            for (int mt = 0; mt < 2; mt++) {
                mma16816(aqk[mt][2 * pg],     Aq[mt][0], Bh);
                mma16816(aqk[mt][2 * pg + 1], Aq[mt][0], Bh + 2);
                mma16816(aqk[mt][2 * pg],     Aq[mt][0], Bl);
                mma16816(aqk[mt][2 * pg + 1], Aq[mt][0], Bl + 2);
                mma16816(aqk[mt][2 * pg],     Aq[mt][1], Bh);
                mma16816(aqk[mt][2 * pg + 1], Aq[mt][1], Bh + 2);
            }
        }
        // rel: 4 shared band groups; mt0 uses g=1..3, mt1 uses g=0..2
        #pragma unroll
        for (int g = 0; g < 4; g++) {
            uint32_t Bh[4], Bl[4];
            ldB(SC_SEH, tb + g * 16, k16, Bh);
            ldB(SC_SEL, tb + g * 16, k16, Bl);
            if (g >= 1) {
                const int li = g - 1;
                mma16816(arl[0][2 * li],     A2[0][0], Bh);
                mma16816(arl[0][2 * li + 1], A2[0][0], Bh + 2);
                mma16816(arl[0][2 * li],     A2[0][0], Bl);
                mma16816(arl[0][2 * li + 1], A2[0][0], Bl + 2);
                mma16816(arl[0][2 * li],     A2[0][1], Bh);
                mma16816(arl[0][2 * li + 1], A2[0][1], Bh + 2);
            }
            if (g <= 2) {
                const int li = g;
                mma16816(arl[1][2 * li],     A2[1][0], Bh);
                mma16816(arl[1][2 * li + 1], A2[1][0], Bh + 2);
                mma16816(arl[1][2 * li],     A2[1][0], Bl);
                mma16816(arl[1][2 * li + 1], A2[1][0], Bl + 2);
                mma16816(arl[1][2 * li],     A2[1][1], Bh);
                mma16816(arl[1][2 * li + 1], A2[1][1], Bh + 2);
            }
        }
    }

    // ---- per-(warp,mt) skew gather (48-wide band each; stride 56 fp32) ----
    const int r0 = lane >> 2, cb = (lane & 3) * 2;
    #pragma unroll
    for (int mt = 0; mt < 2; mt++) {
        float* Rs = (float*)(smem + SC_SR + (w * 2 + mt) * SC_RSW);
        #pragma unroll
        for (int nt = 0; nt < 6; nt++) {
            int tcol = nt * 8 + cb;
            Rs[r0 * 56 + tcol]           = arl[mt][nt][0];
            Rs[r0 * 56 + tcol + 1]       = arl[mt][nt][1];
            Rs[(r0 + 8) * 56 + tcol]     = arl[mt][nt][2];
            Rs[(r0 + 8) * 56 + tcol + 1] = arl[mt][nt][3];
        }
    }
    __syncwarp();

    #pragma unroll
    for (int mt = 0; mt < 2; mt++) {
        float* Rs = (float*)(smem + SC_SR + (w * 2 + mt) * SC_RSW);
        #pragma unroll
        for (int nt = 0; nt < 4; nt++) {
            int jc = nt * 8 + cb;
            float2 o0, o1;
            o0.x = (aqk[mt][nt][0] + Rs[r0 * 56 + 15 + jc - r0]) * 0.125f;
            o0.y = (aqk[mt][nt][1] + Rs[r0 * 56 + 16 + jc - r0]) * 0.125f;
            o1.x = (aqk[mt][nt][2] + Rs[(r0 + 8) * 56 + 7 + jc - r0]) * 0.125f;
            o1.y = (aqk[mt][nt][3] + Rs[(r0 + 8) * 56 + 8 + jc - r0]) * 0.125f;
            size_t base = ((size_t)z * L_ + i0 + 32 * iw + 16 * mt + r0) * L_
                        + j0 + 32 * jw + jc;
            *(float2*)&p[base]          = o0;
            *(float2*)&p[base + 8 * L_] = o1;
        }
    }
}

// ===========================================================================
// Single-pass row softmax; loads ONLY j <= i (predicated), writes full row.
// ===========================================================================
__global__ __launch_bounds__(256)
void softmax1p(float* __restrict__ p)
{
    const int i = blockIdx.x, z = blockIdx.y, tid = threadIdx.x;
    float* row = p + ((size_t)z * L_ + i) * L_;
    __shared__ float sh[8];

    const int j0 = tid * 4;
    float4 x;
    if (j0 <= i) {
        x = *(const float4*)&row[j0];
        if (j0 + 1 > i) x.y = -FLT_MAX;
        if (j0 + 2 > i) x.z = -FLT_MAX;
        if (j0 + 3 > i) x.w = -FLT_MAX;
    } else {
        x = make_float4(-FLT_MAX, -FLT_MAX, -FLT_MAX, -FLT_MAX);
    }

    float m = fmaxf(fmaxf(x.x, x.y), fmaxf(x.z, x.w));
    #pragma unroll
    for (int o = 16; o > 0; o >>= 1) m = fmaxf(m, __shfl_xor_sync(0xffffffffu, m, o));
    if ((tid & 31) == 0) sh[tid >> 5] = m;
    __syncthreads();
    float mt = -FLT_MAX;
    #pragma unroll
    for (int wv = 0; wv < 8; wv++) mt = fmaxf(mt, sh[wv]);
    __syncthreads();

    float4 e;
    e.x = __expf(x.x - mt);
    e.y = __expf(x.y - mt);
    e.z = __expf(x.z - mt);
    e.w = __expf(x.w - mt);
    float s = e.x + e.y + e.z + e.w;
    #pragma unroll
    for (int o = 16; o > 0; o >>= 1) s += __shfl_xor_sync(0xffffffffu, s, o);
    if ((tid & 31) == 0) sh[tid >> 5] = s;
    __syncthreads();
    float st = 0.f;
    #pragma unroll
    for (int wv = 0; wv < 8; wv++) st += sh[wv];
    const float inv = 1.0f / st;

    e.x *= inv; e.y *= inv; e.z *= inv; e.w *= inv;
    *(float4*)&row[j0] = e;
}

// ===========================================================================
// HMMA pv: out[i,d] = sum_{j<=i} p[i,j] v[j,d]; writes att bf16 hi/lo directly.
// ===========================================================================
__global__ __launch_bounds__(128)
void pv_tc(const float* __restrict__ p,
           const __nv_bfloat16* __restrict__ vh, const __nv_bfloat16* __restrict__ vl,
           __nv_bfloat16* __restrict__ oh, __nv_bfloat16* __restrict__ ol)
{
    const int ti = blockIdx.x, z = blockIdx.y;
    const int i0 = ti * 64;
    const int h = z >> 2, b = z & 3;
    const int tid = threadIdx.x;
    const int lane = tid & 31, w = tid >> 5;

    __shared__ __align__(128) char sv[2][2][4096];
    __shared__ __align__(128) char sp[4][2][1280];
    const uint32_t svb = smem_u32(&sv[0][0][0]);
    const uint32_t spw = smem_u32(&sp[w][0][0]);

    auto loadV = [&](int kj, int bi) {
        #pragma unroll
        for (int t = 0; t < 4; t++) {
            int cid = tid + t * 128;
            int sel = cid >> 8, rid = (cid >> 3) & 31, c = cid & 7;
            const __nv_bfloat16* g = (sel ? vl : vh)
                + ((size_t)(b * L_ + kj + rid) * D_ + h * 64 + c * 8);
            cpa16(svb + bi * 8192 + sel * 4096 + rid * 128 + ((c ^ (rid & 7)) * 16), g);
        }
        asm volatile("cp.async.commit_group;" ::: "memory");
    };

    float acc[8][4];
    #pragma unroll
    for (int i = 0; i < 8; i++)
        #pragma unroll
        for (int q = 0; q < 4; q++) acc[i][q] = 0.f;

    const int nch = (i0 + 64) >> 5;
    loadV(0, 0);

    for (int c = 0; c < nch; c++) {
        const int bi = c & 1;
        __syncthreads();
        if (c + 1 < nch) loadV((c + 1) * 32, bi ^ 1);

        {
            const int row = lane >> 1, chalf = lane & 1;
            const float* gp = p + ((size_t)z * L_ + i0 + 16 * w + row) * L_
                                + c * 32 + chalf * 16;
            uint32_t* ph = (uint32_t*)(&sp[w][0][0] + row * 80 + chalf * 32);
            uint32_t* pl = (uint32_t*)(&sp[w][1][0] + row * 80 + chalf * 32);
            #pragma unroll
            for (int q = 0; q < 4; q++) {
                float4 v = *(const float4*)(gp + q * 4);
                __nv_bfloat162 h0, h1, l0, l1;
                h0.x = __float2bfloat16(v.x); h0.y = __float2bfloat16(v.y);
                h1.x = __float2bfloat16(v.z); h1.y = __float2bfloat16(v.w);
                l0.x = __float2bfloat16(v.x - __bfloat162float(h0.x));
                l0.y = __float2bfloat16(v.y - __bfloat162float(h0.y));
                l1.x = __float2bfloat16(v.z - __bfloat162float(h1.x));
                l1.y = __float2bfloat16(v.w - __bfloat162float(h1.y));
                ph[q * 2]     = *(uint32_t*)&h0;
                ph[q * 2 + 1] = *(uint32_t*)&h1;
                pl[q * 2]     = *(uint32_t*)&l0;
                pl[q * 2 + 1] = *(uint32_t*)&l1;
            }
        }
        __syncwarp();
        if (c + 1 < nch) asm volatile("cp.async.wait_group 1;" ::: "memory");
        else             asm volatile("cp.async.wait_group 0;" ::: "memory");
        __syncthreads();

        #pragma unroll
        for (int k16 = 0; k16 < 32; k16 += 16) {
            uint32_t Aph[4], Apl[4];
            {
                int arow = lane & 15;
                int ac = (k16 >> 3) + (lane >> 4);
                ldsm_x4(Aph, spw + arow * 80 + ac * 16);
                ldsm_x4(Apl, spw + 1280 + arow * 80 + ac * 16);
            }
            #pragma unroll
            for (int p4 = 0; p4 < 4; p4++) {
                uint32_t Bh[4], Bl[4];
                int krow = k16 + ((lane >> 3) & 1) * 8 + (lane & 7);
                int cc = p4 * 2 + (lane >> 4);
                uint32_t off = krow * 128 + ((cc ^ (krow & 7)) * 16);
                ldsm_x4_t(Bh, svb + bi * 8192 + off);
                ldsm_x4_t(Bl, svb + bi * 8192 + 4096 + off);
                mma16816(acc[2 * p4],     Aph, Bh);
                mma16816(acc[2 * p4 + 1], Aph, Bh + 2);
                mma16816(acc[2 * p4],     Aph, Bl);
                mma16816(acc[2 * p4 + 1], Aph, Bl + 2);
                mma16816(acc[2 * p4],     Apl, Bh);
                mma16816(acc[2 * p4 + 1], Apl, Bh + 2);
            }
        }
    }

    const int r0 = lane >> 2, cb = (lane & 3) * 2;
    #pragma unroll
    for (int nt = 0; nt < 8; nt++) {
        const int d = nt * 8 + cb;
        #pragma unroll
        for (int rr = 0; rr < 2; rr++) {
            const int i = i0 + 16 * w + r0 + rr * 8;
            const size_t idx = (size_t)(b * L_ + i) * D_ + h * 64 + d;
            float a0 = acc[nt][rr * 2], a1 = acc[nt][rr * 2 + 1];
            __nv_bfloat162 hh, ll;
            hh.x = __float2bfloat16(a0);
            hh.y = __float2bfloat16(a1);
            ll.x = __float2bfloat16(a0 - __bfloat162float(hh.x));
            ll.y = __float2bfloat16(a1 - __bfloat162float(hh.y));
            *(__nv_bfloat162*)&oh[idx] = hh;
            *(__nv_bfloat162*)&ol[idx] = ll;
        }
    }
}

// ===========================================================================
// LayerNorm
// ===========================================================================
__global__ __launch_bounds__(256)
void ln_kernel(const float* __restrict__ x, const float* __restrict__ gam,
               const float* __restrict__ bet, float* __restrict__ y)
{
    const int r = blockIdx.x, tid = threadIdx.x;
    __shared__ float sh[16];
    const float* xr = x + (size_t)r * D_;
    float4 xv = *(const float4*)&xr[tid * 4];
    float s  = xv.x + xv.y + xv.z + xv.w;
    float ss = xv.x*xv.x + xv.y*xv.y + xv.z*xv.z + xv.w*xv.w;
    #pragma unroll
    for (int o = 16; o > 0; o >>= 1) {
        s  += __shfl_xor_sync(0xffffffffu, s,  o);
        ss += __shfl_xor_sync(0xffffffffu, ss, o);
    }
    if ((tid & 31) == 0) { sh[tid >> 5] = s; sh[8 + (tid >> 5)] = ss; }
    __syncthreads();
    float st = 0.f, sst = 0.f;
    #pragma unroll
    for (int wv = 0; wv < 8; wv++) { st += sh[wv]; sst += sh[8 + wv]; }
    const float mu  = st * (1.0f / D_);
    const float var = sst * (1.0f / D_) - mu * mu;
    const float rs  = rsqrtf(var + 1e-5f);
    float4 gv = *(const float4*)&gam[tid * 4];
    float4 bv = *(const float4*)&bet[tid * 4];
    float4 o4;
    o4.x = (xv.x - mu) * rs * gv.x + bv.x;
    o4.y = (xv.y - mu) * rs * gv.y + bv.y;
    o4.z = (xv.z - mu) * rs * gv.z + bv.z;
    o4.w = (xv.w - mu) * rs * gv.w + bv.w;
    *(float4*)&y[(size_t)r * D_ + tid * 4] = o4;
}

// ===========================================================================
// Launch
// ===========================================================================
extern "C" void kernel_launch(void* const* d_in, const int* in_sizes, int n_in,
                              void* d_out, int out_size)
{
    const float* q_in = (const float*)d_in[0];
    const float* k_in = (const float*)d_in[1];
    const float* v_in = (const float*)d_in[2];
    const float* Wq   = (const float*)d_in[3];
    const float* Wq2  = (const float*)d_in[4];
    const float* Wk   = (const float*)d_in[5];
    const float* Wv   = (const float*)d_in[6];
    const float* Wo   = (const float*)d_in[7];
    const float* ln_g = (const float*)d_in[8];
    const float* ln_b = (const float*)d_in[9];
    const float* Er   = (const float*)d_in[10];
    (void)in_sizes; (void)n_in;

    float *px, *pfb;
    __nv_bfloat16 *ah, *al, *bh, *bl, *ch, *cl, *wh, *wl;
    __nv_bfloat16 *qh, *ql, *q2h, *q2l, *kh, *kl, *vh, *vl, *eh, *el;
    cudaGetSymbolAddress((void**)&px,  g_x);
    cudaGetSymbolAddress((void**)&pfb, g_pfb);
    cudaGetSymbolAddress((void**)&ah,  g_ah);
    cudaGetSymbolAddress((void**)&al,  g_al);
    cudaGetSymbolAddress((void**)&bh,  g_bh);
    cudaGetSymbolAddress((void**)&bl,  g_bl);
    cudaGetSymbolAddress((void**)&ch,  g_ch);
    cudaGetSymbolAddress((void**)&cl,  g_cl);
    cudaGetSymbolAddress((void**)&wh,  g_wh);
    cudaGetSymbolAddress((void**)&wl,  g_wl);
    cudaGetSymbolAddress((void**)&qh,  g_qh);
    cudaGetSymbolAddress((void**)&ql,  g_ql);
    cudaGetSymbolAddress((void**)&q2h, g_q2h);
    cudaGetSymbolAddress((void**)&q2l, g_q2l);
    cudaGetSymbolAddress((void**)&kh,  g_kh);
    cudaGetSymbolAddress((void**)&kl,  g_kl);
    cudaGetSymbolAddress((void**)&vh,  g_vh);
    cudaGetSymbolAddress((void**)&vl,  g_vl);
    cudaGetSymbolAddress((void**)&eh,  g_eh);
    cudaGetSymbolAddress((void**)&el,  g_el);

    float* y_out = (float*)d_out;
    const long long ysz = (long long)B_ * L_ * D_;
    const long long psz = (long long)HB_ * L_ * L_;
    float* p_buf = ((long long)out_size >= ysz + psz) ? (y_out + ysz) : pfb;

    const int gsmem = 2 * STAGE_BYTES;
    cudaFuncSetAttribute(gemm_tc, cudaFuncAttributeMaxDynamicSharedMemorySize, gsmem);
    cudaFuncSetAttribute(gemm_proj4, cudaFuncAttributeMaxDynamicSharedMemorySize, gsmem);
    cudaFuncSetAttribute(score_tc, cudaFuncAttributeMaxDynamicSharedMemorySize, SC_SMEM);

    const int M = B_ * L_;
    const dim3 ggemm(D_ / 128, M / 128);
    const size_t WSZ = (size_t)D_ * D_;

    // all splits upfront
    split_act_all<<<dim3(4096, 1, 4), 256>>>(q_in, k_in, v_in, Er,
                                             ah, al, bh, bl, ch, cl, eh, el);
    split_w_all<<<dim3(32, 32, 5), 256>>>(Wq, Wq2, Wk, Wv, Wo, wh, wl);

    // 4 projections in ONE batched launch (z selects buffers)
    gemm_proj4<<<dim3(D_ / 128, M / 128, 4), 256, gsmem>>>();

    // attention middle: scores (tri-grid, 32x32-per-warp layout), softmax, pv
    score_tc<<<dim3(136, HB_), 128, SC_SMEM>>>(qh, ql, q2h, q2l, kh, kl, eh, el, p_buf);
    softmax1p<<<dim3(L_, HB_), 256>>>(p_buf);
    pv_tc<<<dim3(16, HB_), 128>>>(p_buf, vh, vl, ah, al);   // att -> ah/al

    // Wo GEMM (fp32 out + residual), then LN
    gemm_tc<<<ggemm, 256, gsmem>>>(ah, al, wh + 4 * WSZ, wl + 4 * WSZ,
                                   px, q_in, nullptr, nullptr, D_, D_);
    ln_kernel<<<B_ * L_, 256>>>(px, ln_g, ln_b, y_out);
}

// round 10
// speedup vs baseline: 1.6972x; 1.0444x over previous
#include <cuda_runtime.h>
#include <cuda_bf16.h>
#include <cfloat>
#include <cstdint>

// Problem constants
#define B_  4
#define L_  1024
#define D_  1024
#define H_  16
#define HB_ 64   // H*B

// ===========================================================================
// Scratch (static __device__)
// ===========================================================================
__device__ float g_x  [B_ * L_ * D_];
__device__ float g_pfb[HB_ * L_ * L_];               // fallback p buffer
__device__ __nv_bfloat16 g_ah[B_ * L_ * D_];         // q_in split hi / att hi
__device__ __nv_bfloat16 g_al[B_ * L_ * D_];         // q_in split lo / att lo
__device__ __nv_bfloat16 g_bh[B_ * L_ * D_];         // k_in split hi
__device__ __nv_bfloat16 g_bl[B_ * L_ * D_];         // k_in split lo
__device__ __nv_bfloat16 g_ch[B_ * L_ * D_];         // v_in split hi
__device__ __nv_bfloat16 g_cl[B_ * L_ * D_];         // v_in split lo
__device__ __nv_bfloat16 g_wh[5 * D_ * D_];          // weights^T split hi [N,K]
__device__ __nv_bfloat16 g_wl[5 * D_ * D_];          // weights^T split lo [N,K]
__device__ __nv_bfloat16 g_qh [B_ * L_ * D_];
__device__ __nv_bfloat16 g_ql [B_ * L_ * D_];
__device__ __nv_bfloat16 g_q2h[B_ * L_ * D_];
__device__ __nv_bfloat16 g_q2l[B_ * L_ * D_];
__device__ __nv_bfloat16 g_kh [B_ * L_ * D_];
__device__ __nv_bfloat16 g_kl [B_ * L_ * D_];
__device__ __nv_bfloat16 g_vh [B_ * L_ * D_];
__device__ __nv_bfloat16 g_vl [B_ * L_ * D_];
__device__ __nv_bfloat16 g_eh [H_ * L_ * 64];
__device__ __nv_bfloat16 g_el [H_ * L_ * 64];

// ===========================================================================
// PTX helpers (base sm_103-legal)
// ===========================================================================
__device__ __forceinline__ uint32_t smem_u32(const void* p) {
    uint32_t a;
    asm("{ .reg .u64 t; cvta.to.shared.u64 t, %1; cvt.u32.u64 %0, t; }"
        : "=r"(a) : "l"(p));
    return a;
}
__device__ __forceinline__ void cpa16(uint32_t saddr, const void* g) {
    asm volatile("cp.async.cg.shared.global [%0], [%1], 16;" :: "r"(saddr), "l"(g));
}
__device__ __forceinline__ void cpa16z(uint32_t saddr, const void* g, int sz) {
    asm volatile("cp.async.cg.shared.global [%0], [%1], 16, %2;"
                 :: "r"(saddr), "l"(g), "r"(sz));
}
__device__ __forceinline__ void ldsm_x4(uint32_t* r, uint32_t addr) {
    asm volatile("ldmatrix.sync.aligned.m8n8.x4.shared.b16 {%0,%1,%2,%3}, [%4];"
                 : "=r"(r[0]), "=r"(r[1]), "=r"(r[2]), "=r"(r[3]) : "r"(addr));
}
__device__ __forceinline__ void ldsm_x4_t(uint32_t* r, uint32_t addr) {
    asm volatile("ldmatrix.sync.aligned.m8n8.x4.trans.shared.b16 {%0,%1,%2,%3}, [%4];"
                 : "=r"(r[0]), "=r"(r[1]), "=r"(r[2]), "=r"(r[3]) : "r"(addr));
}
__device__ __forceinline__ void mma16816(float* c, const uint32_t* a, const uint32_t* b) {
    asm volatile(
        "mma.sync.aligned.m16n8k16.row.col.f32.bf16.bf16.f32 "
        "{%0,%1,%2,%3}, {%4,%5,%6,%7}, {%8,%9}, {%0,%1,%2,%3};"
        : "+f"(c[0]), "+f"(c[1]), "+f"(c[2]), "+f"(c[3])
        : "r"(a[0]), "r"(a[1]), "r"(a[2]), "r"(a[3]), "r"(b[0]), "r"(b[1]));
}

// ===========================================================================
// fp32 -> bf16 hi/lo splits: all activations + Er in one launch (grid.z=4)
// ===========================================================================
__global__ __launch_bounds__(256)
void split_act_all(const float* __restrict__ x0, const float* __restrict__ x1,
                   const float* __restrict__ x2, const float* __restrict__ x3,
                   __nv_bfloat16* __restrict__ h0, __nv_bfloat16* __restrict__ l0,
                   __nv_bfloat16* __restrict__ h1, __nv_bfloat16* __restrict__ l1,
                   __nv_bfloat16* __restrict__ h2, __nv_bfloat16* __restrict__ l2,
                   __nv_bfloat16* __restrict__ h3, __nv_bfloat16* __restrict__ l3)
{
    const int zz = blockIdx.z;
    const float* x; __nv_bfloat16 *hi, *lo; int n;
    if      (zz == 0) { x = x0; hi = h0; lo = l0; n = B_ * L_ * D_; }
    else if (zz == 1) { x = x1; hi = h1; lo = l1; n = B_ * L_ * D_; }
    else if (zz == 2) { x = x2; hi = h2; lo = l2; n = B_ * L_ * D_; }
    else              { x = x3; hi = h3; lo = l3; n = H_ * L_ * 64; }
    int i = (blockIdx.x * 256 + threadIdx.x) * 4;
    if (i >= n) return;
    float4 v = *(const float4*)&x[i];
    __nv_bfloat16 a0 = __float2bfloat16(v.x);
    __nv_bfloat16 a1 = __float2bfloat16(v.y);
    __nv_bfloat16 a2 = __float2bfloat16(v.z);
    __nv_bfloat16 a3 = __float2bfloat16(v.w);
    __nv_bfloat162 hp0; hp0.x = a0; hp0.y = a1;
    __nv_bfloat162 hp1; hp1.x = a2; hp1.y = a3;
    *(__nv_bfloat162*)&hi[i]     = hp0;
    *(__nv_bfloat162*)&hi[i + 2] = hp1;
    __nv_bfloat162 lp0, lp1;
    lp0.x = __float2bfloat16(v.x - __bfloat162float(a0));
    lp0.y = __float2bfloat16(v.y - __bfloat162float(a1));
    lp1.x = __float2bfloat16(v.z - __bfloat162float(a2));
    lp1.y = __float2bfloat16(v.w - __bfloat162float(a3));
    *(__nv_bfloat162*)&lo[i]     = lp0;
    *(__nv_bfloat162*)&lo[i + 2] = lp1;
}

// All 5 weights: W[K,N] fp32 -> Wt[N,K] bf16 hi/lo (transpose + split), grid.z=5
__global__ __launch_bounds__(256)
void split_w_all(const float* __restrict__ W0, const float* __restrict__ W1,
                 const float* __restrict__ W2, const float* __restrict__ W3,
                 const float* __restrict__ W4,
                 __nv_bfloat16* __restrict__ th, __nv_bfloat16* __restrict__ tl)
{
    const float* W;
    switch (blockIdx.z) {
        case 0: W = W0; break;
        case 1: W = W1; break;
        case 2: W = W2; break;
        case 3: W = W3; break;
        default: W = W4; break;
    }
    __nv_bfloat16* h = th + (size_t)blockIdx.z * D_ * D_;
    __nv_bfloat16* l = tl + (size_t)blockIdx.z * D_ * D_;
    __shared__ float t[32][33];
    const int bx = blockIdx.x * 32;
    const int by = blockIdx.y * 32;
    const int tx = threadIdx.x & 31;
    const int ty = threadIdx.x >> 5;
    #pragma unroll
    for (int r = ty; r < 32; r += 8)
        t[r][tx] = W[(size_t)(by + r) * D_ + bx + tx];
    __syncthreads();
    #pragma unroll
    for (int r = ty; r < 32; r += 8) {
        float v = t[tx][r];
        __nv_bfloat16 hh = __float2bfloat16(v);
        h[(size_t)(bx + r) * D_ + by + tx] = hh;
        l[(size_t)(bx + r) * D_ + by + tx] = __float2bfloat16(v - __bfloat162float(hh));
    }
}

// ===========================================================================
// HMMA split-bf16 GEMM body
// ===========================================================================
#define TSTRIDE 40
#define TILE_BYTES (128 * TSTRIDE * 2)
#define STAGE_BYTES (4 * TILE_BYTES)

__device__ __forceinline__ void gemm_body(
    const __nv_bfloat16* __restrict__ Ah, const __nv_bfloat16* __restrict__ Al,
    const __nv_bfloat16* __restrict__ Bh, const __nv_bfloat16* __restrict__ Bl,
    float* __restrict__ C, const float* __restrict__ R,
    __nv_bfloat16* __restrict__ Oh, __nv_bfloat16* __restrict__ Ol,
    int K, int N, char* smem)
{
    const uint32_t sb0 = smem_u32(smem);
    const int tid  = threadIdx.x;
    const int wid  = tid >> 5;
    const int lane = tid & 31;
    const int m0 = blockIdx.y * 128;
    const int n0 = blockIdx.x * 128;
    const int wm = (wid & 3) * 32;
    const int wn = (wid >> 2) * 64;

    const __nv_bfloat16* gT[4] = {
        Ah + (size_t)m0 * K, Al + (size_t)m0 * K,
        Bh + (size_t)n0 * K, Bl + (size_t)n0 * K };

    auto load_chunk = [&](int c, int st) {
        const uint32_t sb = sb0 + st * STAGE_BYTES;
        const int k0 = c * 32;
        #pragma unroll
        for (int t = 0; t < 4; t++) {
            const __nv_bfloat16* g = gT[t] + k0;
            const uint32_t tb = sb + t * TILE_BYTES;
            #pragma unroll
            for (int it = 0; it < 2; it++) {
                int o   = tid + it * 256;
                int row = o >> 2, c16 = o & 3;
                cpa16(tb + row * (TSTRIDE * 2) + c16 * 16,
                      g + (size_t)row * K + c16 * 8);
            }
        }
        asm volatile("cp.async.commit_group;" ::: "memory");
    };

    float acc[2][8][4];
    #pragma unroll
    for (int i = 0; i < 2; i++)
        #pragma unroll
        for (int j = 0; j < 8; j++)
            #pragma unroll
            for (int q = 0; q < 4; q++) acc[i][j][q] = 0.f;

    const int arow = lane & 15;
    const int acolq = (lane >> 4) * 8;
    const int nrow = ((lane >> 4) * 8) + (lane & 7);
    const int bcolq = ((lane >> 3) & 1) * 8;

    const int NC = K / 32;
    load_chunk(0, 0);

    for (int c = 0; c < NC; ++c) {
        const int st = c & 1;
        if (c + 1 < NC) {
            load_chunk(c + 1, st ^ 1);
            asm volatile("cp.async.wait_group 1;" ::: "memory");
        } else {
            asm volatile("cp.async.wait_group 0;" ::: "memory");
        }
        __syncthreads();

        const uint32_t sb  = sb0 + st * STAGE_BYTES;
        const uint32_t sAh = sb;
        const uint32_t sAl = sb + TILE_BYTES;
        const uint32_t sBh = sb + 2 * TILE_BYTES;
        const uint32_t sBl = sb + 3 * TILE_BYTES;

        #pragma unroll
        for (int k16 = 0; k16 < 32; k16 += 16) {
            uint32_t ah[2][4], al[2][4], bh[4][4], bl[4][4];
            #pragma unroll
            for (int mt = 0; mt < 2; mt++) {
                uint32_t off = ((wm + mt * 16 + arow) * TSTRIDE + k16 + acolq) * 2;
                ldsm_x4(ah[mt], sAh + off);
                ldsm_x4(al[mt], sAl + off);
            }
            #pragma unroll
            for (int p = 0; p < 4; p++) {
                uint32_t off = ((wn + p * 16 + nrow) * TSTRIDE + k16 + bcolq) * 2;
                ldsm_x4(bh[p], sBh + off);
                ldsm_x4(bl[p], sBl + off);
            }
            #pragma unroll
            for (int mt = 0; mt < 2; mt++)
                #pragma unroll
                for (int nt = 0; nt < 8; nt++) {
                    const uint32_t* bhf = &bh[nt >> 1][(nt & 1) * 2];
                    const uint32_t* blf = &bl[nt >> 1][(nt & 1) * 2];
                    mma16816(acc[mt][nt], ah[mt], bhf);
                    mma16816(acc[mt][nt], ah[mt], blf);
                    mma16816(acc[mt][nt], al[mt], bhf);
                }
        }
        __syncthreads();
    }

    #pragma unroll
    for (int mt = 0; mt < 2; mt++) {
        const int m = m0 + wm + mt * 16 + (lane >> 2);
        #pragma unroll
        for (int nt = 0; nt < 8; nt++) {
            const int n = n0 + wn + nt * 8 + (lane & 3) * 2;
            if (Oh) {
                #pragma unroll
                for (int rr = 0; rr < 2; rr++) {
                    const size_t idx = (size_t)(m + rr * 8) * N + n;
                    float a0 = acc[mt][nt][rr * 2], a1 = acc[mt][nt][rr * 2 + 1];
                    __nv_bfloat162 hh, ll;
                    hh.x = __float2bfloat16(a0);
                    hh.y = __float2bfloat16(a1);
                    ll.x = __float2bfloat16(a0 - __bfloat162float(hh.x));
                    ll.y = __float2bfloat16(a1 - __bfloat162float(hh.y));
                    *(__nv_bfloat162*)&Oh[idx] = hh;
                    *(__nv_bfloat162*)&Ol[idx] = ll;
                }
            } else {
                float2 o0 = make_float2(acc[mt][nt][0], acc[mt][nt][1]);
                float2 o1 = make_float2(acc[mt][nt][2], acc[mt][nt][3]);
                if (R) {
                    const float2 r0 = *(const float2*)&R[(size_t)m * N + n];
                    const float2 r1 = *(const float2*)&R[(size_t)(m + 8) * N + n];
                    o0.x += r0.x; o0.y += r0.y;
                    o1.x += r1.x; o1.y += r1.y;
                }
                *(float2*)&C[(size_t)m * N + n] = o0;
                *(float2*)&C[(size_t)(m + 8) * N + n] = o1;
            }
        }
    }
}

// Generic GEMM entry (used for Wo)
__global__ __launch_bounds__(256, 2)
void gemm_tc(const __nv_bfloat16* __restrict__ Ah, const __nv_bfloat16* __restrict__ Al,
             const __nv_bfloat16* __restrict__ Bh, const __nv_bfloat16* __restrict__ Bl,
             float* __restrict__ C, const float* __restrict__ R,
             __nv_bfloat16* __restrict__ Oh, __nv_bfloat16* __restrict__ Ol,
             int K, int N)
{
    extern __shared__ __align__(16) char smem[];
    gemm_body(Ah, Al, Bh, Bl, C, R, Oh, Ol, K, N, smem);
}

// Batched projection GEMMs: z selects (A, W, O) from static buffers.
__global__ __launch_bounds__(256, 2)
void gemm_proj4()
{
    extern __shared__ __align__(16) char smem[];
    const size_t WSZ = (size_t)D_ * D_;
    const __nv_bfloat16 *Ah, *Al;
    __nv_bfloat16 *Oh, *Ol;
    const int z = blockIdx.z;
    switch (z) {
        case 0:  Ah = g_ah; Al = g_al; Oh = g_qh;  Ol = g_ql;  break;
        case 1:  Ah = g_ah; Al = g_al; Oh = g_q2h; Ol = g_q2l; break;
        case 2:  Ah = g_bh; Al = g_bl; Oh = g_kh;  Ol = g_kl;  break;
        default: Ah = g_ch; Al = g_cl; Oh = g_vh;  Ol = g_vl;  break;
    }
    gemm_body(Ah, Al, g_wh + z * WSZ, g_wl + z * WSZ,
              nullptr, nullptr, Oh, Ol, D_, D_, smem);
}

// ===========================================================================
// HMMA score kernel v3: 128 threads, 4 warps in 2(i) x 2(j) quadrants,
// each warp computes 32x32 (two 16-row m-tiles sharing a 64-wide Er band).
// ===========================================================================
#define SC_SQH 0
#define SC_SQL 8192
#define SC_S2H 16384
#define SC_S2L 24576
#define SC_SKH 32768
#define SC_SKL 40960
#define SC_SEH 49152
#define SC_SEL 65536
#define SC_SR  81920
#define SC_RSW 3584                    // per-(warp,mt) gather bytes (16 x 56 fp32)
#define SC_SMEM (81920 + 8 * SC_RSW)   // 110592

__global__ __launch_bounds__(128, 2)
void score_tc(const __nv_bfloat16* __restrict__ qh, const __nv_bfloat16* __restrict__ ql,
              const __nv_bfloat16* __restrict__ q2h, const __nv_bfloat16* __restrict__ q2l,
              const __nv_bfloat16* __restrict__ kh, const __nv_bfloat16* __restrict__ kl,
              const __nv_bfloat16* __restrict__ eh, const __nv_bfloat16* __restrict__ el,
              float* __restrict__ p)
{
    const int x = blockIdx.x;
    int ti = (int)((__fsqrt_rn(8.0f * x + 1.0f) - 1.0f) * 0.5f);
    if (ti * (ti + 1) / 2 > x) ti--;
    else if ((ti + 1) * (ti + 2) / 2 <= x) ti++;
    const int tj = x - ti * (ti + 1) / 2;
    const int z = blockIdx.y;
    const int i0 = ti * 64, j0 = tj * 64;
    const int h = z >> 2, b = z & 3;
    const int rbase = L_ - 64 - i0 + j0;

    extern __shared__ __align__(16) char smem[];
    const uint32_t sb = smem_u32(smem);
    const int tid = threadIdx.x;
    const int lane = tid & 31, w = tid >> 5;
    const int iw = w & 1, jw = w >> 1;

    auto load64 = [&](uint32_t st, const __nv_bfloat16* g) {
        #pragma unroll
        for (int t = 0; t < 4; t++) {
            int cid = tid + t * 128;
            int row = cid >> 3, c = cid & 7;
            cpa16(sb + st + row * 128 + ((c ^ (row & 7)) * 16),
                  g + (size_t)row * D_ + c * 8);
        }
    };
    const size_t qoff = (size_t)(b * L_ + i0) * D_ + h * 64;
    const size_t koff = (size_t)(b * L_ + j0) * D_ + h * 64;
    load64(SC_SQH, qh  + qoff);
    load64(SC_SQL, ql  + qoff);
    load64(SC_S2H, q2h + qoff);
    load64(SC_S2L, q2l + qoff);
    load64(SC_SKH, kh  + koff);
    load64(SC_SKL, kl  + koff);
    {
        const __nv_bfloat16* ehp = eh + (size_t)h * L_ * 64;
        const __nv_bfloat16* elp = el + (size_t)h * L_ * 64;
        #pragma unroll
        for (int t = 0; t < 8; t++) {
            int cid = tid + t * 128;
            int row = cid >> 3, c = cid & 7;
            int r = rbase + row;
            int sz = (r < L_) ? 16 : 0;
            int rc = (r < L_) ? r : 0;
            uint32_t so = row * 128 + ((c ^ (row & 7)) * 16);
            cpa16z(sb + SC_SEH + so, ehp + (size_t)rc * 64 + c * 8, sz);
            cpa16z(sb + SC_SEL + so, elp + (size_t)rc * 64 + c * 8, sz);
        }
    }
    asm volatile("cp.async.commit_group;" ::: "memory");
    asm volatile("cp.async.wait_group 0;" ::: "memory");
    __syncthreads();

    float aqk[2][4][4], arl[2][6][4];
    #pragma unroll
    for (int m2 = 0; m2 < 2; m2++) {
        #pragma unroll
        for (int i = 0; i < 4; i++)
            #pragma unroll
            for (int q = 0; q < 4; q++) aqk[m2][i][q] = 0.f;
        #pragma unroll
        for (int i = 0; i < 6; i++)
            #pragma unroll
            for (int q = 0; q < 4; q++) arl[m2][i][q] = 0.f;
    }

    const int tb = 32 + 32 * jw - 32 * iw;

    auto ldB = [&](uint32_t st, int nrow0, int k16, uint32_t* r) {
        int row = nrow0 + (lane >> 4) * 8 + (lane & 7);
        int c = (k16 >> 3) + ((lane >> 3) & 1);
        ldsm_x4(r, sb + st + row * 128 + ((c ^ (row & 7)) * 16));
    };

    #pragma unroll
    for (int k16 = 0; k16 < 64; k16 += 16) {
        uint32_t Aq[2][2][4], A2[2][2][4];
        #pragma unroll
        for (int mt = 0; mt < 2; mt++) {
            int row = 32 * iw + 16 * mt + (lane & 15);
            int c = (k16 >> 3) + (lane >> 4);
            uint32_t off = row * 128 + ((c ^ (row & 7)) * 16);
            ldsm_x4(Aq[mt][0], sb + SC_SQH + off);
            ldsm_x4(Aq[mt][1], sb + SC_SQL + off);
            ldsm_x4(A2[mt][0], sb + SC_S2H + off);
            ldsm_x4(A2[mt][1], sb + SC_S2L + off);
        }
        #pragma unroll
        for (int pg = 0; pg < 2; pg++) {
            uint32_t Bh[4], Bl[4];
            ldB(SC_SKH, 32 * jw + pg * 16, k16, Bh);
            ldB(SC_SKL, 32 * jw + pg * 16, k16, Bl);
            #pragma unroll
            for (int mt = 0; mt < 2; mt++) {
                mma16816(aqk[mt][2 * pg],     Aq[mt][0], Bh);
                mma16816(aqk[mt][2 * pg + 1], Aq[mt][0], Bh + 2);
                mma16816(aqk[mt][2 * pg],     Aq[mt][0], Bl);
                mma16816(aqk[mt][2 * pg + 1], Aq[mt][0], Bl + 2);
                mma16816(aqk[mt][2 * pg],     Aq[mt][1], Bh);
                mma16816(aqk[mt][2 * pg + 1], Aq[mt][1], Bh + 2);
            }
        }
        #pragma unroll
        for (int g = 0; g < 4; g++) {
            uint32_t Bh[4], Bl[4];
            ldB(SC_SEH, tb + g * 16, k16, Bh);
            ldB(SC_SEL, tb + g * 16, k16, Bl);
            if (g >= 1) {
                const int li = g - 1;
                mma16816(arl[0][2 * li],     A2[0][0], Bh);
                mma16816(arl[0][2 * li + 1], A2[0][0], Bh + 2);
                mma16816(arl[0][2 * li],     A2[0][0], Bl);
                mma16816(arl[0][2 * li + 1], A2[0][0], Bl + 2);
                mma16816(arl[0][2 * li],     A2[0][1], Bh);
                mma16816(arl[0][2 * li + 1], A2[0][1], Bh + 2);
            }
            if (g <= 2) {
                const int li = g;
                mma16816(arl[1][2 * li],     A2[1][0], Bh);
                mma16816(arl[1][2 * li + 1], A2[1][0], Bh + 2);
                mma16816(arl[1][2 * li],     A2[1][0], Bl);
                mma16816(arl[1][2 * li + 1], A2[1][0], Bl + 2);
                mma16816(arl[1][2 * li],     A2[1][1], Bh);
                mma16816(arl[1][2 * li + 1], A2[1][1], Bh + 2);
            }
        }
    }

    const int r0 = lane >> 2, cb = (lane & 3) * 2;
    #pragma unroll
    for (int mt = 0; mt < 2; mt++) {
        float* Rs = (float*)(smem + SC_SR + (w * 2 + mt) * SC_RSW);
        #pragma unroll
        for (int nt = 0; nt < 6; nt++) {
            int tcol = nt * 8 + cb;
            Rs[r0 * 56 + tcol]           = arl[mt][nt][0];
            Rs[r0 * 56 + tcol + 1]       = arl[mt][nt][1];
            Rs[(r0 + 8) * 56 + tcol]     = arl[mt][nt][2];
            Rs[(r0 + 8) * 56 + tcol + 1] = arl[mt][nt][3];
        }
    }
    __syncwarp();

    #pragma unroll
    for (int mt = 0; mt < 2; mt++) {
        float* Rs = (float*)(smem + SC_SR + (w * 2 + mt) * SC_RSW);
        #pragma unroll
        for (int nt = 0; nt < 4; nt++) {
            int jc = nt * 8 + cb;
            float2 o0, o1;
            o0.x = (aqk[mt][nt][0] + Rs[r0 * 56 + 15 + jc - r0]) * 0.125f;
            o0.y = (aqk[mt][nt][1] + Rs[r0 * 56 + 16 + jc - r0]) * 0.125f;
            o1.x = (aqk[mt][nt][2] + Rs[(r0 + 8) * 56 + 7 + jc - r0]) * 0.125f;
            o1.y = (aqk[mt][nt][3] + Rs[(r0 + 8) * 56 + 8 + jc - r0]) * 0.125f;
            size_t base = ((size_t)z * L_ + i0 + 32 * iw + 16 * mt + r0) * L_
                        + j0 + 32 * jw + jc;
            *(float2*)&p[base]          = o0;
            *(float2*)&p[base + 8 * L_] = o1;
        }
    }
}

// ===========================================================================
// Warp-per-row softmax: each warp owns one full row (32 fp32/lane, in regs).
// No smem, no __syncthreads — pure shfl reductions. Loads only j <= i;
// exp(-FLT_MAX)=0 writes the upper-triangle zeros.
// grid: (L/8, HB), 256 threads (8 warps = 8 rows per CTA).
// ===========================================================================
__global__ __launch_bounds__(256)
void softmax_warp(float* __restrict__ p)
{
    const int lane = threadIdx.x & 31;
    const int i = blockIdx.x * 8 + (threadIdx.x >> 5);
    const int z = blockIdx.y;
    float* row = p + ((size_t)z * L_ + i) * L_;

    float4 v[8];
    float m = -FLT_MAX;
    #pragma unroll
    for (int t = 0; t < 8; t++) {
        const int j0 = t * 128 + lane * 4;
        if (j0 <= i) {
            v[t] = *(const float4*)&row[j0];
            if (j0 + 1 > i) v[t].y = -FLT_MAX;
            if (j0 + 2 > i) v[t].z = -FLT_MAX;
            if (j0 + 3 > i) v[t].w = -FLT_MAX;
        } else {
            v[t] = make_float4(-FLT_MAX, -FLT_MAX, -FLT_MAX, -FLT_MAX);
        }
        m = fmaxf(m, fmaxf(fmaxf(v[t].x, v[t].y), fmaxf(v[t].z, v[t].w)));
    }
    #pragma unroll
    for (int o = 16; o > 0; o >>= 1) m = fmaxf(m, __shfl_xor_sync(0xffffffffu, m, o));

    float s = 0.f;
    #pragma unroll
    for (int t = 0; t < 8; t++) {
        v[t].x = __expf(v[t].x - m);
        v[t].y = __expf(v[t].y - m);
        v[t].z = __expf(v[t].z - m);
        v[t].w = __expf(v[t].w - m);
        s += (v[t].x + v[t].y) + (v[t].z + v[t].w);
    }
    #pragma unroll
    for (int o = 16; o > 0; o >>= 1) s += __shfl_xor_sync(0xffffffffu, s, o);
    const float inv = 1.0f / s;

    #pragma unroll
    for (int t = 0; t < 8; t++) {
        const int j0 = t * 128 + lane * 4;
        float4 e;
        e.x = v[t].x * inv; e.y = v[t].y * inv;
        e.z = v[t].z * inv; e.w = v[t].w * inv;
        *(float4*)&row[j0] = e;
    }
}

// ===========================================================================
// HMMA pv: out[i,d] = sum_{j<=i} p[i,j] v[j,d]; writes att bf16 hi/lo directly.
// ===========================================================================
__global__ __launch_bounds__(128)
void pv_tc(const float* __restrict__ p,
           const __nv_bfloat16* __restrict__ vh, const __nv_bfloat16* __restrict__ vl,
           __nv_bfloat16* __restrict__ oh, __nv_bfloat16* __restrict__ ol)
{
    const int ti = blockIdx.x, z = blockIdx.y;
    const int i0 = ti * 64;
    const int h = z >> 2, b = z & 3;
    const int tid = threadIdx.x;
    const int lane = tid & 31, w = tid >> 5;

    __shared__ __align__(128) char sv[2][2][4096];
    __shared__ __align__(128) char sp[4][2][1280];
    const uint32_t svb = smem_u32(&sv[0][0][0]);
    const uint32_t spw = smem_u32(&sp[w][0][0]);

    auto loadV = [&](int kj, int bi) {
        #pragma unroll
        for (int t = 0; t < 4; t++) {
            int cid = tid + t * 128;
            int sel = cid >> 8, rid = (cid >> 3) & 31, c = cid & 7;
            const __nv_bfloat16* g = (sel ? vl : vh)
                + ((size_t)(b * L_ + kj + rid) * D_ + h * 64 + c * 8);
            cpa16(svb + bi * 8192 + sel * 4096 + rid * 128 + ((c ^ (rid & 7)) * 16), g);
        }
        asm volatile("cp.async.commit_group;" ::: "memory");
    };

    float acc[8][4];
    #pragma unroll
    for (int i = 0; i < 8; i++)
        #pragma unroll
        for (int q = 0; q < 4; q++) acc[i][q] = 0.f;

    const int nch = (i0 + 64) >> 5;
    loadV(0, 0);

    for (int c = 0; c < nch; c++) {
        const int bi = c & 1;
        __syncthreads();
        if (c + 1 < nch) loadV((c + 1) * 32, bi ^ 1);

        {
            const int row = lane >> 1, chalf = lane & 1;
            const float* gp = p + ((size_t)z * L_ + i0 + 16 * w + row) * L_
                                + c * 32 + chalf * 16;
            uint32_t* ph = (uint32_t*)(&sp[w][0][0] + row * 80 + chalf * 32);
            uint32_t* pl = (uint32_t*)(&sp[w][1][0] + row * 80 + chalf * 32);
            #pragma unroll
            for (int q = 0; q < 4; q++) {
                float4 v = *(const float4*)(gp + q * 4);
                __nv_bfloat162 h0, h1, l0, l1;
                h0.x = __float2bfloat16(v.x); h0.y = __float2bfloat16(v.y);
                h1.x = __float2bfloat16(v.z); h1.y = __float2bfloat16(v.w);
                l0.x = __float2bfloat16(v.x - __bfloat162float(h0.x));
                l0.y = __float2bfloat16(v.y - __bfloat162float(h0.y));
                l1.x = __float2bfloat16(v.z - __bfloat162float(h1.x));
                l1.y = __float2bfloat16(v.w - __bfloat162float(h1.y));
                ph[q * 2]     = *(uint32_t*)&h0;
                ph[q * 2 + 1] = *(uint32_t*)&h1;
                pl[q * 2]     = *(uint32_t*)&l0;
                pl[q * 2 + 1] = *(uint32_t*)&l1;
            }
        }
        __syncwarp();
        if (c + 1 < nch) asm volatile("cp.async.wait_group 1;" ::: "memory");
        else             asm volatile("cp.async.wait_group 0;" ::: "memory");
        __syncthreads();

        #pragma unroll
        for (int k16 = 0; k16 < 32; k16 += 16) {
            uint32_t Aph[4], Apl[4];
            {
                int arow = lane & 15;
                int ac = (k16 >> 3) + (lane >> 4);
                ldsm_x4(Aph, spw + arow * 80 + ac * 16);
                ldsm_x4(Apl, spw + 1280 + arow * 80 + ac * 16);
            }
            #pragma unroll
            for (int p4 = 0; p4 < 4; p4++) {
                uint32_t Bh[4], Bl[4];
                int krow = k16 + ((lane >> 3) & 1) * 8 + (lane & 7);
                int cc = p4 * 2 + (lane >> 4);
                uint32_t off = krow * 128 + ((cc ^ (krow & 7)) * 16);
                ldsm_x4_t(Bh, svb + bi * 8192 + off);
                ldsm_x4_t(Bl, svb + bi * 8192 + 4096 + off);
                mma16816(acc[2 * p4],     Aph, Bh);
                mma16816(acc[2 * p4 + 1], Aph, Bh + 2);
                mma16816(acc[2 * p4],     Aph, Bl);
                mma16816(acc[2 * p4 + 1], Aph, Bl + 2);
                mma16816(acc[2 * p4],     Apl, Bh);
                mma16816(acc[2 * p4 + 1], Apl, Bh + 2);
            }
        }
    }

    const int r0 = lane >> 2, cb = (lane & 3) * 2;
    #pragma unroll
    for (int nt = 0; nt < 8; nt++) {
        const int d = nt * 8 + cb;
        #pragma unroll
        for (int rr = 0; rr < 2; rr++) {
            const int i = i0 + 16 * w + r0 + rr * 8;
            const size_t idx = (size_t)(b * L_ + i) * D_ + h * 64 + d;
            float a0 = acc[nt][rr * 2], a1 = acc[nt][rr * 2 + 1];
            __nv_bfloat162 hh, ll;
            hh.x = __float2bfloat16(a0);
            hh.y = __float2bfloat16(a1);
            ll.x = __float2bfloat16(a0 - __bfloat162float(hh.x));
            ll.y = __float2bfloat16(a1 - __bfloat162float(hh.y));
            *(__nv_bfloat162*)&oh[idx] = hh;
            *(__nv_bfloat162*)&ol[idx] = ll;
        }
    }
}

// ===========================================================================
// LayerNorm
// ===========================================================================
__global__ __launch_bounds__(256)
void ln_kernel(const float* __restrict__ x, const float* __restrict__ gam,
               const float* __restrict__ bet, float* __restrict__ y)
{
    const int r = blockIdx.x, tid = threadIdx.x;
    __shared__ float sh[16];
    const float* xr = x + (size_t)r * D_;
    float4 xv = *(const float4*)&xr[tid * 4];
    float s  = xv.x + xv.y + xv.z + xv.w;
    float ss = xv.x*xv.x + xv.y*xv.y + xv.z*xv.z + xv.w*xv.w;
    #pragma unroll
    for (int o = 16; o > 0; o >>= 1) {
        s  += __shfl_xor_sync(0xffffffffu, s,  o);
        ss += __shfl_xor_sync(0xffffffffu, ss, o);
    }
    if ((tid & 31) == 0) { sh[tid >> 5] = s; sh[8 + (tid >> 5)] = ss; }
    __syncthreads();
    float st = 0.f, sst = 0.f;
    #pragma unroll
    for (int wv = 0; wv < 8; wv++) { st += sh[wv]; sst += sh[8 + wv]; }
    const float mu  = st * (1.0f / D_);
    const float var = sst * (1.0f / D_) - mu * mu;
    const float rs  = rsqrtf(var + 1e-5f);
    float4 gv = *(const float4*)&gam[tid * 4];
    float4 bv = *(const float4*)&bet[tid * 4];
    float4 o4;
    o4.x = (xv.x - mu) * rs * gv.x + bv.x;
    o4.y = (xv.y - mu) * rs * gv.y + bv.y;
    o4.z = (xv.z - mu) * rs * gv.z + bv.z;
    o4.w = (xv.w - mu) * rs * gv.w + bv.w;
    *(float4*)&y[(size_t)r * D_ + tid * 4] = o4;
}

// ===========================================================================
// Launch
// ===========================================================================
extern "C" void kernel_launch(void* const* d_in, const int* in_sizes, int n_in,
                              void* d_out, int out_size)
{
    const float* q_in = (const float*)d_in[0];
    const float* k_in = (const float*)d_in[1];
    const float* v_in = (const float*)d_in[2];
    const float* Wq   = (const float*)d_in[3];
    const float* Wq2  = (const float*)d_in[4];
    const float* Wk   = (const float*)d_in[5];
    const float* Wv   = (const float*)d_in[6];
    const float* Wo   = (const float*)d_in[7];
    const float* ln_g = (const float*)d_in[8];
    const float* ln_b = (const float*)d_in[9];
    const float* Er   = (const float*)d_in[10];
    (void)in_sizes; (void)n_in;

    float *px, *pfb;
    __nv_bfloat16 *ah, *al, *bh, *bl, *ch, *cl, *wh, *wl;
    __nv_bfloat16 *qh, *ql, *q2h, *q2l, *kh, *kl, *vh, *vl, *eh, *el;
    cudaGetSymbolAddress((void**)&px,  g_x);
    cudaGetSymbolAddress((void**)&pfb, g_pfb);
    cudaGetSymbolAddress((void**)&ah,  g_ah);
    cudaGetSymbolAddress((void**)&al,  g_al);
    cudaGetSymbolAddress((void**)&bh,  g_bh);
    cudaGetSymbolAddress((void**)&bl,  g_bl);
    cudaGetSymbolAddress((void**)&ch,  g_ch);
    cudaGetSymbolAddress((void**)&cl,  g_cl);
    cudaGetSymbolAddress((void**)&wh,  g_wh);
    cudaGetSymbolAddress((void**)&wl,  g_wl);
    cudaGetSymbolAddress((void**)&qh,  g_qh);
    cudaGetSymbolAddress((void**)&ql,  g_ql);
    cudaGetSymbolAddress((void**)&q2h, g_q2h);
    cudaGetSymbolAddress((void**)&q2l, g_q2l);
    cudaGetSymbolAddress((void**)&kh,  g_kh);
    cudaGetSymbolAddress((void**)&kl,  g_kl);
    cudaGetSymbolAddress((void**)&vh,  g_vh);
    cudaGetSymbolAddress((void**)&vl,  g_vl);
    cudaGetSymbolAddress((void**)&eh,  g_eh);
    cudaGetSymbolAddress((void**)&el,  g_el);

    float* y_out = (float*)d_out;
    const long long ysz = (long long)B_ * L_ * D_;
    const long long psz = (long long)HB_ * L_ * L_;
    float* p_buf = ((long long)out_size >= ysz + psz) ? (y_out + ysz) : pfb;

    const int gsmem = 2 * STAGE_BYTES;
    cudaFuncSetAttribute(gemm_tc, cudaFuncAttributeMaxDynamicSharedMemorySize, gsmem);
    cudaFuncSetAttribute(gemm_proj4, cudaFuncAttributeMaxDynamicSharedMemorySize, gsmem);
    cudaFuncSetAttribute(score_tc, cudaFuncAttributeMaxDynamicSharedMemorySize, SC_SMEM);

    const int M = B_ * L_;
    const dim3 ggemm(D_ / 128, M / 128);
    const size_t WSZ = (size_t)D_ * D_;

    // all splits upfront
    split_act_all<<<dim3(4096, 1, 4), 256>>>(q_in, k_in, v_in, Er,
                                             ah, al, bh, bl, ch, cl, eh, el);
    split_w_all<<<dim3(32, 32, 5), 256>>>(Wq, Wq2, Wk, Wv, Wo, wh, wl);

    // 4 projections in ONE batched launch (z selects buffers)
    gemm_proj4<<<dim3(D_ / 128, M / 128, 4), 256, gsmem>>>();

    // attention middle: scores (tri-grid), warp-per-row softmax, pv
    score_tc<<<dim3(136, HB_), 128, SC_SMEM>>>(qh, ql, q2h, q2l, kh, kl, eh, el, p_buf);
    softmax_warp<<<dim3(L_ / 8, HB_), 256>>>(p_buf);
    pv_tc<<<dim3(16, HB_), 128>>>(p_buf, vh, vl, ah, al);   // att -> ah/al

    // Wo GEMM (fp32 out + residual), then LN
    gemm_tc<<<ggemm, 256, gsmem>>>(ah, al, wh + 4 * WSZ, wl + 4 * WSZ,
                                   px, q_in, nullptr, nullptr, D_, D_);
    ln_kernel<<<B_ * L_, 256>>>(px, ln_g, ln_b, y_out);
}